// round 7
// baseline (speedup 1.0000x reference)
#include <cuda_runtime.h>
#include <cuda_fp16.h>
#include <cstdint>

#define B_    2
#define QLEN  900
#define DIMV  256
#define NH    8
#define HD    32
#define KVLEN 4096
#define GRD   64
#define RPEH  512

// ---------------- scratch ----------------
__device__ __half d_Qh[B_*NH*QLEN*HD];     // (b,h,q,32) f16 pre-scaled
__device__ __half d_Kh[B_*NH*KVLEN*HD];    // (b,h,kv,32) f16
__device__ __half d_Vh[B_*NH*KVLEN*HD];    // (b,h,kv,32) f16
__device__ __half d_ctxh[B_*QLEN*DIMV];    // (b,q,256) f16
__device__ float  d_rpex[B_*NH*QLEN*GRD];
__device__ float  d_rpey[B_*NH*QLEN*GRD];
__device__ __half d_Wh[4*65536];           // qw,kw,vw,ow f16
__device__ __half d_Akv[B_*KVLEN*DIMV];    // kvst f16
__device__ __half d_Aq[B_*QLEN*DIMV];      // hidden f16

// ---------------- helpers ----------------
__device__ __forceinline__ void ldmx4(uint32_t* r, uint32_t a) {
    asm volatile("ldmatrix.sync.aligned.m8n8.x4.shared.b16 {%0,%1,%2,%3}, [%4];"
                 : "=r"(r[0]), "=r"(r[1]), "=r"(r[2]), "=r"(r[3]) : "r"(a));
}
__device__ __forceinline__ void ldmx2(uint32_t* r, uint32_t a) {
    asm volatile("ldmatrix.sync.aligned.m8n8.x2.shared.b16 {%0,%1}, [%2];"
                 : "=r"(r[0]), "=r"(r[1]) : "r"(a));
}
__device__ __forceinline__ void ldmx2t(uint32_t* r, uint32_t a) {
    asm volatile("ldmatrix.sync.aligned.m8n8.x2.trans.shared.b16 {%0,%1}, [%2];"
                 : "=r"(r[0]), "=r"(r[1]) : "r"(a));
}
__device__ __forceinline__ void mma16816(float* c, const uint32_t* a, const uint32_t* b) {
    asm volatile("mma.sync.aligned.m16n8k16.row.col.f32.f16.f16.f32 "
                 "{%0,%1,%2,%3}, {%4,%5,%6,%7}, {%8,%9}, {%0,%1,%2,%3};"
                 : "+f"(c[0]), "+f"(c[1]), "+f"(c[2]), "+f"(c[3])
                 : "r"(a[0]), "r"(a[1]), "r"(a[2]), "r"(a[3]), "r"(b[0]), "r"(b[1]));
}
__device__ __forceinline__ uint32_t smem_u32(const void* p) {
    return (uint32_t)__cvta_generic_to_shared(p);
}
__device__ __forceinline__ uint32_t packh2(float a, float b) {
    __half2 h = __floats2half2_rn(a, b);
    return *(uint32_t*)&h;
}
#define CP16(dst, src) asm volatile("cp.async.cg.shared.global [%0], [%1], 16;" :: "r"(dst), "l"(src) : "memory")
#define CP_COMMIT() asm volatile("cp.async.commit_group;" ::: "memory")
#define CP_WAIT1() asm volatile("cp.async.wait_group 1;" ::: "memory")
#define CP_WAIT0() asm volatile("cp.async.wait_group 0;" ::: "memory")

// ---------------- one-shot fp32 -> f16 convert ----------------
// units of 4 floats: [0,16384) qw | kw | vw | ow | [65536,589824) kvst | hidden
__global__ void convert_all(const float* __restrict__ qw, const float* __restrict__ kw,
                            const float* __restrict__ vw, const float* __restrict__ ow,
                            const float* __restrict__ kvst, const float* __restrict__ hidden)
{
    unsigned u = blockIdx.x * 256 + threadIdx.x;
    const float* src; __half* dst; unsigned off;
    if      (u <  16384) { src = qw;     dst = d_Wh;          off = u; }
    else if (u <  32768) { src = kw;     dst = d_Wh + 65536;  off = u - 16384; }
    else if (u <  49152) { src = vw;     dst = d_Wh + 131072; off = u - 32768; }
    else if (u <  65536) { src = ow;     dst = d_Wh + 196608; off = u - 49152; }
    else if (u < 589824) { src = kvst;   dst = d_Akv;         off = u - 65536; }
    else                 { src = hidden; dst = d_Aq;          off = u - 589824; }
    float4 f = ((const float4*)src)[off];
    uint2 o; o.x = packh2(f.x, f.y); o.y = packh2(f.z, f.w);
    ((uint2*)dst)[off] = o;
}

// ---------------- HMMA GEMM 128x64 tile, optional dual weights ----------------
// C = A(Mx256,f16) @ W(256x256 f16 [n][k])^T + bias; mode 0: f32 [row][256];
// mode 1: half (b,head,row,32)
__global__ void __launch_bounds__(256) gemm_dual(
    const __half* __restrict__ Ah,
    const __half* __restrict__ W1, const float* __restrict__ b1v, void* __restrict__ C1,
    const __half* __restrict__ W2, const float* __restrict__ b2v, void* __restrict__ C2,
    int M, int rpb, float scale, int mode)
{
    __shared__ __half As[128 * 40];
    __shared__ __half Ws1[64 * 40];
    __shared__ __half Ws2[64 * 40];

    const int tid = threadIdx.x;
    const int lane = tid & 31;
    const int wid = tid >> 5;
    const int bm = blockIdx.x * 128;
    const int bn = blockIdx.y * 64;
    const bool dual = (W2 != nullptr);

    const int arow = tid >> 1, aseg = (tid & 1) * 16;
    const int wrow = tid >> 2, wseg = (tid & 3) * 8;

    float c1[8][4], c2[8][4];
#pragma unroll
    for (int j = 0; j < 8; j++) {
        c1[j][0] = c1[j][1] = c1[j][2] = c1[j][3] = 0.f;
        c2[j][0] = c2[j][1] = c2[j][2] = c2[j][3] = 0.f;
    }

    const uint32_t AsB = smem_u32(As);
    const uint32_t W1B = smem_u32(Ws1);
    const uint32_t W2B = smem_u32(Ws2);

    uint4 pa0 = make_uint4(0,0,0,0), pa1 = pa0, pw1, pw2 = make_uint4(0,0,0,0);
    // preload k0 = 0
    if (bm + arow < M) {
        const uint4* ap = (const uint4*)&Ah[(size_t)(bm + arow) * 256 + aseg];
        pa0 = ap[0]; pa1 = ap[1];
    }
    pw1 = *(const uint4*)&W1[(size_t)(bn + wrow) * 256 + wseg];
    if (dual) pw2 = *(const uint4*)&W2[(size_t)(bn + wrow) * 256 + wseg];

#pragma unroll 1
    for (int kit = 0; kit < 8; kit++) {
        *(uint4*)&As[arow * 40 + aseg]     = pa0;
        *(uint4*)&As[arow * 40 + aseg + 8] = pa1;
        *(uint4*)&Ws1[wrow * 40 + wseg]    = pw1;
        if (dual) *(uint4*)&Ws2[wrow * 40 + wseg] = pw2;
        __syncthreads();

        if (kit < 7) {
            int k0 = (kit + 1) * 32;
            pa0 = make_uint4(0,0,0,0); pa1 = pa0;
            if (bm + arow < M) {
                const uint4* ap = (const uint4*)&Ah[(size_t)(bm + arow) * 256 + k0 + aseg];
                pa0 = ap[0]; pa1 = ap[1];
            }
            pw1 = *(const uint4*)&W1[(size_t)(bn + wrow) * 256 + k0 + wseg];
            if (dual) pw2 = *(const uint4*)&W2[(size_t)(bn + wrow) * 256 + k0 + wseg];
        }

        uint32_t a0[4], a1[4];
        uint32_t aa = AsB + (uint32_t)((wid * 16 + (lane & 15)) * 40 + ((lane >> 4) * 8)) * 2;
        ldmx4(a0, aa);
        ldmx4(a1, aa + 32);
#pragma unroll
        for (int j = 0; j < 8; j++) {
            uint32_t woff = (uint32_t)((j * 8 + (lane & 7)) * 40 + ((lane >> 3) & 1) * 8) * 2;
            uint32_t b0[2], b1[2];
            ldmx2(b0, W1B + woff);
            ldmx2(b1, W1B + woff + 32);
            mma16816(c1[j], a0, b0);
            mma16816(c1[j], a1, b1);
            if (dual) {
                ldmx2(b0, W2B + woff);
                ldmx2(b1, W2B + woff + 32);
                mma16816(c2[j], a0, b0);
                mma16816(c2[j], a1, b1);
            }
        }
        __syncthreads();
    }

    const int r0 = bm + wid * 16 + (lane >> 2);
    const int cb = 2 * (lane & 3);
    if (mode == 0) {
        float* C = (float*)C1;
#pragma unroll
        for (int j = 0; j < 8; j++) {
            int col = bn + j * 8 + cb;
            float bb0 = b1v[col], bb1 = b1v[col + 1];
            if (r0 < M)     *(float2*)&C[(size_t)r0 * 256 + col]       = make_float2((c1[j][0] + bb0) * scale, (c1[j][1] + bb1) * scale);
            if (r0 + 8 < M) *(float2*)&C[(size_t)(r0 + 8) * 256 + col] = make_float2((c1[j][2] + bb0) * scale, (c1[j][3] + bb1) * scale);
        }
    } else {
        __half* Ca = (__half*)C1;
        __half* Cb = (__half*)C2;
        int ba = r0 / rpb, ra = r0 - ba * rpb;
        int bb = (r0 + 8) / rpb, rb = (r0 + 8) - bb * rpb;
#pragma unroll
        for (int j = 0; j < 8; j++) {
            int col = bn + j * 8 + cb;
            int head = col >> 5, d = col & 31;
            float x0 = b1v[col], x1 = b1v[col + 1];
            if (r0 < M) {
                *(uint32_t*)&Ca[((size_t)((ba * NH + head) * rpb + ra)) * HD + d] =
                    packh2((c1[j][0] + x0) * scale, (c1[j][1] + x1) * scale);
            }
            if (r0 + 8 < M) {
                *(uint32_t*)&Ca[((size_t)((bb * NH + head) * rpb + rb)) * HD + d] =
                    packh2((c1[j][2] + x0) * scale, (c1[j][3] + x1) * scale);
            }
            if (dual) {
                float y0 = b2v[col], y1 = b2v[col + 1];
                if (r0 < M) {
                    *(uint32_t*)&Cb[((size_t)((ba * NH + head) * rpb + ra)) * HD + d] =
                        packh2((c2[j][0] + y0) * scale, (c2[j][1] + y1) * scale);
                }
                if (r0 + 8 < M) {
                    *(uint32_t*)&Cb[((size_t)((bb * NH + head) * rpb + rb)) * HD + d] =
                        packh2((c2[j][2] + y0) * scale, (c2[j][3] + y1) * scale);
                }
            }
        }
    }
}

// ---------------- RPE via tensor cores (hi/lo split, fp32-quality) ----------------
// block = one (b, q, axis). hidden_j(p) = relu(a_j - s_j*px_p); out = W2 @ hidden.
#define RA_OFF   0
#define RS_OFF   2048
#define W2HI_OFF 4096
#define W2LO_OFF 12416
#define HHI_OFF  20736
#define HLO_OFF  38144
#define RED_OFF  55552
#define RPE_SMEM 57600

__global__ void __launch_bounds__(256) rpe_tc(
    const float* __restrict__ refpts,
    const float* __restrict__ w1a, const float* __restrict__ b1a, const float* __restrict__ w2a,
    const float* __restrict__ w1b, const float* __restrict__ b1b, const float* __restrict__ w2b,
    float* __restrict__ outx, float* __restrict__ outy)
{
    extern __shared__ char smem[];
    float*  a_s  = (float*)(smem + RA_OFF);
    float*  s_s  = (float*)(smem + RS_OFF);
    __half* w2hi = (__half*)(smem + W2HI_OFF);
    __half* w2lo = (__half*)(smem + W2LO_OFF);
    __half* Hhi  = (__half*)(smem + HHI_OFF);
    __half* Hlo  = (__half*)(smem + HLO_OFF);
    float*  red  = (float*)(smem + RED_OFF);

    const int tid = threadIdx.x;
    const int lane = tid & 31;
    const int wid = tid >> 5;
    const int q = blockIdx.x;
    const int b = blockIdx.y;
    const int axis = blockIdx.z;

    const float* w1 = axis ? w1b : w1a;
    const float* bb1 = axis ? b1b : b1a;
    const float* w2 = axis ? w2b : w2a;
    float* out = axis ? outy : outx;

    const float* rp = refpts + ((size_t)b * QLEN + q) * 4;
    const float cc = rp[axis];
    const float ss = rp[2 + axis];
    const float lo = (cc - 0.5f * ss) * 1024.0f;
    const float hi = (cc + 0.5f * ss) * 1024.0f;

    // a_j, s_j
#pragma unroll
    for (int r = 0; r < 2; r++) {
        int j = tid + r * 256;
        float wx = w1[j * 2], wy = w1[j * 2 + 1];
        a_s[j] = wx * lo + wy * hi + bb1[j];
        s_s[j] = wx + wy;
    }
    // w2 hi/lo
    for (int i = tid; i < RPEH * NH; i += 256) {
        int h = i >> 9, j = i & 511;
        float f = w2[h * RPEH + j];
        __half fh = __float2half_rn(f);
        w2hi[h * 520 + j] = fh;
        w2lo[h * 520 + j] = __float2half_rn(f - __half2float(fh));
    }
    __syncthreads();

    const int p  = tid >> 2;
    const int jq = tid & 3;
    const float px = (p + 0.5f) * 16.0f;

    float c[4];
    c[0] = c[1] = c[2] = c[3] = 0.f;
    const int mt = wid & 3;
    const int kh = wid >> 2;
    const uint32_t HhiB = smem_u32(Hhi);
    const uint32_t HloB = smem_u32(Hlo);
    const uint32_t WhiB = smem_u32(w2hi);
    const uint32_t WloB = smem_u32(w2lo);

#pragma unroll 1
    for (int c4 = 0; c4 < 4; c4++) {
        const int jbase = c4 * 128;
        // hidden chunk: this thread covers 32 j's for its p
#pragma unroll 8
        for (int jj = 0; jj < 32; jj += 2) {
            int j = jbase + jq * 32 + jj;
            float h0 = fmaxf(a_s[j]     - s_s[j]     * px, 0.f);
            float h1 = fmaxf(a_s[j + 1] - s_s[j + 1] * px, 0.f);
            __half h0h = __float2half_rn(h0);
            __half h1h = __float2half_rn(h1);
            __half2 hhiv; hhiv.x = h0h; hhiv.y = h1h;
            __half2 hlov = __floats2half2_rn(h0 - __half2float(h0h), h1 - __half2float(h1h));
            int col = jq * 32 + jj;
            *(uint32_t*)&Hhi[p * 136 + col] = *(uint32_t*)&hhiv;
            *(uint32_t*)&Hlo[p * 136 + col] = *(uint32_t*)&hlov;
        }
        __syncthreads();

        // layer 2 mma: warp (mt, kh) does 4 of 8 k-steps in this chunk
#pragma unroll
        for (int kk = kh * 4; kk < kh * 4 + 4; kk++) {
            uint32_t aoff = (uint32_t)((mt * 16 + (lane & 15)) * 136 + kk * 16 + ((lane >> 4) * 8)) * 2;
            uint32_t ahi[4], alo[4];
            ldmx4(ahi, HhiB + aoff);
            ldmx4(alo, HloB + aoff);
            uint32_t woff = (uint32_t)((lane & 7) * 520 + jbase + kk * 16 + ((lane >> 3) & 1) * 8) * 2;
            uint32_t bhi[2], blo[2];
            ldmx2(bhi, WhiB + woff);
            ldmx2(blo, WloB + woff);
            mma16816(c, ahi, bhi);
            mma16816(c, alo, bhi);
            mma16816(c, ahi, blo);
        }
        __syncthreads();
    }

    // reduce k-split halves
    if (kh == 1) {
#pragma unroll
        for (int i = 0; i < 4; i++) red[(mt * 32 + lane) * 4 + i] = c[i];
    }
    __syncthreads();
    if (kh == 0) {
#pragma unroll
        for (int i = 0; i < 4; i++) c[i] += red[(mt * 32 + lane) * 4 + i];
        int p0 = mt * 16 + (lane >> 2);
        int h0 = 2 * (lane & 3);
        size_t base = ((size_t)(b * NH) * QLEN + q) * GRD;
        out[base + (size_t)h0 * QLEN * GRD + p0]           = c[0];
        out[base + (size_t)(h0 + 1) * QLEN * GRD + p0]     = c[1];
        out[base + (size_t)h0 * QLEN * GRD + p0 + 8]       = c[2];
        out[base + (size_t)(h0 + 1) * QLEN * GRD + p0 + 8] = c[3];
    }
}

// ---------------- HMMA flash attention (cp.async double-buffered K/V) ----------------
#define PK 40
#define PR 68
#define QS_OFF  0
#define KS_OFF  5120
#define VS_OFF  15360
#define RX_OFF  25600
#define RY_OFF  43008
#define MK_OFF  60416
#define ATTN_SMEM 76800

__global__ void __launch_bounds__(128) attn_mma(const int* __restrict__ mask)
{
    extern __shared__ char smem[];
    __half* Qs  = (__half*)(smem + QS_OFF);
    float*  rxs = (float*)(smem + RX_OFF);
    float*  rys = (float*)(smem + RY_OFF);
    float*  mks = (float*)(smem + MK_OFF);

    const int tid = threadIdx.x;
    const int lane = tid & 31;
    const int wid = tid >> 5;
    const int bh = blockIdx.y;
    const int b = bh >> 3;
    const int head = bh & 7;
    const int q0 = blockIdx.x * 64;

    const __half* Kb = d_Kh + (size_t)bh * KVLEN * HD;
    const __half* Vb = d_Vh + (size_t)bh * KVLEN * HD;

    const int srow = tid >> 1, sseg = (tid & 1) * 16;
    // prefetch tile 0
    {
        uint32_t kd = smem_u32(smem + KS_OFF) + (uint32_t)(srow * PK + sseg) * 2;
        uint32_t vd = smem_u32(smem + VS_OFF) + (uint32_t)(srow * PK + sseg) * 2;
        const __half* ks = Kb + (size_t)srow * HD + sseg;
        const __half* vs = Vb + (size_t)srow * HD + sseg;
        CP16(kd, ks); CP16(kd + 16, ks + 8);
        CP16(vd, vs); CP16(vd + 16, vs + 8);
        CP_COMMIT();
    }

    const int* mb = mask + b * KVLEN;
    for (int i = tid; i < KVLEN; i += 128) mks[i] = -100.0f * (float)mb[i];

    {
        int row = tid >> 1, seg = tid & 1;
        int q = q0 + row;
        uint4 v0 = make_uint4(0, 0, 0, 0), v1 = make_uint4(0, 0, 0, 0);
        if (q < QLEN) {
            const uint4* qp = (const uint4*)(d_Qh + ((size_t)bh * QLEN + q) * HD + seg * 16);
            v0 = qp[0]; v1 = qp[1];
        }
        *(uint4*)(Qs + row * PK + seg * 16)     = v0;
        *(uint4*)(Qs + row * PK + seg * 16 + 8) = v1;
    }
    {
        int row = tid >> 1, sb = (tid & 1) * 32;
        int q = q0 + row;
        if (q < QLEN) {
            const float4* px = (const float4*)(d_rpex + ((size_t)bh * QLEN + q) * GRD + sb);
            const float4* py = (const float4*)(d_rpey + ((size_t)bh * QLEN + q) * GRD + sb);
#pragma unroll
            for (int u = 0; u < 8; u++) {
                *(float4*)(rxs + row * PR + sb + u * 4) = px[u];
                *(float4*)(rys + row * PR + sb + u * 4) = py[u];
            }
        } else {
            float4 z = make_float4(0.f, 0.f, 0.f, 0.f);
#pragma unroll
            for (int u = 0; u < 8; u++) {
                *(float4*)(rxs + row * PR + sb + u * 4) = z;
                *(float4*)(rys + row * PR + sb + u * 4) = z;
            }
        }
    }
    __syncthreads();

    uint32_t aQ[2][4];
    {
        uint32_t base = smem_u32(Qs);
        int m = wid * 16 + (lane & 15);
        uint32_t a0 = base + (uint32_t)(m * PK + ((lane >> 4) * 8)) * 2;
        ldmx4(aQ[0], a0);
        ldmx4(aQ[1], a0 + 32);
    }

    float oc[4][4];
#pragma unroll
    for (int i = 0; i < 4; i++)
#pragma unroll
        for (int j = 0; j < 4; j++) oc[i][j] = 0.f;
    float m_run0 = -1e30f, m_run1 = -1e30f, l_run0 = 0.f, l_run1 = 0.f;

    const int r0 = wid * 16 + (lane >> 2);
    const int cb = 2 * (lane & 3);

    for (int t = 0; t < 64; t++) {
        if (t + 1 < 64) {
            int buf = (t + 1) & 1;
            uint32_t kd = smem_u32(smem + KS_OFF + buf * 5120) + (uint32_t)(srow * PK + sseg) * 2;
            uint32_t vd = smem_u32(smem + VS_OFF + buf * 5120) + (uint32_t)(srow * PK + sseg) * 2;
            const __half* ks = Kb + (size_t)((t + 1) * 64 + srow) * HD + sseg;
            const __half* vs = Vb + (size_t)((t + 1) * 64 + srow) * HD + sseg;
            CP16(kd, ks); CP16(kd + 16, ks + 8);
            CP16(vd, vs); CP16(vd + 16, vs + 8);
            CP_COMMIT();
            CP_WAIT1();
        } else {
            CP_WAIT0();
        }
        __syncthreads();

        const uint32_t KsB = smem_u32(smem + KS_OFF + (t & 1) * 5120);
        const uint32_t VsB = smem_u32(smem + VS_OFF + (t & 1) * 5120);

        float sc[8][4];
#pragma unroll
        for (int j = 0; j < 8; j++) {
            sc[j][0] = sc[j][1] = sc[j][2] = sc[j][3] = 0.f;
            uint32_t addr = KsB + (uint32_t)((j * 8 + (lane & 7)) * PK + ((lane >> 3) & 1) * 8) * 2;
            uint32_t bk0[2], bk1[2];
            ldmx2(bk0, addr);
            ldmx2(bk1, addr + 32);
            mma16816(sc[j], aQ[0], bk0);
            mma16816(sc[j], aQ[1], bk1);
        }

        float ry0 = rys[r0 * PR + t];
        float ry1 = rys[(r0 + 8) * PR + t];
        float mx0 = -1e30f, mx1 = -1e30f;
#pragma unroll
        for (int j = 0; j < 8; j++) {
            int n = j * 8 + cb;
            float2 rxa = *(float2*)(rxs + r0 * PR + n);
            float2 rxb = *(float2*)(rxs + (r0 + 8) * PR + n);
            float2 mk  = *(float2*)(mks + t * 64 + n);
            sc[j][0] += rxa.x + ry0 + mk.x;
            sc[j][1] += rxa.y + ry0 + mk.y;
            sc[j][2] += rxb.x + ry1 + mk.x;
            sc[j][3] += rxb.y + ry1 + mk.y;
            mx0 = fmaxf(mx0, fmaxf(sc[j][0], sc[j][1]));
            mx1 = fmaxf(mx1, fmaxf(sc[j][2], sc[j][3]));
        }
        mx0 = fmaxf(mx0, __shfl_xor_sync(0xffffffffu, mx0, 1));
        mx0 = fmaxf(mx0, __shfl_xor_sync(0xffffffffu, mx0, 2));
        mx1 = fmaxf(mx1, __shfl_xor_sync(0xffffffffu, mx1, 1));
        mx1 = fmaxf(mx1, __shfl_xor_sync(0xffffffffu, mx1, 2));

        float mn0 = fmaxf(m_run0, mx0), mn1 = fmaxf(m_run1, mx1);
        float f0 = __expf(m_run0 - mn0), f1 = __expf(m_run1 - mn1);
        m_run0 = mn0; m_run1 = mn1;

        float la0 = 0.f, la1 = 0.f;
        uint32_t pa[4][4];
#pragma unroll
        for (int j = 0; j < 8; j++) {
            float p0 = __expf(sc[j][0] - mn0);
            float p1 = __expf(sc[j][1] - mn0);
            float p2 = __expf(sc[j][2] - mn1);
            float p3 = __expf(sc[j][3] - mn1);
            la0 += p0 + p1; la1 += p2 + p3;
            int kt = j >> 1, hi = j & 1;
            pa[kt][2 * hi]     = packh2(p0, p1);
            pa[kt][2 * hi + 1] = packh2(p2, p3);
        }
        la0 += __shfl_xor_sync(0xffffffffu, la0, 1);
        la0 += __shfl_xor_sync(0xffffffffu, la0, 2);
        la1 += __shfl_xor_sync(0xffffffffu, la1, 1);
        la1 += __shfl_xor_sync(0xffffffffu, la1, 2);
        l_run0 = l_run0 * f0 + la0;
        l_run1 = l_run1 * f1 + la1;

#pragma unroll
        for (int no = 0; no < 4; no++) {
            oc[no][0] *= f0; oc[no][1] *= f0;
            oc[no][2] *= f1; oc[no][3] *= f1;
        }

#pragma unroll
        for (int kt = 0; kt < 4; kt++) {
            uint32_t addr = VsB + (uint32_t)((kt * 16 + (lane & 15)) * PK) * 2;
#pragma unroll
            for (int no = 0; no < 4; no++) {
                uint32_t bv[2];
                ldmx2t(bv, addr + (uint32_t)(no * 8) * 2);
                mma16816(oc[no], pa[kt], bv);
            }
        }
        __syncthreads();
    }

    {
        float inv0 = 1.0f / l_run0;
        float inv1 = 1.0f / l_run1;
        int qa = q0 + r0, qb = qa + 8;
#pragma unroll
        for (int no = 0; no < 4; no++) {
            int col = head * HD + no * 8 + cb;
            if (qa < QLEN) {
                *(uint32_t*)&d_ctxh[((size_t)b * QLEN + qa) * DIMV + col] =
                    packh2(oc[no][0] * inv0, oc[no][1] * inv0);
            }
            if (qb < QLEN) {
                *(uint32_t*)&d_ctxh[((size_t)b * QLEN + qb) * DIMV + col] =
                    packh2(oc[no][2] * inv1, oc[no][3] * inv1);
            }
        }
    }
}

// ---------------- launch ----------------
extern "C" void kernel_launch(void* const* d_in, const int* in_sizes, int n_in,
                              void* d_out, int out_size)
{
    const float* hidden = (const float*)d_in[0];
    const float* refpts = (const float*)d_in[1];
    const float* kvst   = (const float*)d_in[2];
    const int*   amask  = (const int*)d_in[4];
    const float* m1w1 = (const float*)d_in[5];
    const float* m1b1 = (const float*)d_in[6];
    const float* m1w2 = (const float*)d_in[7];
    const float* m2w1 = (const float*)d_in[8];
    const float* m2b1 = (const float*)d_in[9];
    const float* m2w2 = (const float*)d_in[10];
    const float* qb = (const float*)d_in[12];
    const float* kb = (const float*)d_in[14];
    const float* vb = (const float*)d_in[16];
    const float* ob = (const float*)d_in[18];
    const float* qw = (const float*)d_in[11];
    const float* kw = (const float*)d_in[13];
    const float* vw = (const float*)d_in[15];
    const float* ow = (const float*)d_in[17];
    float* out = (float*)d_out;

    void *pQ, *pK, *pV, *pRX, *pRY, *pCTX, *pWh, *pAkv, *pAq;
    cudaGetSymbolAddress(&pQ,   d_Qh);
    cudaGetSymbolAddress(&pK,   d_Kh);
    cudaGetSymbolAddress(&pV,   d_Vh);
    cudaGetSymbolAddress(&pRX,  d_rpex);
    cudaGetSymbolAddress(&pRY,  d_rpey);
    cudaGetSymbolAddress(&pCTX, d_ctxh);
    cudaGetSymbolAddress(&pWh,  d_Wh);
    cudaGetSymbolAddress(&pAkv, d_Akv);
    cudaGetSymbolAddress(&pAq,  d_Aq);

    cudaFuncSetAttribute(attn_mma, cudaFuncAttributeMaxDynamicSharedMemorySize, ATTN_SMEM);
    cudaFuncSetAttribute(rpe_tc,   cudaFuncAttributeMaxDynamicSharedMemorySize, RPE_SMEM);

    const float qscale = 0.17677669529663687f;  // 1/sqrt(32)
    __half* Wh = (__half*)pWh;

    convert_all<<<2754, 256>>>(qw, kw, vw, ow, kvst, hidden);
    gemm_dual<<<dim3(64, 4), 256>>>((const __half*)pAkv, Wh + 65536, kb, pK,
                                    Wh + 131072, vb, pV, B_ * KVLEN, KVLEN, 1.0f, 1);
    gemm_dual<<<dim3(15, 4), 256>>>((const __half*)pAq, Wh, qb, pQ,
                                    nullptr, nullptr, nullptr, B_ * QLEN, QLEN, qscale, 1);
    rpe_tc<<<dim3(QLEN, B_, 2), 256, RPE_SMEM>>>(refpts, m1w1, m1b1, m1w2,
                                                 m2w1, m2b1, m2w2, (float*)pRX, (float*)pRY);
    attn_mma<<<dim3((QLEN + 63) / 64, B_ * NH), 128, ATTN_SMEM>>>(amask);
    gemm_dual<<<dim3(15, 4), 256>>>((const __half*)pCTX, Wh + 196608, ob, out,
                                    nullptr, nullptr, nullptr, B_ * QLEN, QLEN, 1.0f, 0);
}

// round 8
// speedup vs baseline: 1.8219x; 1.8219x over previous
#include <cuda_runtime.h>
#include <cuda_fp16.h>
#include <cstdint>

#define B_    2
#define QLEN  900
#define DIMV  256
#define NH    8
#define HD    32
#define KVLEN 4096
#define GRD   64
#define RPEH  512

// ---------------- scratch ----------------
__device__ __half d_Qh[B_*NH*QLEN*HD];     // (b,h,q,32) f16 pre-scaled
__device__ __half d_Kh[B_*NH*KVLEN*HD];    // (b,h,kv,32) f16
__device__ __half d_Vh[B_*NH*KVLEN*HD];    // (b,h,kv,32) f16
__device__ __half d_ctxh[B_*QLEN*DIMV];    // (b,q,256) f16
__device__ float  d_rpex[B_*NH*QLEN*GRD];
__device__ float  d_rpey[B_*NH*QLEN*GRD];
__device__ __half d_Wh[4*65536];           // qw,kw,vw,ow f16
__device__ __half d_Akv[B_*KVLEN*DIMV];    // kvst f16
__device__ __half d_Aq[B_*QLEN*DIMV];      // hidden f16

// ---------------- helpers ----------------
__device__ __forceinline__ void ldmx4(uint32_t* r, uint32_t a) {
    asm volatile("ldmatrix.sync.aligned.m8n8.x4.shared.b16 {%0,%1,%2,%3}, [%4];"
                 : "=r"(r[0]), "=r"(r[1]), "=r"(r[2]), "=r"(r[3]) : "r"(a));
}
__device__ __forceinline__ void ldmx2(uint32_t* r, uint32_t a) {
    asm volatile("ldmatrix.sync.aligned.m8n8.x2.shared.b16 {%0,%1}, [%2];"
                 : "=r"(r[0]), "=r"(r[1]) : "r"(a));
}
__device__ __forceinline__ void ldmx2t(uint32_t* r, uint32_t a) {
    asm volatile("ldmatrix.sync.aligned.m8n8.x2.trans.shared.b16 {%0,%1}, [%2];"
                 : "=r"(r[0]), "=r"(r[1]) : "r"(a));
}
__device__ __forceinline__ void mma16816(float* c, const uint32_t* a, const uint32_t* b) {
    asm volatile("mma.sync.aligned.m16n8k16.row.col.f32.f16.f16.f32 "
                 "{%0,%1,%2,%3}, {%4,%5,%6,%7}, {%8,%9}, {%0,%1,%2,%3};"
                 : "+f"(c[0]), "+f"(c[1]), "+f"(c[2]), "+f"(c[3])
                 : "r"(a[0]), "r"(a[1]), "r"(a[2]), "r"(a[3]), "r"(b[0]), "r"(b[1]));
}
__device__ __forceinline__ uint32_t smem_u32(const void* p) {
    return (uint32_t)__cvta_generic_to_shared(p);
}
__device__ __forceinline__ uint32_t packh2(float a, float b) {
    __half2 h = __floats2half2_rn(a, b);
    return *(uint32_t*)&h;
}
#define CP16(dst, src) asm volatile("cp.async.cg.shared.global [%0], [%1], 16;" :: "r"(dst), "l"(src) : "memory")
#define CP_COMMIT() asm volatile("cp.async.commit_group;" ::: "memory")
#define CP_WAIT1() asm volatile("cp.async.wait_group 1;" ::: "memory")
#define CP_WAIT0() asm volatile("cp.async.wait_group 0;" ::: "memory")

// ---------------- one-shot fp32 -> f16 convert ----------------
__global__ void convert_all(const float* __restrict__ qw, const float* __restrict__ kw,
                            const float* __restrict__ vw, const float* __restrict__ ow,
                            const float* __restrict__ kvst, const float* __restrict__ hidden)
{
    unsigned u = blockIdx.x * 256 + threadIdx.x;
    const float* src; __half* dst; unsigned off;
    if      (u <  16384) { src = qw;     dst = d_Wh;          off = u; }
    else if (u <  32768) { src = kw;     dst = d_Wh + 65536;  off = u - 16384; }
    else if (u <  49152) { src = vw;     dst = d_Wh + 131072; off = u - 32768; }
    else if (u <  65536) { src = ow;     dst = d_Wh + 196608; off = u - 49152; }
    else if (u < 589824) { src = kvst;   dst = d_Akv;         off = u - 65536; }
    else                 { src = hidden; dst = d_Aq;          off = u - 589824; }
    float4 f = ((const float4*)src)[off];
    uint2 o; o.x = packh2(f.x, f.y); o.y = packh2(f.z, f.w);
    ((uint2*)dst)[off] = o;
}

// ---------------- HMMA GEMM 128x64 tile, optional dual weights ----------------
__global__ void __launch_bounds__(256) gemm_dual(
    const __half* __restrict__ Ah,
    const __half* __restrict__ W1, const float* __restrict__ b1v, void* __restrict__ C1,
    const __half* __restrict__ W2, const float* __restrict__ b2v, void* __restrict__ C2,
    int M, int rpb, float scale, int mode)
{
    __shared__ __half As[128 * 40];
    __shared__ __half Ws1[64 * 40];
    __shared__ __half Ws2[64 * 40];

    const int tid = threadIdx.x;
    const int lane = tid & 31;
    const int wid = tid >> 5;
    const int bm = blockIdx.x * 128;
    const int bn = blockIdx.y * 64;
    const bool dual = (W2 != nullptr);

    const int arow = tid >> 1, aseg = (tid & 1) * 16;
    const int wrow = tid >> 2, wseg = (tid & 3) * 8;

    float c1[8][4], c2[8][4];
#pragma unroll
    for (int j = 0; j < 8; j++) {
        c1[j][0] = c1[j][1] = c1[j][2] = c1[j][3] = 0.f;
        c2[j][0] = c2[j][1] = c2[j][2] = c2[j][3] = 0.f;
    }

    const uint32_t AsB = smem_u32(As);
    const uint32_t W1B = smem_u32(Ws1);
    const uint32_t W2B = smem_u32(Ws2);

    uint4 pa0 = make_uint4(0,0,0,0), pa1 = pa0, pw1, pw2 = make_uint4(0,0,0,0);
    if (bm + arow < M) {
        const uint4* ap = (const uint4*)&Ah[(size_t)(bm + arow) * 256 + aseg];
        pa0 = ap[0]; pa1 = ap[1];
    }
    pw1 = *(const uint4*)&W1[(size_t)(bn + wrow) * 256 + wseg];
    if (dual) pw2 = *(const uint4*)&W2[(size_t)(bn + wrow) * 256 + wseg];

#pragma unroll 1
    for (int kit = 0; kit < 8; kit++) {
        *(uint4*)&As[arow * 40 + aseg]     = pa0;
        *(uint4*)&As[arow * 40 + aseg + 8] = pa1;
        *(uint4*)&Ws1[wrow * 40 + wseg]    = pw1;
        if (dual) *(uint4*)&Ws2[wrow * 40 + wseg] = pw2;
        __syncthreads();

        if (kit < 7) {
            int k0 = (kit + 1) * 32;
            pa0 = make_uint4(0,0,0,0); pa1 = pa0;
            if (bm + arow < M) {
                const uint4* ap = (const uint4*)&Ah[(size_t)(bm + arow) * 256 + k0 + aseg];
                pa0 = ap[0]; pa1 = ap[1];
            }
            pw1 = *(const uint4*)&W1[(size_t)(bn + wrow) * 256 + k0 + wseg];
            if (dual) pw2 = *(const uint4*)&W2[(size_t)(bn + wrow) * 256 + k0 + wseg];
        }

        uint32_t a0[4], a1[4];
        uint32_t aa = AsB + (uint32_t)((wid * 16 + (lane & 15)) * 40 + ((lane >> 4) * 8)) * 2;
        ldmx4(a0, aa);
        ldmx4(a1, aa + 32);
#pragma unroll
        for (int j = 0; j < 8; j++) {
            uint32_t woff = (uint32_t)((j * 8 + (lane & 7)) * 40 + ((lane >> 3) & 1) * 8) * 2;
            uint32_t b0[2], b1[2];
            ldmx2(b0, W1B + woff);
            ldmx2(b1, W1B + woff + 32);
            mma16816(c1[j], a0, b0);
            mma16816(c1[j], a1, b1);
            if (dual) {
                ldmx2(b0, W2B + woff);
                ldmx2(b1, W2B + woff + 32);
                mma16816(c2[j], a0, b0);
                mma16816(c2[j], a1, b1);
            }
        }
        __syncthreads();
    }

    const int r0 = bm + wid * 16 + (lane >> 2);
    const int cb = 2 * (lane & 3);
    if (mode == 0) {
        float* C = (float*)C1;
#pragma unroll
        for (int j = 0; j < 8; j++) {
            int col = bn + j * 8 + cb;
            float bb0 = b1v[col], bb1 = b1v[col + 1];
            if (r0 < M)     *(float2*)&C[(size_t)r0 * 256 + col]       = make_float2((c1[j][0] + bb0) * scale, (c1[j][1] + bb1) * scale);
            if (r0 + 8 < M) *(float2*)&C[(size_t)(r0 + 8) * 256 + col] = make_float2((c1[j][2] + bb0) * scale, (c1[j][3] + bb1) * scale);
        }
    } else {
        __half* Ca = (__half*)C1;
        __half* Cb = (__half*)C2;
        int ba = r0 / rpb, ra = r0 - ba * rpb;
        int bb = (r0 + 8) / rpb, rb = (r0 + 8) - bb * rpb;
#pragma unroll
        for (int j = 0; j < 8; j++) {
            int col = bn + j * 8 + cb;
            int head = col >> 5, d = col & 31;
            float x0 = b1v[col], x1 = b1v[col + 1];
            if (r0 < M) {
                *(uint32_t*)&Ca[((size_t)((ba * NH + head) * rpb + ra)) * HD + d] =
                    packh2((c1[j][0] + x0) * scale, (c1[j][1] + x1) * scale);
            }
            if (r0 + 8 < M) {
                *(uint32_t*)&Ca[((size_t)((bb * NH + head) * rpb + rb)) * HD + d] =
                    packh2((c1[j][2] + x0) * scale, (c1[j][3] + x1) * scale);
            }
            if (dual) {
                float y0 = b2v[col], y1 = b2v[col + 1];
                if (r0 < M) {
                    *(uint32_t*)&Cb[((size_t)((ba * NH + head) * rpb + ra)) * HD + d] =
                        packh2((c2[j][0] + y0) * scale, (c2[j][1] + y1) * scale);
                }
                if (r0 + 8 < M) {
                    *(uint32_t*)&Cb[((size_t)((bb * NH + head) * rpb + rb)) * HD + d] =
                        packh2((c2[j][2] + y0) * scale, (c2[j][3] + y1) * scale);
                }
            }
        }
    }
}

// ---------------- RPE v2: A-fragments computed in registers, hi/lo 3-MMA ----------------
// block = (q pair, b, axis); 8 warps = 2 queries x 4 m-tiles (p 0..63).
__global__ void __launch_bounds__(256) rpe_tc2(
    const float* __restrict__ refpts,
    const float* __restrict__ w1a, const float* __restrict__ b1a, const float* __restrict__ w2a,
    const float* __restrict__ w1b, const float* __restrict__ b1b, const float* __restrict__ w2b,
    float* __restrict__ outx, float* __restrict__ outy)
{
    __shared__ __half  w2hi[8 * 520];
    __shared__ __half  w2lo[8 * 520];
    __shared__ float2  as2[2][512];   // (a_j, s_j) interleaved, per query

    const int tid = threadIdx.x;
    const int lane = tid & 31;
    const int wid = tid >> 5;
    const int qp = blockIdx.x;
    const int b = blockIdx.y;
    const int axis = blockIdx.z;

    const float* w1  = axis ? w1b : w1a;
    const float* bb1 = axis ? b1b : b1a;
    const float* w2  = axis ? w2b : w2a;
    float* out = axis ? outy : outx;

    // stage w2 hi/lo (once per block, serves 8 warps)
    for (int i = tid; i < RPEH * NH; i += 256) {
        int h = i >> 9, j = i & 511;
        float f = w2[h * RPEH + j];
        __half fh = __float2half_rn(f);
        w2hi[h * 520 + j] = fh;
        w2lo[h * 520 + j] = __float2half_rn(f - __half2float(fh));
    }
    // (a_j, s_j) for the 2 queries
    for (int i = tid; i < 2 * RPEH; i += 256) {
        int qi = i >> 9, j = i & 511;
        const float* rp = refpts + ((size_t)b * QLEN + qp * 2 + qi) * 4;
        float cc = rp[axis], ss = rp[2 + axis];
        float lo = (cc - 0.5f * ss) * 1024.0f;
        float hi = (cc + 0.5f * ss) * 1024.0f;
        float wx = w1[j * 2], wy = w1[j * 2 + 1];
        as2[qi][j] = make_float2(wx * lo + wy * hi + bb1[j], wx + wy);
    }
    __syncthreads();

    const int qi = wid >> 2;          // query within pair
    const int mt = wid & 3;           // m-tile (p block of 16)
    const int q  = qp * 2 + qi;
    const int r  = lane >> 2;
    const int c0 = 2 * (lane & 3);
    const float px0 = (mt * 16 + r + 0.5f) * 16.0f;
    const float px1 = px0 + 128.0f;   // +8 positions

    const uint32_t WhiB = smem_u32(w2hi);
    const uint32_t WloB = smem_u32(w2lo);
    const float2* asq = as2[qi];

    float c[4] = {0.f, 0.f, 0.f, 0.f};

#pragma unroll 4
    for (int kk = 0; kk < 32; kk++) {
        int j0 = kk * 16 + c0;
        float4 v0 = *(const float4*)&asq[j0];       // a(j0), s(j0), a(j0+1), s(j0+1)
        float4 v1 = *(const float4*)&asq[j0 + 8];

        float hA0 = fmaxf(v0.x - v0.y * px0, 0.f);
        float hA1 = fmaxf(v0.z - v0.w * px0, 0.f);
        float hB0 = fmaxf(v0.x - v0.y * px1, 0.f);
        float hB1 = fmaxf(v0.z - v0.w * px1, 0.f);
        float hA2 = fmaxf(v1.x - v1.y * px0, 0.f);
        float hA3 = fmaxf(v1.z - v1.w * px0, 0.f);
        float hB2 = fmaxf(v1.x - v1.y * px1, 0.f);
        float hB3 = fmaxf(v1.z - v1.w * px1, 0.f);

        uint32_t ahi[4], alo[4];
        {
            __half2 t; float2 f;
            t = __floats2half2_rn(hA0, hA1); ahi[0] = *(uint32_t*)&t;
            f = __half22float2(t);
            t = __floats2half2_rn(hA0 - f.x, hA1 - f.y); alo[0] = *(uint32_t*)&t;
            t = __floats2half2_rn(hB0, hB1); ahi[1] = *(uint32_t*)&t;
            f = __half22float2(t);
            t = __floats2half2_rn(hB0 - f.x, hB1 - f.y); alo[1] = *(uint32_t*)&t;
            t = __floats2half2_rn(hA2, hA3); ahi[2] = *(uint32_t*)&t;
            f = __half22float2(t);
            t = __floats2half2_rn(hA2 - f.x, hA3 - f.y); alo[2] = *(uint32_t*)&t;
            t = __floats2half2_rn(hB2, hB3); ahi[3] = *(uint32_t*)&t;
            f = __half22float2(t);
            t = __floats2half2_rn(hB2 - f.x, hB3 - f.y); alo[3] = *(uint32_t*)&t;
        }

        uint32_t woff = (uint32_t)((lane & 7) * 520 + kk * 16 + ((lane >> 3) & 1) * 8) * 2;
        uint32_t bhi[2], blo[2];
        ldmx2(bhi, WhiB + woff);
        ldmx2(blo, WloB + woff);
        mma16816(c, ahi, bhi);
        mma16816(c, alo, bhi);
        mma16816(c, ahi, blo);
    }

    // output: rows p0/p0+8, heads c0/c0+1
    {
        int p0 = mt * 16 + r;
        size_t hstride = (size_t)QLEN * GRD;
        size_t base = ((size_t)(b * NH + c0) * QLEN + q) * GRD;
        out[base + p0]                = c[0];
        out[base + hstride + p0]      = c[1];
        out[base + p0 + 8]            = c[2];
        out[base + hstride + p0 + 8]  = c[3];
    }
}

// ---------------- HMMA flash attention (cp.async double-buffered K/V) ----------------
#define PK 40
#define PR 68
#define QS_OFF  0
#define KS_OFF  5120
#define VS_OFF  15360
#define RX_OFF  25600
#define RY_OFF  43008
#define MK_OFF  60416
#define ATTN_SMEM 76800

__global__ void __launch_bounds__(128) attn_mma(const int* __restrict__ mask)
{
    extern __shared__ char smem[];
    __half* Qs  = (__half*)(smem + QS_OFF);
    float*  rxs = (float*)(smem + RX_OFF);
    float*  rys = (float*)(smem + RY_OFF);
    float*  mks = (float*)(smem + MK_OFF);

    const int tid = threadIdx.x;
    const int lane = tid & 31;
    const int wid = tid >> 5;
    const int bh = blockIdx.y;
    const int b = bh >> 3;
    const int head = bh & 7;
    const int q0 = blockIdx.x * 64;

    const __half* Kb = d_Kh + (size_t)bh * KVLEN * HD;
    const __half* Vb = d_Vh + (size_t)bh * KVLEN * HD;

    const int srow = tid >> 1, sseg = (tid & 1) * 16;
    {
        uint32_t kd = smem_u32(smem + KS_OFF) + (uint32_t)(srow * PK + sseg) * 2;
        uint32_t vd = smem_u32(smem + VS_OFF) + (uint32_t)(srow * PK + sseg) * 2;
        const __half* ks = Kb + (size_t)srow * HD + sseg;
        const __half* vs = Vb + (size_t)srow * HD + sseg;
        CP16(kd, ks); CP16(kd + 16, ks + 8);
        CP16(vd, vs); CP16(vd + 16, vs + 8);
        CP_COMMIT();
    }

    const int* mb = mask + b * KVLEN;
    for (int i = tid; i < KVLEN; i += 128) mks[i] = -100.0f * (float)mb[i];

    {
        int row = tid >> 1, seg = tid & 1;
        int q = q0 + row;
        uint4 v0 = make_uint4(0, 0, 0, 0), v1 = make_uint4(0, 0, 0, 0);
        if (q < QLEN) {
            const uint4* qp = (const uint4*)(d_Qh + ((size_t)bh * QLEN + q) * HD + seg * 16);
            v0 = qp[0]; v1 = qp[1];
        }
        *(uint4*)(Qs + row * PK + seg * 16)     = v0;
        *(uint4*)(Qs + row * PK + seg * 16 + 8) = v1;
    }
    {
        int row = tid >> 1, sb = (tid & 1) * 32;
        int q = q0 + row;
        if (q < QLEN) {
            const float4* px = (const float4*)(d_rpex + ((size_t)bh * QLEN + q) * GRD + sb);
            const float4* py = (const float4*)(d_rpey + ((size_t)bh * QLEN + q) * GRD + sb);
#pragma unroll
            for (int u = 0; u < 8; u++) {
                *(float4*)(rxs + row * PR + sb + u * 4) = px[u];
                *(float4*)(rys + row * PR + sb + u * 4) = py[u];
            }
        } else {
            float4 z = make_float4(0.f, 0.f, 0.f, 0.f);
#pragma unroll
            for (int u = 0; u < 8; u++) {
                *(float4*)(rxs + row * PR + sb + u * 4) = z;
                *(float4*)(rys + row * PR + sb + u * 4) = z;
            }
        }
    }
    __syncthreads();

    uint32_t aQ[2][4];
    {
        uint32_t base = smem_u32(Qs);
        int m = wid * 16 + (lane & 15);
        uint32_t a0 = base + (uint32_t)(m * PK + ((lane >> 4) * 8)) * 2;
        ldmx4(aQ[0], a0);
        ldmx4(aQ[1], a0 + 32);
    }

    float oc[4][4];
#pragma unroll
    for (int i = 0; i < 4; i++)
#pragma unroll
        for (int j = 0; j < 4; j++) oc[i][j] = 0.f;
    float m_run0 = -1e30f, m_run1 = -1e30f, l_run0 = 0.f, l_run1 = 0.f;

    const int r0 = wid * 16 + (lane >> 2);
    const int cb = 2 * (lane & 3);

    for (int t = 0; t < 64; t++) {
        if (t + 1 < 64) {
            int buf = (t + 1) & 1;
            uint32_t kd = smem_u32(smem + KS_OFF + buf * 5120) + (uint32_t)(srow * PK + sseg) * 2;
            uint32_t vd = smem_u32(smem + VS_OFF + buf * 5120) + (uint32_t)(srow * PK + sseg) * 2;
            const __half* ks = Kb + (size_t)((t + 1) * 64 + srow) * HD + sseg;
            const __half* vs = Vb + (size_t)((t + 1) * 64 + srow) * HD + sseg;
            CP16(kd, ks); CP16(kd + 16, ks + 8);
            CP16(vd, vs); CP16(vd + 16, vs + 8);
            CP_COMMIT();
            CP_WAIT1();
        } else {
            CP_WAIT0();
        }
        __syncthreads();

        const uint32_t KsB = smem_u32(smem + KS_OFF + (t & 1) * 5120);
        const uint32_t VsB = smem_u32(smem + VS_OFF + (t & 1) * 5120);

        float sc[8][4];
#pragma unroll
        for (int j = 0; j < 8; j++) {
            sc[j][0] = sc[j][1] = sc[j][2] = sc[j][3] = 0.f;
            uint32_t addr = KsB + (uint32_t)((j * 8 + (lane & 7)) * PK + ((lane >> 3) & 1) * 8) * 2;
            uint32_t bk0[2], bk1[2];
            ldmx2(bk0, addr);
            ldmx2(bk1, addr + 32);
            mma16816(sc[j], aQ[0], bk0);
            mma16816(sc[j], aQ[1], bk1);
        }

        float ry0 = rys[r0 * PR + t];
        float ry1 = rys[(r0 + 8) * PR + t];
        float mx0 = -1e30f, mx1 = -1e30f;
#pragma unroll
        for (int j = 0; j < 8; j++) {
            int n = j * 8 + cb;
            float2 rxa = *(float2*)(rxs + r0 * PR + n);
            float2 rxb = *(float2*)(rxs + (r0 + 8) * PR + n);
            float2 mk  = *(float2*)(mks + t * 64 + n);
            sc[j][0] += rxa.x + ry0 + mk.x;
            sc[j][1] += rxa.y + ry0 + mk.y;
            sc[j][2] += rxb.x + ry1 + mk.x;
            sc[j][3] += rxb.y + ry1 + mk.y;
            mx0 = fmaxf(mx0, fmaxf(sc[j][0], sc[j][1]));
            mx1 = fmaxf(mx1, fmaxf(sc[j][2], sc[j][3]));
        }
        mx0 = fmaxf(mx0, __shfl_xor_sync(0xffffffffu, mx0, 1));
        mx0 = fmaxf(mx0, __shfl_xor_sync(0xffffffffu, mx0, 2));
        mx1 = fmaxf(mx1, __shfl_xor_sync(0xffffffffu, mx1, 1));
        mx1 = fmaxf(mx1, __shfl_xor_sync(0xffffffffu, mx1, 2));

        float mn0 = fmaxf(m_run0, mx0), mn1 = fmaxf(m_run1, mx1);
        float f0 = __expf(m_run0 - mn0), f1 = __expf(m_run1 - mn1);
        m_run0 = mn0; m_run1 = mn1;

        float la0 = 0.f, la1 = 0.f;
        uint32_t pa[4][4];
#pragma unroll
        for (int j = 0; j < 8; j++) {
            float p0 = __expf(sc[j][0] - mn0);
            float p1 = __expf(sc[j][1] - mn0);
            float p2 = __expf(sc[j][2] - mn1);
            float p3 = __expf(sc[j][3] - mn1);
            la0 += p0 + p1; la1 += p2 + p3;
            int kt = j >> 1, hi = j & 1;
            pa[kt][2 * hi]     = packh2(p0, p1);
            pa[kt][2 * hi + 1] = packh2(p2, p3);
        }
        la0 += __shfl_xor_sync(0xffffffffu, la0, 1);
        la0 += __shfl_xor_sync(0xffffffffu, la0, 2);
        la1 += __shfl_xor_sync(0xffffffffu, la1, 1);
        la1 += __shfl_xor_sync(0xffffffffu, la1, 2);
        l_run0 = l_run0 * f0 + la0;
        l_run1 = l_run1 * f1 + la1;

#pragma unroll
        for (int no = 0; no < 4; no++) {
            oc[no][0] *= f0; oc[no][1] *= f0;
            oc[no][2] *= f1; oc[no][3] *= f1;
        }

#pragma unroll
        for (int kt = 0; kt < 4; kt++) {
            uint32_t addr = VsB + (uint32_t)((kt * 16 + (lane & 15)) * PK) * 2;
#pragma unroll
            for (int no = 0; no < 4; no++) {
                uint32_t bv[2];
                ldmx2t(bv, addr + (uint32_t)(no * 8) * 2);
                mma16816(oc[no], pa[kt], bv);
            }
        }
        __syncthreads();
    }

    {
        float inv0 = 1.0f / l_run0;
        float inv1 = 1.0f / l_run1;
        int qa = q0 + r0, qb = qa + 8;
#pragma unroll
        for (int no = 0; no < 4; no++) {
            int col = head * HD + no * 8 + cb;
            if (qa < QLEN) {
                *(uint32_t*)&d_ctxh[((size_t)b * QLEN + qa) * DIMV + col] =
                    packh2(oc[no][0] * inv0, oc[no][1] * inv0);
            }
            if (qb < QLEN) {
                *(uint32_t*)&d_ctxh[((size_t)b * QLEN + qb) * DIMV + col] =
                    packh2(oc[no][2] * inv1, oc[no][3] * inv1);
            }
        }
    }
}

// ---------------- launch ----------------
extern "C" void kernel_launch(void* const* d_in, const int* in_sizes, int n_in,
                              void* d_out, int out_size)
{
    const float* hidden = (const float*)d_in[0];
    const float* refpts = (const float*)d_in[1];
    const float* kvst   = (const float*)d_in[2];
    const int*   amask  = (const int*)d_in[4];
    const float* m1w1 = (const float*)d_in[5];
    const float* m1b1 = (const float*)d_in[6];
    const float* m1w2 = (const float*)d_in[7];
    const float* m2w1 = (const float*)d_in[8];
    const float* m2b1 = (const float*)d_in[9];
    const float* m2w2 = (const float*)d_in[10];
    const float* qw = (const float*)d_in[11];
    const float* qb = (const float*)d_in[12];
    const float* kw = (const float*)d_in[13];
    const float* kb = (const float*)d_in[14];
    const float* vw = (const float*)d_in[15];
    const float* vb = (const float*)d_in[16];
    const float* ow = (const float*)d_in[17];
    const float* ob = (const float*)d_in[18];
    float* out = (float*)d_out;

    void *pQ, *pK, *pV, *pRX, *pRY, *pCTX, *pWh, *pAkv, *pAq;
    cudaGetSymbolAddress(&pQ,   d_Qh);
    cudaGetSymbolAddress(&pK,   d_Kh);
    cudaGetSymbolAddress(&pV,   d_Vh);
    cudaGetSymbolAddress(&pRX,  d_rpex);
    cudaGetSymbolAddress(&pRY,  d_rpey);
    cudaGetSymbolAddress(&pCTX, d_ctxh);
    cudaGetSymbolAddress(&pWh,  d_Wh);
    cudaGetSymbolAddress(&pAkv, d_Akv);
    cudaGetSymbolAddress(&pAq,  d_Aq);

    cudaFuncSetAttribute(attn_mma, cudaFuncAttributeMaxDynamicSharedMemorySize, ATTN_SMEM);

    const float qscale = 0.17677669529663687f;  // 1/sqrt(32)
    __half* Wh = (__half*)pWh;

    convert_all<<<2754, 256>>>(qw, kw, vw, ow, kvst, hidden);
    gemm_dual<<<dim3(64, 4), 256>>>((const __half*)pAkv, Wh + 65536, kb, pK,
                                    Wh + 131072, vb, pV, B_ * KVLEN, KVLEN, 1.0f, 1);
    gemm_dual<<<dim3(15, 4), 256>>>((const __half*)pAq, Wh, qb, pQ,
                                    nullptr, nullptr, nullptr, B_ * QLEN, QLEN, qscale, 1);
    rpe_tc2<<<dim3(QLEN / 2, B_, 2), 256>>>(refpts, m1w1, m1b1, m1w2,
                                            m2w1, m2b1, m2w2, (float*)pRX, (float*)pRY);
    attn_mma<<<dim3((QLEN + 63) / 64, B_ * NH), 128, ATTN_SMEM>>>(amask);
    gemm_dual<<<dim3(15, 4), 256>>>((const __half*)pCTX, Wh + 196608, ob, out,
                                    nullptr, nullptr, nullptr, B_ * QLEN, QLEN, 1.0f, 0);
}

// round 9
// speedup vs baseline: 2.1379x; 1.1734x over previous
#include <cuda_runtime.h>
#include <cuda_fp16.h>
#include <cstdint>

#define B_    2
#define QLEN  900
#define DIMV  256
#define NH    8
#define HD    32
#define KVLEN 4096
#define GRD   64
#define RPEH  512
#define L2E   1.4426950408889634f

// ---------------- scratch ----------------
__device__ __half d_Qh[B_*NH*QLEN*HD];     // (b,h,q,32) f16 pre-scaled (incl. log2e)
__device__ __half d_Kh[B_*NH*KVLEN*HD];    // (b,h,kv,32) f16
__device__ __half d_Vh[B_*NH*KVLEN*HD];    // (b,h,kv,32) f16
__device__ __half d_ctxh[B_*QLEN*DIMV];    // (b,q,256) f16
__device__ float  d_rpex[B_*NH*QLEN*GRD];  // log2e-scaled
__device__ float  d_rpey[B_*NH*QLEN*GRD];  // log2e-scaled
__device__ __half d_Wh[4*65536];           // qw,kw,vw,ow f16
__device__ __half d_Akv[B_*KVLEN*DIMV];    // kvst f16
__device__ __half d_Aq[B_*QLEN*DIMV];      // hidden f16
__device__ __half d_w2hi[2*8*512];         // w2 hi (axis, head, j)
__device__ __half d_w2lo[2*8*512];         // w2 lo
__device__ float  d_mskf[B_*KVLEN];        // -100*log2e*mask

// ---------------- helpers ----------------
__device__ __forceinline__ void ldmx4(uint32_t* r, uint32_t a) {
    asm volatile("ldmatrix.sync.aligned.m8n8.x4.shared.b16 {%0,%1,%2,%3}, [%4];"
                 : "=r"(r[0]), "=r"(r[1]), "=r"(r[2]), "=r"(r[3]) : "r"(a));
}
__device__ __forceinline__ void ldmx2(uint32_t* r, uint32_t a) {
    asm volatile("ldmatrix.sync.aligned.m8n8.x2.shared.b16 {%0,%1}, [%2];"
                 : "=r"(r[0]), "=r"(r[1]) : "r"(a));
}
__device__ __forceinline__ void ldmx2t(uint32_t* r, uint32_t a) {
    asm volatile("ldmatrix.sync.aligned.m8n8.x2.trans.shared.b16 {%0,%1}, [%2];"
                 : "=r"(r[0]), "=r"(r[1]) : "r"(a));
}
__device__ __forceinline__ void mma16816(float* c, const uint32_t* a, const uint32_t* b) {
    asm volatile("mma.sync.aligned.m16n8k16.row.col.f32.f16.f16.f32 "
                 "{%0,%1,%2,%3}, {%4,%5,%6,%7}, {%8,%9}, {%0,%1,%2,%3};"
                 : "+f"(c[0]), "+f"(c[1]), "+f"(c[2]), "+f"(c[3])
                 : "r"(a[0]), "r"(a[1]), "r"(a[2]), "r"(a[3]), "r"(b[0]), "r"(b[1]));
}
__device__ __forceinline__ uint32_t smem_u32(const void* p) {
    return (uint32_t)__cvta_generic_to_shared(p);
}
__device__ __forceinline__ uint32_t packh2(float a, float b) {
    __half2 h = __floats2half2_rn(a, b);
    return *(uint32_t*)&h;
}
__device__ __forceinline__ float ex2(float x) {
    float y;
    asm("ex2.approx.ftz.f32 %0, %1;" : "=f"(y) : "f"(x));
    return y;
}
#define CP16(dst, src) asm volatile("cp.async.cg.shared.global [%0], [%1], 16;" :: "r"(dst), "l"(src) : "memory")
#define CP_COMMIT() asm volatile("cp.async.commit_group;" ::: "memory")
#define CP_WAIT1() asm volatile("cp.async.wait_group 1;" ::: "memory")
#define CP_WAIT0() asm volatile("cp.async.wait_group 0;" ::: "memory")

// ---------------- one-shot convert: f16 casts + w2 hi/lo + mask float ----------------
// unit = 16 bytes of source
__global__ void convert_all(const float* __restrict__ qw, const float* __restrict__ kw,
                            const float* __restrict__ vw, const float* __restrict__ ow,
                            const float* __restrict__ kvst, const float* __restrict__ hidden,
                            const float* __restrict__ m1w2, const float* __restrict__ m2w2,
                            const int* __restrict__ amask)
{
    unsigned u = blockIdx.x * 256 + threadIdx.x;
    if (u < 705024u) {
        const float* src; __half* dst; unsigned off;
        if      (u <  16384) { src = qw;     dst = d_Wh;          off = u; }
        else if (u <  32768) { src = kw;     dst = d_Wh + 65536;  off = u - 16384; }
        else if (u <  49152) { src = vw;     dst = d_Wh + 131072; off = u - 32768; }
        else if (u <  65536) { src = ow;     dst = d_Wh + 196608; off = u - 49152; }
        else if (u < 589824) { src = kvst;   dst = d_Akv;         off = u - 65536; }
        else                 { src = hidden; dst = d_Aq;          off = u - 589824; }
        float4 f = ((const float4*)src)[off];
        uint2 o; o.x = packh2(f.x, f.y); o.y = packh2(f.z, f.w);
        ((uint2*)dst)[off] = o;
    } else if (u < 707072u) {
        unsigned off = u - 705024u;         // 0..2047 ; 1024 per axis
        int axis = off >> 10;
        unsigned o2 = off & 1023;
        const float* src = axis ? m2w2 : m1w2;
        float4 f = ((const float4*)src)[o2];
        __half hx = __float2half_rn(f.x), hy = __float2half_rn(f.y);
        __half hz = __float2half_rn(f.z), hw = __float2half_rn(f.w);
        uint2 hiu, lou;
        {
            __half2 a; a.x = hx; a.y = hy; hiu.x = *(uint32_t*)&a;
            __half2 b; b.x = hz; b.y = hw; hiu.y = *(uint32_t*)&b;
        }
        lou.x = packh2(f.x - __half2float(hx), f.y - __half2float(hy));
        lou.y = packh2(f.z - __half2float(hz), f.w - __half2float(hw));
        ((uint2*)(d_w2hi + axis * 4096))[o2] = hiu;
        ((uint2*)(d_w2lo + axis * 4096))[o2] = lou;
    } else {
        unsigned off = u - 707072u;         // 0..2047 int4 units
        int4 m = ((const int4*)amask)[off];
        float4 f = make_float4(-100.0f * L2E * m.x, -100.0f * L2E * m.y,
                               -100.0f * L2E * m.z, -100.0f * L2E * m.w);
        ((float4*)d_mskf)[off] = f;
    }
}

// ---------------- HMMA GEMM 128x64 tile, optional dual weights ----------------
__global__ void __launch_bounds__(256) gemm_dual(
    const __half* __restrict__ Ah,
    const __half* __restrict__ W1, const float* __restrict__ b1v, void* __restrict__ C1,
    const __half* __restrict__ W2, const float* __restrict__ b2v, void* __restrict__ C2,
    int M, int rpb, float scale, int mode)
{
    __shared__ __half As[128 * 40];
    __shared__ __half Ws1[64 * 40];
    __shared__ __half Ws2[64 * 40];

    const int tid = threadIdx.x;
    const int lane = tid & 31;
    const int wid = tid >> 5;
    const int bm = blockIdx.x * 128;
    const int bn = blockIdx.y * 64;
    const bool dual = (W2 != nullptr);

    const int arow = tid >> 1, aseg = (tid & 1) * 16;
    const int wrow = tid >> 2, wseg = (tid & 3) * 8;

    float c1[8][4], c2[8][4];
#pragma unroll
    for (int j = 0; j < 8; j++) {
        c1[j][0] = c1[j][1] = c1[j][2] = c1[j][3] = 0.f;
        c2[j][0] = c2[j][1] = c2[j][2] = c2[j][3] = 0.f;
    }

    const uint32_t AsB = smem_u32(As);
    const uint32_t W1B = smem_u32(Ws1);
    const uint32_t W2B = smem_u32(Ws2);

    uint4 pa0 = make_uint4(0,0,0,0), pa1 = pa0, pw1, pw2 = make_uint4(0,0,0,0);
    if (bm + arow < M) {
        const uint4* ap = (const uint4*)&Ah[(size_t)(bm + arow) * 256 + aseg];
        pa0 = ap[0]; pa1 = ap[1];
    }
    pw1 = *(const uint4*)&W1[(size_t)(bn + wrow) * 256 + wseg];
    if (dual) pw2 = *(const uint4*)&W2[(size_t)(bn + wrow) * 256 + wseg];

#pragma unroll 1
    for (int kit = 0; kit < 8; kit++) {
        *(uint4*)&As[arow * 40 + aseg]     = pa0;
        *(uint4*)&As[arow * 40 + aseg + 8] = pa1;
        *(uint4*)&Ws1[wrow * 40 + wseg]    = pw1;
        if (dual) *(uint4*)&Ws2[wrow * 40 + wseg] = pw2;
        __syncthreads();

        if (kit < 7) {
            int k0 = (kit + 1) * 32;
            pa0 = make_uint4(0,0,0,0); pa1 = pa0;
            if (bm + arow < M) {
                const uint4* ap = (const uint4*)&Ah[(size_t)(bm + arow) * 256 + k0 + aseg];
                pa0 = ap[0]; pa1 = ap[1];
            }
            pw1 = *(const uint4*)&W1[(size_t)(bn + wrow) * 256 + k0 + wseg];
            if (dual) pw2 = *(const uint4*)&W2[(size_t)(bn + wrow) * 256 + k0 + wseg];
        }

        uint32_t a0[4], a1[4];
        uint32_t aa = AsB + (uint32_t)((wid * 16 + (lane & 15)) * 40 + ((lane >> 4) * 8)) * 2;
        ldmx4(a0, aa);
        ldmx4(a1, aa + 32);
#pragma unroll
        for (int j = 0; j < 8; j++) {
            uint32_t woff = (uint32_t)((j * 8 + (lane & 7)) * 40 + ((lane >> 3) & 1) * 8) * 2;
            uint32_t b0[2], b1[2];
            ldmx2(b0, W1B + woff);
            ldmx2(b1, W1B + woff + 32);
            mma16816(c1[j], a0, b0);
            mma16816(c1[j], a1, b1);
            if (dual) {
                ldmx2(b0, W2B + woff);
                ldmx2(b1, W2B + woff + 32);
                mma16816(c2[j], a0, b0);
                mma16816(c2[j], a1, b1);
            }
        }
        __syncthreads();
    }

    const int r0 = bm + wid * 16 + (lane >> 2);
    const int cb = 2 * (lane & 3);
    if (mode == 0) {
        float* C = (float*)C1;
#pragma unroll
        for (int j = 0; j < 8; j++) {
            int col = bn + j * 8 + cb;
            float bb0 = b1v[col], bb1 = b1v[col + 1];
            if (r0 < M)     *(float2*)&C[(size_t)r0 * 256 + col]       = make_float2((c1[j][0] + bb0) * scale, (c1[j][1] + bb1) * scale);
            if (r0 + 8 < M) *(float2*)&C[(size_t)(r0 + 8) * 256 + col] = make_float2((c1[j][2] + bb0) * scale, (c1[j][3] + bb1) * scale);
        }
    } else {
        __half* Ca = (__half*)C1;
        __half* Cb = (__half*)C2;
        int ba = r0 / rpb, ra = r0 - ba * rpb;
        int bb = (r0 + 8) / rpb, rb = (r0 + 8) - bb * rpb;
#pragma unroll
        for (int j = 0; j < 8; j++) {
            int col = bn + j * 8 + cb;
            int head = col >> 5, d = col & 31;
            float x0 = b1v[col], x1 = b1v[col + 1];
            if (r0 < M) {
                *(uint32_t*)&Ca[((size_t)((ba * NH + head) * rpb + ra)) * HD + d] =
                    packh2((c1[j][0] + x0) * scale, (c1[j][1] + x1) * scale);
            }
            if (r0 + 8 < M) {
                *(uint32_t*)&Ca[((size_t)((bb * NH + head) * rpb + rb)) * HD + d] =
                    packh2((c1[j][2] + x0) * scale, (c1[j][3] + x1) * scale);
            }
            if (dual) {
                float y0 = b2v[col], y1 = b2v[col + 1];
                if (r0 < M) {
                    *(uint32_t*)&Cb[((size_t)((ba * NH + head) * rpb + ra)) * HD + d] =
                        packh2((c2[j][0] + y0) * scale, (c2[j][1] + y1) * scale);
                }
                if (r0 + 8 < M) {
                    *(uint32_t*)&Cb[((size_t)((bb * NH + head) * rpb + rb)) * HD + d] =
                        packh2((c2[j][2] + y0) * scale, (c2[j][3] + y1) * scale);
                }
            }
        }
    }
}

// ---------------- RPE v3: 4 queries/block, precomputed w2 hi/lo, log2e output ----------
#define MKFRAG(px, hi0, lo0, hi1, lo1) { \
    float h0 = fmaxf(v0.x - v0.y * (px), 0.f); \
    float h1 = fmaxf(v0.z - v0.w * (px), 0.f); \
    float h2 = fmaxf(v1.x - v1.y * (px), 0.f); \
    float h3 = fmaxf(v1.z - v1.w * (px), 0.f); \
    __half2 t0 = __floats2half2_rn(h0, h1); float2 g0 = __half22float2(t0); \
    __half2 u0 = __floats2half2_rn(h0 - g0.x, h1 - g0.y); \
    __half2 t1 = __floats2half2_rn(h2, h3); float2 g1 = __half22float2(t1); \
    __half2 u1 = __floats2half2_rn(h2 - g1.x, h3 - g1.y); \
    hi0 = *(uint32_t*)&t0; lo0 = *(uint32_t*)&u0; \
    hi1 = *(uint32_t*)&t1; lo1 = *(uint32_t*)&u1; }

__global__ void __launch_bounds__(256) rpe_tc3(
    const float* __restrict__ refpts,
    const float* __restrict__ w1a, const float* __restrict__ b1a,
    const float* __restrict__ w1b, const float* __restrict__ b1b,
    float* __restrict__ outx, float* __restrict__ outy)
{
    __shared__ __half w2hi[8 * 520];
    __shared__ __half w2lo[8 * 520];
    __shared__ float2 as2[4][512];

    const int tid = threadIdx.x;
    const int lane = tid & 31;
    const int wid = tid >> 5;
    const int q0 = blockIdx.x * 4;
    const int b = blockIdx.y;
    const int axis = blockIdx.z;

    const float* w1  = axis ? w1b : w1a;
    const float* bb1 = axis ? b1b : b1a;
    float* out = axis ? outy : outx;

    const __half* ghi = d_w2hi + axis * 4096;
    const __half* glo = d_w2lo + axis * 4096;
#pragma unroll
    for (int i = tid; i < 2048; i += 256) {
        int h = i >> 8, jj = (i & 255) * 2;
        *(uint32_t*)&w2hi[h * 520 + jj] = *(const uint32_t*)&ghi[h * 512 + jj];
        *(uint32_t*)&w2lo[h * 520 + jj] = *(const uint32_t*)&glo[h * 512 + jj];
    }
#pragma unroll
    for (int i = tid; i < 4 * 512; i += 256) {
        int qi = i >> 9, j = i & 511;
        const float* rp = refpts + ((size_t)b * QLEN + q0 + qi) * 4;
        float cc = rp[axis], ss = rp[2 + axis];
        float lo = (cc - 0.5f * ss) * 1024.f, hi = (cc + 0.5f * ss) * 1024.f;
        float wx = w1[j * 2], wy = w1[j * 2 + 1];
        as2[qi][j] = make_float2(wx * lo + wy * hi + bb1[j], wx + wy);
    }
    __syncthreads();

    const int qi = wid >> 1;
    const int mt = wid & 1;
    const int q = q0 + qi;
    const int r = lane >> 2;
    const int c0 = 2 * (lane & 3);
    const float pxA = (mt * 16 + r + 0.5f) * 16.f;
    const float pxB = pxA + 128.f;
    const float pxC = pxA + 512.f;
    const float pxD = pxA + 640.f;

    const uint32_t WhiB = smem_u32(w2hi);
    const uint32_t WloB = smem_u32(w2lo);
    const float2* asq = as2[qi];

    float cA[4] = {0.f, 0.f, 0.f, 0.f};
    float cB[4] = {0.f, 0.f, 0.f, 0.f};

#pragma unroll 4
    for (int kk = 0; kk < 32; kk++) {
        int j0 = kk * 16 + c0;
        float4 v0 = *(const float4*)&asq[j0];
        float4 v1 = *(const float4*)&asq[j0 + 8];

        uint32_t ahiA[4], aloA[4], ahiB[4], aloB[4];
        MKFRAG(pxA, ahiA[0], aloA[0], ahiA[2], aloA[2]);
        MKFRAG(pxB, ahiA[1], aloA[1], ahiA[3], aloA[3]);
        MKFRAG(pxC, ahiB[0], aloB[0], ahiB[2], aloB[2]);
        MKFRAG(pxD, ahiB[1], aloB[1], ahiB[3], aloB[3]);

        uint32_t woff = (uint32_t)((lane & 7) * 520 + kk * 16 + ((lane >> 3) & 1) * 8) * 2;
        uint32_t bhi[2], blo[2];
        ldmx2(bhi, WhiB + woff);
        ldmx2(blo, WloB + woff);
        mma16816(cA, ahiA, bhi);
        mma16816(cA, aloA, bhi);
        mma16816(cA, ahiA, blo);
        mma16816(cB, ahiB, bhi);
        mma16816(cB, aloB, bhi);
        mma16816(cB, ahiB, blo);
    }

    {
        int p0 = mt * 16 + r;
        size_t hstride = (size_t)QLEN * GRD;
        size_t base = ((size_t)(b * NH + c0) * QLEN + q) * GRD;
        out[base + p0]               = cA[0] * L2E;
        out[base + hstride + p0]     = cA[1] * L2E;
        out[base + p0 + 8]           = cA[2] * L2E;
        out[base + hstride + p0 + 8] = cA[3] * L2E;
        out[base + p0 + 32]               = cB[0] * L2E;
        out[base + hstride + p0 + 32]     = cB[1] * L2E;
        out[base + p0 + 40]               = cB[2] * L2E;
        out[base + hstride + p0 + 40]     = cB[3] * L2E;
    }
}

// ---------------- HMMA flash attention (log2-domain, cp.async double-buffered) -------
#define PK 40
#define PR 68
#define QS_OFF  0
#define KS_OFF  5120
#define VS_OFF  15360
#define RX_OFF  25600
#define RY_OFF  43008
#define MK_OFF  60416
#define ATTN_SMEM 76800

__global__ void __launch_bounds__(128) attn_mma()
{
    extern __shared__ char smem[];
    __half* Qs  = (__half*)(smem + QS_OFF);
    float*  rxs = (float*)(smem + RX_OFF);
    float*  rys = (float*)(smem + RY_OFF);
    float*  mks = (float*)(smem + MK_OFF);

    const int tid = threadIdx.x;
    const int lane = tid & 31;
    const int wid = tid >> 5;
    const int bh = blockIdx.y;
    const int b = bh >> 3;
    const int head = bh & 7;
    const int q0 = blockIdx.x * 64;

    const __half* Kb = d_Kh + (size_t)bh * KVLEN * HD;
    const __half* Vb = d_Vh + (size_t)bh * KVLEN * HD;

    const int srow = tid >> 1, sseg = (tid & 1) * 16;
    {
        uint32_t kd = smem_u32(smem + KS_OFF) + (uint32_t)(srow * PK + sseg) * 2;
        uint32_t vd = smem_u32(smem + VS_OFF) + (uint32_t)(srow * PK + sseg) * 2;
        const __half* ks = Kb + (size_t)srow * HD + sseg;
        const __half* vs = Vb + (size_t)srow * HD + sseg;
        CP16(kd, ks); CP16(kd + 16, ks + 8);
        CP16(vd, vs); CP16(vd + 16, vs + 8);
        CP_COMMIT();
    }

    // mask (pre-scaled floats)
    {
        const float4* mg = (const float4*)(d_mskf + b * KVLEN);
#pragma unroll
        for (int i = tid; i < KVLEN / 4; i += 128) ((float4*)mks)[i] = mg[i];
    }

    {
        int row = tid >> 1, seg = tid & 1;
        int q = q0 + row;
        uint4 v0 = make_uint4(0, 0, 0, 0), v1 = make_uint4(0, 0, 0, 0);
        if (q < QLEN) {
            const uint4* qp = (const uint4*)(d_Qh + ((size_t)bh * QLEN + q) * HD + seg * 16);
            v0 = qp[0]; v1 = qp[1];
        }
        *(uint4*)(Qs + row * PK + seg * 16)     = v0;
        *(uint4*)(Qs + row * PK + seg * 16 + 8) = v1;
    }
    {
        int row = tid >> 1, sb = (tid & 1) * 32;
        int q = q0 + row;
        if (q < QLEN) {
            const float4* px = (const float4*)(d_rpex + ((size_t)bh * QLEN + q) * GRD + sb);
            const float4* py = (const float4*)(d_rpey + ((size_t)bh * QLEN + q) * GRD + sb);
#pragma unroll
            for (int u = 0; u < 8; u++) {
                *(float4*)(rxs + row * PR + sb + u * 4) = px[u];
                *(float4*)(rys + row * PR + sb + u * 4) = py[u];
            }
        } else {
            float4 z = make_float4(0.f, 0.f, 0.f, 0.f);
#pragma unroll
            for (int u = 0; u < 8; u++) {
                *(float4*)(rxs + row * PR + sb + u * 4) = z;
                *(float4*)(rys + row * PR + sb + u * 4) = z;
            }
        }
    }
    __syncthreads();

    uint32_t aQ[2][4];
    {
        uint32_t base = smem_u32(Qs);
        int m = wid * 16 + (lane & 15);
        uint32_t a0 = base + (uint32_t)(m * PK + ((lane >> 4) * 8)) * 2;
        ldmx4(aQ[0], a0);
        ldmx4(aQ[1], a0 + 32);
    }

    float oc[4][4];
#pragma unroll
    for (int i = 0; i < 4; i++)
#pragma unroll
        for (int j = 0; j < 4; j++) oc[i][j] = 0.f;
    float m_run0 = -1e30f, m_run1 = -1e30f, l_run0 = 0.f, l_run1 = 0.f;

    const int r0 = wid * 16 + (lane >> 2);
    const int cb = 2 * (lane & 3);

    for (int t = 0; t < 64; t++) {
        if (t + 1 < 64) {
            int buf = (t + 1) & 1;
            uint32_t kd = smem_u32(smem + KS_OFF + buf * 5120) + (uint32_t)(srow * PK + sseg) * 2;
            uint32_t vd = smem_u32(smem + VS_OFF + buf * 5120) + (uint32_t)(srow * PK + sseg) * 2;
            const __half* ks = Kb + (size_t)((t + 1) * 64 + srow) * HD + sseg;
            const __half* vs = Vb + (size_t)((t + 1) * 64 + srow) * HD + sseg;
            CP16(kd, ks); CP16(kd + 16, ks + 8);
            CP16(vd, vs); CP16(vd + 16, vs + 8);
            CP_COMMIT();
            CP_WAIT1();
        } else {
            CP_WAIT0();
        }
        __syncthreads();

        const uint32_t KsB = smem_u32(smem + KS_OFF + (t & 1) * 5120);
        const uint32_t VsB = smem_u32(smem + VS_OFF + (t & 1) * 5120);

        float sc[8][4];
#pragma unroll
        for (int j = 0; j < 8; j++) {
            sc[j][0] = sc[j][1] = sc[j][2] = sc[j][3] = 0.f;
            uint32_t addr = KsB + (uint32_t)((j * 8 + (lane & 7)) * PK + ((lane >> 3) & 1) * 8) * 2;
            uint32_t bk0[2], bk1[2];
            ldmx2(bk0, addr);
            ldmx2(bk1, addr + 32);
            mma16816(sc[j], aQ[0], bk0);
            mma16816(sc[j], aQ[1], bk1);
        }

        float ry0 = rys[r0 * PR + t];
        float ry1 = rys[(r0 + 8) * PR + t];
        float mx0 = -1e30f, mx1 = -1e30f;
#pragma unroll
        for (int j = 0; j < 8; j++) {
            int n = j * 8 + cb;
            float2 rxa = *(float2*)(rxs + r0 * PR + n);
            float2 rxb = *(float2*)(rxs + (r0 + 8) * PR + n);
            float2 mk  = *(float2*)(mks + t * 64 + n);
            sc[j][0] += rxa.x + ry0 + mk.x;
            sc[j][1] += rxa.y + ry0 + mk.y;
            sc[j][2] += rxb.x + ry1 + mk.x;
            sc[j][3] += rxb.y + ry1 + mk.y;
            mx0 = fmaxf(mx0, fmaxf(sc[j][0], sc[j][1]));
            mx1 = fmaxf(mx1, fmaxf(sc[j][2], sc[j][3]));
        }
        mx0 = fmaxf(mx0, __shfl_xor_sync(0xffffffffu, mx0, 1));
        mx0 = fmaxf(mx0, __shfl_xor_sync(0xffffffffu, mx0, 2));
        mx1 = fmaxf(mx1, __shfl_xor_sync(0xffffffffu, mx1, 1));
        mx1 = fmaxf(mx1, __shfl_xor_sync(0xffffffffu, mx1, 2));

        float mn0 = fmaxf(m_run0, mx0), mn1 = fmaxf(m_run1, mx1);
        float f0 = ex2(m_run0 - mn0), f1 = ex2(m_run1 - mn1);
        m_run0 = mn0; m_run1 = mn1;

        float la0 = 0.f, la1 = 0.f;
        uint32_t pa[4][4];
#pragma unroll
        for (int j = 0; j < 8; j++) {
            float p0 = ex2(sc[j][0] - mn0);
            float p1 = ex2(sc[j][1] - mn0);
            float p2 = ex2(sc[j][2] - mn1);
            float p3 = ex2(sc[j][3] - mn1);
            la0 += p0 + p1; la1 += p2 + p3;
            int kt = j >> 1, hi = j & 1;
            pa[kt][2 * hi]     = packh2(p0, p1);
            pa[kt][2 * hi + 1] = packh2(p2, p3);
        }
        la0 += __shfl_xor_sync(0xffffffffu, la0, 1);
        la0 += __shfl_xor_sync(0xffffffffu, la0, 2);
        la1 += __shfl_xor_sync(0xffffffffu, la1, 1);
        la1 += __shfl_xor_sync(0xffffffffu, la1, 2);
        l_run0 = l_run0 * f0 + la0;
        l_run1 = l_run1 * f1 + la1;

#pragma unroll
        for (int no = 0; no < 4; no++) {
            oc[no][0] *= f0; oc[no][1] *= f0;
            oc[no][2] *= f1; oc[no][3] *= f1;
        }

#pragma unroll
        for (int kt = 0; kt < 4; kt++) {
            uint32_t addr = VsB + (uint32_t)((kt * 16 + (lane & 15)) * PK) * 2;
#pragma unroll
            for (int no = 0; no < 4; no++) {
                uint32_t bv[2];
                ldmx2t(bv, addr + (uint32_t)(no * 8) * 2);
                mma16816(oc[no], pa[kt], bv);
            }
        }
        __syncthreads();
    }

    {
        float inv0 = 1.0f / l_run0;
        float inv1 = 1.0f / l_run1;
        int qa = q0 + r0, qb = qa + 8;
#pragma unroll
        for (int no = 0; no < 4; no++) {
            int col = head * HD + no * 8 + cb;
            if (qa < QLEN) {
                *(uint32_t*)&d_ctxh[((size_t)b * QLEN + qa) * DIMV + col] =
                    packh2(oc[no][0] * inv0, oc[no][1] * inv0);
            }
            if (qb < QLEN) {
                *(uint32_t*)&d_ctxh[((size_t)b * QLEN + qb) * DIMV + col] =
                    packh2(oc[no][2] * inv1, oc[no][3] * inv1);
            }
        }
    }
}

// ---------------- launch ----------------
extern "C" void kernel_launch(void* const* d_in, const int* in_sizes, int n_in,
                              void* d_out, int out_size)
{
    const float* hidden = (const float*)d_in[0];
    const float* refpts = (const float*)d_in[1];
    const float* kvst   = (const float*)d_in[2];
    const int*   amask  = (const int*)d_in[4];
    const float* m1w1 = (const float*)d_in[5];
    const float* m1b1 = (const float*)d_in[6];
    const float* m1w2 = (const float*)d_in[7];
    const float* m2w1 = (const float*)d_in[8];
    const float* m2b1 = (const float*)d_in[9];
    const float* m2w2 = (const float*)d_in[10];
    const float* qw = (const float*)d_in[11];
    const float* qb = (const float*)d_in[12];
    const float* kw = (const float*)d_in[13];
    const float* kb = (const float*)d_in[14];
    const float* vw = (const float*)d_in[15];
    const float* vb = (const float*)d_in[16];
    const float* ow = (const float*)d_in[17];
    const float* ob = (const float*)d_in[18];
    float* out = (float*)d_out;

    void *pQ, *pK, *pV, *pRX, *pRY, *pCTX, *pWh;
    cudaGetSymbolAddress(&pQ,   d_Qh);
    cudaGetSymbolAddress(&pK,   d_Kh);
    cudaGetSymbolAddress(&pV,   d_Vh);
    cudaGetSymbolAddress(&pRX,  d_rpex);
    cudaGetSymbolAddress(&pRY,  d_rpey);
    cudaGetSymbolAddress(&pCTX, d_ctxh);
    cudaGetSymbolAddress(&pWh,  d_Wh);
    void *pAkv, *pAq;
    cudaGetSymbolAddress(&pAkv, d_Akv);
    cudaGetSymbolAddress(&pAq,  d_Aq);

    cudaFuncSetAttribute(attn_mma, cudaFuncAttributeMaxDynamicSharedMemorySize, ATTN_SMEM);

    const float qs2 = 0.17677669529663687f * L2E;  // 1/sqrt(32) * log2(e)
    __half* Wh = (__half*)pWh;

    convert_all<<<2770, 256>>>(qw, kw, vw, ow, kvst, hidden, m1w2, m2w2, amask);
    gemm_dual<<<dim3(64, 4), 256>>>((const __half*)pAkv, Wh + 65536, kb, pK,
                                    Wh + 131072, vb, pV, B_ * KVLEN, KVLEN, 1.0f, 1);
    gemm_dual<<<dim3(15, 4), 256>>>((const __half*)pAq, Wh, qb, pQ,
                                    nullptr, nullptr, nullptr, B_ * QLEN, QLEN, qs2, 1);
    rpe_tc3<<<dim3(QLEN / 4, B_, 2), 256>>>(refpts, m1w1, m1b1, m2w1, m2b1,
                                            (float*)pRX, (float*)pRY);
    attn_mma<<<dim3((QLEN + 63) / 64, B_ * NH), 128, ATTN_SMEM>>>();
    gemm_dual<<<dim3(15, 4), 256>>>((const __half*)pCTX, Wh + 196608, ob, out,
                                    nullptr, nullptr, nullptr, B_ * QLEN, QLEN, 1.0f, 0);
}

// round 10
// speedup vs baseline: 2.5809x; 1.2072x over previous
#include <cuda_runtime.h>
#include <cuda_fp16.h>
#include <cstdint>

#define B_    2
#define QLEN  900
#define DIMV  256
#define NH    8
#define HD    32
#define KVLEN 4096
#define GRD   64
#define RPEH  512
#define L2E   1.4426950408889634f

// ---------------- scratch ----------------
__device__ __half d_Qh[B_*NH*QLEN*HD];     // (b,h,q,32) f16 pre-scaled (incl. log2e)
__device__ __half d_Kh[B_*NH*KVLEN*HD];    // (b,h,kv,32) f16
__device__ __half d_Vh[B_*NH*KVLEN*HD];    // (b,h,kv,32) f16
__device__ __half d_ctxh[B_*QLEN*DIMV];    // (b,q,256) f16
__device__ float  d_rpex[B_*NH*QLEN*GRD];  // log2e-scaled
__device__ float  d_rpey[B_*NH*QLEN*GRD];  // log2e-scaled
__device__ __half d_Wh[4*65536];           // qw,kw,vw,ow f16
__device__ __half d_Akv[B_*KVLEN*DIMV];    // kvst f16
__device__ __half d_Aq[B_*QLEN*DIMV];      // hidden f16
__device__ __half d_w2hi[2*8*512];         // w2 hi (axis, head, j)
__device__ __half d_w2lo[2*8*512];         // w2 lo
__device__ float  d_mskf[B_*KVLEN];        // -100*log2e*mask

// ---------------- helpers ----------------
__device__ __forceinline__ void ldmx4(uint32_t* r, uint32_t a) {
    asm volatile("ldmatrix.sync.aligned.m8n8.x4.shared.b16 {%0,%1,%2,%3}, [%4];"
                 : "=r"(r[0]), "=r"(r[1]), "=r"(r[2]), "=r"(r[3]) : "r"(a));
}
__device__ __forceinline__ void ldmx2(uint32_t* r, uint32_t a) {
    asm volatile("ldmatrix.sync.aligned.m8n8.x2.shared.b16 {%0,%1}, [%2];"
                 : "=r"(r[0]), "=r"(r[1]) : "r"(a));
}
__device__ __forceinline__ void ldmx2t(uint32_t* r, uint32_t a) {
    asm volatile("ldmatrix.sync.aligned.m8n8.x2.trans.shared.b16 {%0,%1}, [%2];"
                 : "=r"(r[0]), "=r"(r[1]) : "r"(a));
}
__device__ __forceinline__ void mma16816(float* c, const uint32_t* a, const uint32_t* b) {
    asm volatile("mma.sync.aligned.m16n8k16.row.col.f32.f16.f16.f32 "
                 "{%0,%1,%2,%3}, {%4,%5,%6,%7}, {%8,%9}, {%0,%1,%2,%3};"
                 : "+f"(c[0]), "+f"(c[1]), "+f"(c[2]), "+f"(c[3])
                 : "r"(a[0]), "r"(a[1]), "r"(a[2]), "r"(a[3]), "r"(b[0]), "r"(b[1]));
}
__device__ __forceinline__ uint32_t smem_u32(const void* p) {
    return (uint32_t)__cvta_generic_to_shared(p);
}
__device__ __forceinline__ uint32_t packh2(float a, float b) {
    __half2 h = __floats2half2_rn(a, b);
    return *(uint32_t*)&h;
}
__device__ __forceinline__ float ex2(float x) {
    float y;
    asm("ex2.approx.ftz.f32 %0, %1;" : "=f"(y) : "f"(x));
    return y;
}
#define CP16(dst, src) asm volatile("cp.async.cg.shared.global [%0], [%1], 16;" :: "r"(dst), "l"(src) : "memory")
#define CP_COMMIT() asm volatile("cp.async.commit_group;" ::: "memory")
#define CP_WAIT1() asm volatile("cp.async.wait_group 1;" ::: "memory")
#define CP_WAIT0() asm volatile("cp.async.wait_group 0;" ::: "memory")

// ---------------- one-shot convert: f16 casts + w2 hi/lo + mask float ----------------
__global__ void convert_all(const float* __restrict__ qw, const float* __restrict__ kw,
                            const float* __restrict__ vw, const float* __restrict__ ow,
                            const float* __restrict__ kvst, const float* __restrict__ hidden,
                            const float* __restrict__ m1w2, const float* __restrict__ m2w2,
                            const int* __restrict__ amask)
{
    unsigned u = blockIdx.x * 256 + threadIdx.x;
    if (u < 705024u) {
        const float* src; __half* dst; unsigned off;
        if      (u <  16384) { src = qw;     dst = d_Wh;          off = u; }
        else if (u <  32768) { src = kw;     dst = d_Wh + 65536;  off = u - 16384; }
        else if (u <  49152) { src = vw;     dst = d_Wh + 131072; off = u - 32768; }
        else if (u <  65536) { src = ow;     dst = d_Wh + 196608; off = u - 49152; }
        else if (u < 589824) { src = kvst;   dst = d_Akv;         off = u - 65536; }
        else                 { src = hidden; dst = d_Aq;          off = u - 589824; }
        float4 f = ((const float4*)src)[off];
        uint2 o; o.x = packh2(f.x, f.y); o.y = packh2(f.z, f.w);
        ((uint2*)dst)[off] = o;
    } else if (u < 707072u) {
        unsigned off = u - 705024u;
        int axis = off >> 10;
        unsigned o2 = off & 1023;
        const float* src = axis ? m2w2 : m1w2;
        float4 f = ((const float4*)src)[o2];
        __half hx = __float2half_rn(f.x), hy = __float2half_rn(f.y);
        __half hz = __float2half_rn(f.z), hw = __float2half_rn(f.w);
        uint2 hiu, lou;
        {
            __half2 a; a.x = hx; a.y = hy; hiu.x = *(uint32_t*)&a;
            __half2 b; b.x = hz; b.y = hw; hiu.y = *(uint32_t*)&b;
        }
        lou.x = packh2(f.x - __half2float(hx), f.y - __half2float(hy));
        lou.y = packh2(f.z - __half2float(hz), f.w - __half2float(hw));
        ((uint2*)(d_w2hi + axis * 4096))[o2] = hiu;
        ((uint2*)(d_w2lo + axis * 4096))[o2] = lou;
    } else {
        unsigned off = u - 707072u;
        int4 m = ((const int4*)amask)[off];
        float4 f = make_float4(-100.0f * L2E * m.x, -100.0f * L2E * m.y,
                               -100.0f * L2E * m.z, -100.0f * L2E * m.w);
        ((float4*)d_mskf)[off] = f;
    }
}

// ---------------- HMMA GEMM core: 128x32 tile, optional dual weights ----------------
// smem: As 10240B | Ws1 2560B | Ws2 2560B   (15360 total)
__device__ __forceinline__ void gemm_core(char* smem, int bm, int bn,
    const __half* __restrict__ Ah,
    const __half* __restrict__ W1, const float* __restrict__ b1v, void* C1,
    const __half* __restrict__ W2, const float* __restrict__ b2v, void* C2,
    int M, int rpb, float scale, int mode)
{
    __half* As  = (__half*)smem;
    __half* Ws1 = (__half*)(smem + 10240);
    __half* Ws2 = (__half*)(smem + 12800);

    const int tid = threadIdx.x;
    const int lane = tid & 31;
    const int wid = tid >> 5;
    const bool dual = (W2 != nullptr);

    const int arow = tid >> 1, aseg = (tid & 1) * 16;
    const int wrow = tid >> 3, wseg = (tid & 7) * 4;

    float c1[4][4], c2[4][4];
#pragma unroll
    for (int j = 0; j < 4; j++) {
        c1[j][0] = c1[j][1] = c1[j][2] = c1[j][3] = 0.f;
        c2[j][0] = c2[j][1] = c2[j][2] = c2[j][3] = 0.f;
    }

    const uint32_t AsB = smem_u32(As);
    const uint32_t W1B = smem_u32(Ws1);
    const uint32_t W2B = smem_u32(Ws2);

    uint4 pa0 = make_uint4(0,0,0,0), pa1 = pa0;
    uint2 pw1, pw2 = make_uint2(0,0);
    if (bm + arow < M) {
        const uint4* ap = (const uint4*)&Ah[(size_t)(bm + arow) * 256 + aseg];
        pa0 = ap[0]; pa1 = ap[1];
    }
    pw1 = *(const uint2*)&W1[(size_t)(bn + wrow) * 256 + wseg];
    if (dual) pw2 = *(const uint2*)&W2[(size_t)(bn + wrow) * 256 + wseg];

#pragma unroll 1
    for (int kit = 0; kit < 8; kit++) {
        *(uint4*)&As[arow * 40 + aseg]     = pa0;
        *(uint4*)&As[arow * 40 + aseg + 8] = pa1;
        *(uint2*)&Ws1[wrow * 40 + wseg]    = pw1;
        if (dual) *(uint2*)&Ws2[wrow * 40 + wseg] = pw2;
        __syncthreads();

        if (kit < 7) {
            int k0 = (kit + 1) * 32;
            pa0 = make_uint4(0,0,0,0); pa1 = pa0;
            if (bm + arow < M) {
                const uint4* ap = (const uint4*)&Ah[(size_t)(bm + arow) * 256 + k0 + aseg];
                pa0 = ap[0]; pa1 = ap[1];
            }
            pw1 = *(const uint2*)&W1[(size_t)(bn + wrow) * 256 + k0 + wseg];
            if (dual) pw2 = *(const uint2*)&W2[(size_t)(bn + wrow) * 256 + k0 + wseg];
        }

        uint32_t a0[4], a1[4];
        uint32_t aa = AsB + (uint32_t)((wid * 16 + (lane & 15)) * 40 + ((lane >> 4) * 8)) * 2;
        ldmx4(a0, aa);
        ldmx4(a1, aa + 32);
#pragma unroll
        for (int j = 0; j < 4; j++) {
            uint32_t woff = (uint32_t)((j * 8 + (lane & 7)) * 40 + ((lane >> 3) & 1) * 8) * 2;
            uint32_t b0[2], b1[2];
            ldmx2(b0, W1B + woff);
            ldmx2(b1, W1B + woff + 32);
            mma16816(c1[j], a0, b0);
            mma16816(c1[j], a1, b1);
            if (dual) {
                ldmx2(b0, W2B + woff);
                ldmx2(b1, W2B + woff + 32);
                mma16816(c2[j], a0, b0);
                mma16816(c2[j], a1, b1);
            }
        }
        __syncthreads();
    }

    const int r0 = bm + wid * 16 + (lane >> 2);
    const int cb = 2 * (lane & 3);
    if (mode == 0) {
        float* C = (float*)C1;
#pragma unroll
        for (int j = 0; j < 4; j++) {
            int col = bn + j * 8 + cb;
            float bb0 = b1v[col], bb1 = b1v[col + 1];
            if (r0 < M)     *(float2*)&C[(size_t)r0 * 256 + col]       = make_float2((c1[j][0] + bb0) * scale, (c1[j][1] + bb1) * scale);
            if (r0 + 8 < M) *(float2*)&C[(size_t)(r0 + 8) * 256 + col] = make_float2((c1[j][2] + bb0) * scale, (c1[j][3] + bb1) * scale);
        }
    } else {
        __half* Ca = (__half*)C1;
        __half* Cb = (__half*)C2;
        int ba = r0 / rpb, ra = r0 - ba * rpb;
        int bb = (r0 + 8) / rpb, rb = (r0 + 8) - bb * rpb;
#pragma unroll
        for (int j = 0; j < 4; j++) {
            int col = bn + j * 8 + cb;
            int head = col >> 5, d = col & 31;
            float x0 = b1v[col], x1 = b1v[col + 1];
            if (r0 < M) {
                *(uint32_t*)&Ca[((size_t)((ba * NH + head) * rpb + ra)) * HD + d] =
                    packh2((c1[j][0] + x0) * scale, (c1[j][1] + x1) * scale);
            }
            if (r0 + 8 < M) {
                *(uint32_t*)&Ca[((size_t)((bb * NH + head) * rpb + rb)) * HD + d] =
                    packh2((c1[j][2] + x0) * scale, (c1[j][3] + x1) * scale);
            }
            if (dual) {
                float y0 = b2v[col], y1 = b2v[col + 1];
                if (r0 < M) {
                    *(uint32_t*)&Cb[((size_t)((ba * NH + head) * rpb + ra)) * HD + d] =
                        packh2((c2[j][0] + y0) * scale, (c2[j][1] + y1) * scale);
                }
                if (r0 + 8 < M) {
                    *(uint32_t*)&Cb[((size_t)((bb * NH + head) * rpb + rb)) * HD + d] =
                        packh2((c2[j][2] + y0) * scale, (c2[j][3] + y1) * scale);
                }
            }
        }
    }
}

// ---------------- RPE core: 4 queries/block, hi/lo 3-MMA, log2e output ----------------
// smem: w2hi 8320B | w2lo 8320B | as2 16384B  (33024 total)
#define MKFRAG(px, hi0, lo0, hi1, lo1) { \
    float h0 = fmaxf(v0.x - v0.y * (px), 0.f); \
    float h1 = fmaxf(v0.z - v0.w * (px), 0.f); \
    float h2 = fmaxf(v1.x - v1.y * (px), 0.f); \
    float h3 = fmaxf(v1.z - v1.w * (px), 0.f); \
    __half2 t0 = __floats2half2_rn(h0, h1); float2 g0 = __half22float2(t0); \
    __half2 u0 = __floats2half2_rn(h0 - g0.x, h1 - g0.y); \
    __half2 t1 = __floats2half2_rn(h2, h3); float2 g1 = __half22float2(t1); \
    __half2 u1 = __floats2half2_rn(h2 - g1.x, h3 - g1.y); \
    hi0 = *(uint32_t*)&t0; lo0 = *(uint32_t*)&u0; \
    hi1 = *(uint32_t*)&t1; lo1 = *(uint32_t*)&u1; }

__device__ __forceinline__ void rpe_core(char* smem, int q0, int b, int axis,
    const float* __restrict__ refpts,
    const float* __restrict__ w1a, const float* __restrict__ b1a,
    const float* __restrict__ w1b, const float* __restrict__ b1b)
{
    __half* w2hi = (__half*)smem;
    __half* w2lo = (__half*)(smem + 8320);
    float2* as2  = (float2*)(smem + 16640);

    const int tid = threadIdx.x;
    const int lane = tid & 31;
    const int wid = tid >> 5;

    const float* w1  = axis ? w1b : w1a;
    const float* bb1 = axis ? b1b : b1a;
    float* out = axis ? d_rpey : d_rpex;

    const __half* ghi = d_w2hi + axis * 4096;
    const __half* glo = d_w2lo + axis * 4096;
#pragma unroll
    for (int i = tid; i < 2048; i += 256) {
        int h = i >> 8, jj = (i & 255) * 2;
        *(uint32_t*)&w2hi[h * 520 + jj] = *(const uint32_t*)&ghi[h * 512 + jj];
        *(uint32_t*)&w2lo[h * 520 + jj] = *(const uint32_t*)&glo[h * 512 + jj];
    }
#pragma unroll
    for (int i = tid; i < 4 * 512; i += 256) {
        int qi = i >> 9, j = i & 511;
        const float* rp = refpts + ((size_t)b * QLEN + q0 + qi) * 4;
        float cc = rp[axis], ss = rp[2 + axis];
        float lo = (cc - 0.5f * ss) * 1024.f, hi = (cc + 0.5f * ss) * 1024.f;
        float wx = w1[j * 2], wy = w1[j * 2 + 1];
        as2[qi * 512 + j] = make_float2(wx * lo + wy * hi + bb1[j], wx + wy);
    }
    __syncthreads();

    const int qi = wid >> 1;
    const int mt = wid & 1;
    const int q = q0 + qi;
    const int r = lane >> 2;
    const int c0 = 2 * (lane & 3);
    const float pxA = (mt * 16 + r + 0.5f) * 16.f;
    const float pxB = pxA + 128.f;
    const float pxC = pxA + 512.f;
    const float pxD = pxA + 640.f;

    const uint32_t WhiB = smem_u32(w2hi);
    const uint32_t WloB = smem_u32(w2lo);
    const float2* asq = as2 + qi * 512;

    float cA[4] = {0.f, 0.f, 0.f, 0.f};
    float cB[4] = {0.f, 0.f, 0.f, 0.f};

#pragma unroll 4
    for (int kk = 0; kk < 32; kk++) {
        int j0 = kk * 16 + c0;
        float4 v0 = *(const float4*)&asq[j0];
        float4 v1 = *(const float4*)&asq[j0 + 8];

        uint32_t ahiA[4], aloA[4], ahiB[4], aloB[4];
        MKFRAG(pxA, ahiA[0], aloA[0], ahiA[2], aloA[2]);
        MKFRAG(pxB, ahiA[1], aloA[1], ahiA[3], aloA[3]);
        MKFRAG(pxC, ahiB[0], aloB[0], ahiB[2], aloB[2]);
        MKFRAG(pxD, ahiB[1], aloB[1], ahiB[3], aloB[3]);

        uint32_t woff = (uint32_t)((lane & 7) * 520 + kk * 16 + ((lane >> 3) & 1) * 8) * 2;
        uint32_t bhi[2], blo[2];
        ldmx2(bhi, WhiB + woff);
        ldmx2(blo, WloB + woff);
        mma16816(cA, ahiA, bhi);
        mma16816(cA, aloA, bhi);
        mma16816(cA, ahiA, blo);
        mma16816(cB, ahiB, bhi);
        mma16816(cB, aloB, bhi);
        mma16816(cB, ahiB, blo);
    }

    {
        int p0 = mt * 16 + r;
        size_t hstride = (size_t)QLEN * GRD;
        size_t base = ((size_t)(b * NH + c0) * QLEN + q) * GRD;
        out[base + p0]               = cA[0] * L2E;
        out[base + hstride + p0]     = cA[1] * L2E;
        out[base + p0 + 8]           = cA[2] * L2E;
        out[base + hstride + p0 + 8] = cA[3] * L2E;
        out[base + p0 + 32]               = cB[0] * L2E;
        out[base + hstride + p0 + 32]     = cB[1] * L2E;
        out[base + p0 + 40]               = cB[2] * L2E;
        out[base + hstride + p0 + 40]     = cB[3] * L2E;
    }
}

// ---------------- fat mid-kernel: rpe + KV gemm + Q gemm in one launch ----------------
#define FAT_SMEM 33024
__global__ void __launch_bounds__(256, 4) fat_mid(
    const float* __restrict__ refpts,
    const float* __restrict__ w1a, const float* __restrict__ b1a,
    const float* __restrict__ w1b, const float* __restrict__ b1b,
    const float* __restrict__ qb, const float* __restrict__ kb,
    const float* __restrict__ vb, float qs2)
{
    extern __shared__ char smem[];
    int bx = blockIdx.x;
    if (bx < 900) {
        int axis = bx / 450;
        int rem = bx - axis * 450;
        int b = rem / 225;
        int q0 = (rem % 225) * 4;
        rpe_core(smem, q0, b, axis, refpts, w1a, b1a, w1b, b1b);
    } else if (bx < 1412) {
        int i = bx - 900;
        gemm_core(smem, (i & 63) * 128, (i >> 6) * 32,
                  d_Akv, d_Wh + 65536, kb, d_Kh, d_Wh + 131072, vb, d_Vh,
                  B_ * KVLEN, KVLEN, 1.0f, 1);
    } else {
        int i = bx - 1412;
        gemm_core(smem, (i % 15) * 128, (i / 15) * 32,
                  d_Aq, d_Wh, qb, d_Qh, nullptr, nullptr, nullptr,
                  B_ * QLEN, QLEN, qs2, 1);
    }
}

// ---------------- O projection ----------------
__global__ void __launch_bounds__(256) gemm_o(const float* __restrict__ ob, float* __restrict__ out)
{
    extern __shared__ char smem[];
    gemm_core(smem, blockIdx.x * 128, blockIdx.y * 32,
              d_ctxh, d_Wh + 196608, ob, out, nullptr, nullptr, nullptr,
              B_ * QLEN, QLEN, 1.0f, 0);
}

// ---------------- HMMA flash attention (log2-domain, rx in regs, ry-fold) -------------
#define PK 40
#define PR 68
#define QS_OFF  0
#define KS_OFF  5120
#define VS_OFF  15360
#define RY_OFF  25600
#define MK_OFF  43008
#define ATTN_SMEM 59392

__global__ void __launch_bounds__(128) attn_mma()
{
    extern __shared__ char smem[];
    __half* Qs  = (__half*)(smem + QS_OFF);
    float*  rys = (float*)(smem + RY_OFF);
    float*  mks = (float*)(smem + MK_OFF);

    const int tid = threadIdx.x;
    const int lane = tid & 31;
    const int wid = tid >> 5;
    const int bh = blockIdx.y;
    const int b = bh >> 3;
    const int head = bh & 7;
    const int q0 = blockIdx.x * 64;

    const __half* Kb = d_Kh + (size_t)bh * KVLEN * HD;
    const __half* Vb = d_Vh + (size_t)bh * KVLEN * HD;

    const int srow = tid >> 1, sseg = (tid & 1) * 16;
    {
        uint32_t kd = smem_u32(smem + KS_OFF) + (uint32_t)(srow * PK + sseg) * 2;
        uint32_t vd = smem_u32(smem + VS_OFF) + (uint32_t)(srow * PK + sseg) * 2;
        const __half* ks = Kb + (size_t)srow * HD + sseg;
        const __half* vs = Vb + (size_t)srow * HD + sseg;
        CP16(kd, ks); CP16(kd + 16, ks + 8);
        CP16(vd, vs); CP16(vd + 16, vs + 8);
        CP_COMMIT();
    }

    {
        const float4* mg = (const float4*)(d_mskf + b * KVLEN);
#pragma unroll
        for (int i = tid; i < KVLEN / 4; i += 128) ((float4*)mks)[i] = mg[i];
    }

    {
        int row = tid >> 1, seg = tid & 1;
        int q = q0 + row;
        uint4 v0 = make_uint4(0, 0, 0, 0), v1 = make_uint4(0, 0, 0, 0);
        if (q < QLEN) {
            const uint4* qp = (const uint4*)(d_Qh + ((size_t)bh * QLEN + q) * HD + seg * 16);
            v0 = qp[0]; v1 = qp[1];
        }
        *(uint4*)(Qs + row * PK + seg * 16)     = v0;
        *(uint4*)(Qs + row * PK + seg * 16 + 8) = v1;
    }
    {
        int row = tid >> 1, sb = (tid & 1) * 32;
        int q = q0 + row;
        if (q < QLEN) {
            const float4* py = (const float4*)(d_rpey + ((size_t)bh * QLEN + q) * GRD + sb);
#pragma unroll
            for (int u = 0; u < 8; u++) *(float4*)(rys + row * PR + sb + u * 4) = py[u];
        } else {
            float4 z = make_float4(0.f, 0.f, 0.f, 0.f);
#pragma unroll
            for (int u = 0; u < 8; u++) *(float4*)(rys + row * PR + sb + u * 4) = z;
        }
    }
    __syncthreads();

    uint32_t aQ[2][4];
    {
        uint32_t base = smem_u32(Qs);
        int m = wid * 16 + (lane & 15);
        uint32_t a0 = base + (uint32_t)(m * PK + ((lane >> 4) * 8)) * 2;
        ldmx4(aQ[0], a0);
        ldmx4(aQ[1], a0 + 32);
    }

    const int r0 = wid * 16 + (lane >> 2);
    const int cb = 2 * (lane & 3);

    // rx in registers (constant over all kv tiles)
    float2 rxa[8], rxb[8];
    {
        int qa = q0 + r0, qb2 = qa + 8;
        const float* rxg = d_rpex + (size_t)bh * QLEN * GRD;
        float2 z = make_float2(0.f, 0.f);
#pragma unroll
        for (int j = 0; j < 8; j++) {
            int n = j * 8 + cb;
            rxa[j] = (qa  < QLEN) ? *(const float2*)&rxg[(size_t)qa  * GRD + n] : z;
            rxb[j] = (qb2 < QLEN) ? *(const float2*)&rxg[(size_t)qb2 * GRD + n] : z;
        }
    }

    float oc[4][4];
#pragma unroll
    for (int i = 0; i < 4; i++)
#pragma unroll
        for (int j = 0; j < 4; j++) oc[i][j] = 0.f;
    float m_run0 = -1e30f, m_run1 = -1e30f, l_run0 = 0.f, l_run1 = 0.f;

    for (int t = 0; t < 64; t++) {
        if (t + 1 < 64) {
            int buf = (t + 1) & 1;
            uint32_t kd = smem_u32(smem + KS_OFF + buf * 5120) + (uint32_t)(srow * PK + sseg) * 2;
            uint32_t vd = smem_u32(smem + VS_OFF + buf * 5120) + (uint32_t)(srow * PK + sseg) * 2;
            const __half* ks = Kb + (size_t)((t + 1) * 64 + srow) * HD + sseg;
            const __half* vs = Vb + (size_t)((t + 1) * 64 + srow) * HD + sseg;
            CP16(kd, ks); CP16(kd + 16, ks + 8);
            CP16(vd, vs); CP16(vd + 16, vs + 8);
            CP_COMMIT();
            CP_WAIT1();
        } else {
            CP_WAIT0();
        }
        __syncthreads();

        const uint32_t KsB = smem_u32(smem + KS_OFF + (t & 1) * 5120);
        const uint32_t VsB = smem_u32(smem + VS_OFF + (t & 1) * 5120);

        float sc[8][4];
#pragma unroll
        for (int j = 0; j < 8; j++) {
            sc[j][0] = sc[j][1] = sc[j][2] = sc[j][3] = 0.f;
            uint32_t addr = KsB + (uint32_t)((j * 8 + (lane & 7)) * PK + ((lane >> 3) & 1) * 8) * 2;
            uint32_t bk0[2], bk1[2];
            ldmx2(bk0, addr);
            ldmx2(bk1, addr + 32);
            mma16816(sc[j], aQ[0], bk0);
            mma16816(sc[j], aQ[1], bk1);
        }

        // bias (rx + mask only; ry folded into max tracking)
        float mx0 = -1e30f, mx1 = -1e30f;
#pragma unroll
        for (int j = 0; j < 8; j++) {
            int n = j * 8 + cb;
            float2 mk = *(float2*)(mks + t * 64 + n);
            sc[j][0] += rxa[j].x + mk.x;
            sc[j][1] += rxa[j].y + mk.y;
            sc[j][2] += rxb[j].x + mk.x;
            sc[j][3] += rxb[j].y + mk.y;
            mx0 = fmaxf(mx0, fmaxf(sc[j][0], sc[j][1]));
            mx1 = fmaxf(mx1, fmaxf(sc[j][2], sc[j][3]));
        }
        mx0 = fmaxf(mx0, __shfl_xor_sync(0xffffffffu, mx0, 1));
        mx0 = fmaxf(mx0, __shfl_xor_sync(0xffffffffu, mx0, 2));
        mx1 = fmaxf(mx1, __shfl_xor_sync(0xffffffffu, mx1, 1));
        mx1 = fmaxf(mx1, __shfl_xor_sync(0xffffffffu, mx1, 2));

        float ry0 = rys[r0 * PR + t];
        float ry1 = rys[(r0 + 8) * PR + t];
        float mn0 = fmaxf(m_run0, mx0 + ry0), mn1 = fmaxf(m_run1, mx1 + ry1);
        float base0 = mn0 - ry0, base1 = mn1 - ry1;
        float f0 = ex2(m_run0 - mn0), f1 = ex2(m_run1 - mn1);
        m_run0 = mn0; m_run1 = mn1;

        float la0 = 0.f, la1 = 0.f;
        uint32_t pa[4][4];
#pragma unroll
        for (int j = 0; j < 8; j++) {
            float p0 = ex2(sc[j][0] - base0);
            float p1 = ex2(sc[j][1] - base0);
            float p2 = ex2(sc[j][2] - base1);
            float p3 = ex2(sc[j][3] - base1);
            la0 += p0 + p1; la1 += p2 + p3;
            int kt = j >> 1, hi = j & 1;
            pa[kt][2 * hi]     = packh2(p0, p1);
            pa[kt][2 * hi + 1] = packh2(p2, p3);
        }
        la0 += __shfl_xor_sync(0xffffffffu, la0, 1);
        la0 += __shfl_xor_sync(0xffffffffu, la0, 2);
        la1 += __shfl_xor_sync(0xffffffffu, la1, 1);
        la1 += __shfl_xor_sync(0xffffffffu, la1, 2);
        l_run0 = l_run0 * f0 + la0;
        l_run1 = l_run1 * f1 + la1;

#pragma unroll
        for (int no = 0; no < 4; no++) {
            oc[no][0] *= f0; oc[no][1] *= f0;
            oc[no][2] *= f1; oc[no][3] *= f1;
        }

#pragma unroll
        for (int kt = 0; kt < 4; kt++) {
            uint32_t addr = VsB + (uint32_t)((kt * 16 + (lane & 15)) * PK) * 2;
#pragma unroll
            for (int no = 0; no < 4; no++) {
                uint32_t bv[2];
                ldmx2t(bv, addr + (uint32_t)(no * 8) * 2);
                mma16816(oc[no], pa[kt], bv);
            }
        }
        __syncthreads();
    }

    {
        float inv0 = 1.0f / l_run0;
        float inv1 = 1.0f / l_run1;
        int qa = q0 + r0, qb2 = qa + 8;
#pragma unroll
        for (int no = 0; no < 4; no++) {
            int col = head * HD + no * 8 + cb;
            if (qa < QLEN) {
                *(uint32_t*)&d_ctxh[((size_t)b * QLEN + qa) * DIMV + col] =
                    packh2(oc[no][0] * inv0, oc[no][1] * inv0);
            }
            if (qb2 < QLEN) {
                *(uint32_t*)&d_ctxh[((size_t)b * QLEN + qb2) * DIMV + col] =
                    packh2(oc[no][2] * inv1, oc[no][3] * inv1);
            }
        }
    }
}

// ---------------- launch ----------------
extern "C" void kernel_launch(void* const* d_in, const int* in_sizes, int n_in,
                              void* d_out, int out_size)
{
    const float* hidden = (const float*)d_in[0];
    const float* refpts = (const float*)d_in[1];
    const float* kvst   = (const float*)d_in[2];
    const int*   amask  = (const int*)d_in[4];
    const float* m1w1 = (const float*)d_in[5];
    const float* m1b1 = (const float*)d_in[6];
    const float* m1w2 = (const float*)d_in[7];
    const float* m2w1 = (const float*)d_in[8];
    const float* m2b1 = (const float*)d_in[9];
    const float* m2w2 = (const float*)d_in[10];
    const float* qw = (const float*)d_in[11];
    const float* qb = (const float*)d_in[12];
    const float* kw = (const float*)d_in[13];
    const float* kb = (const float*)d_in[14];
    const float* vw = (const float*)d_in[15];
    const float* vb = (const float*)d_in[16];
    const float* ow = (const float*)d_in[17];
    const float* ob = (const float*)d_in[18];
    float* out = (float*)d_out;

    cudaFuncSetAttribute(attn_mma, cudaFuncAttributeMaxDynamicSharedMemorySize, ATTN_SMEM);

    const float qs2 = 0.17677669529663687f * L2E;  // 1/sqrt(32) * log2(e)

    convert_all<<<2770, 256>>>(qw, kw, vw, ow, kvst, hidden, m1w2, m2w2, amask);
    fat_mid<<<1532, 256, FAT_SMEM>>>(refpts, m1w1, m1b1, m2w1, m2b1, qb, kb, vb, qs2);
    attn_mma<<<dim3((QLEN + 63) / 64, B_ * NH), 128, ATTN_SMEM>>>();
    gemm_o<<<dim3(15, 8), 256, 15360>>>(ob, out);
}

// round 11
// speedup vs baseline: 2.6794x; 1.0382x over previous
#include <cuda_runtime.h>
#include <cuda_fp16.h>
#include <cstdint>

#define B_    2
#define QLEN  900
#define DIMV  256
#define NH    8
#define HD    32
#define KVLEN 4096
#define GRD   64
#define RPEH  512
#define L2E   1.4426950408889634f
#define NQT   15          // q tiles of 64
#define NSPL  2           // kv splits

// ---------------- scratch ----------------
__device__ __half d_Qh[B_*NH*QLEN*HD];
__device__ __half d_Kh[B_*NH*KVLEN*HD];
__device__ __half d_Vh[B_*NH*KVLEN*HD];
__device__ __half d_ctxh[B_*QLEN*DIMV];
__device__ float  d_rpex[B_*NH*QLEN*GRD];
__device__ float  d_rpey[B_*NH*QLEN*GRD];
__device__ __half d_Wh[4*65536];
__device__ __half d_Akv[B_*KVLEN*DIMV];
__device__ __half d_Aq[B_*QLEN*DIMV];
__device__ __half d_w2hi[2*8*512];
__device__ __half d_w2lo[2*8*512];
__device__ __half d_mskh[B_*KVLEN];            // -100*log2e*mask (f16)
__device__ float  d_po[16*NQT*NSPL*64*32];     // partial O
__device__ float  d_pm[16*NQT*NSPL*64];        // partial m
__device__ float  d_pl[16*NQT*NSPL*64];        // partial l

// ---------------- helpers ----------------
__device__ __forceinline__ void ldmx4(uint32_t* r, uint32_t a) {
    asm volatile("ldmatrix.sync.aligned.m8n8.x4.shared.b16 {%0,%1,%2,%3}, [%4];"
                 : "=r"(r[0]), "=r"(r[1]), "=r"(r[2]), "=r"(r[3]) : "r"(a));
}
__device__ __forceinline__ void ldmx2(uint32_t* r, uint32_t a) {
    asm volatile("ldmatrix.sync.aligned.m8n8.x2.shared.b16 {%0,%1}, [%2];"
                 : "=r"(r[0]), "=r"(r[1]) : "r"(a));
}
__device__ __forceinline__ void ldmx2t(uint32_t* r, uint32_t a) {
    asm volatile("ldmatrix.sync.aligned.m8n8.x2.trans.shared.b16 {%0,%1}, [%2];"
                 : "=r"(r[0]), "=r"(r[1]) : "r"(a));
}
__device__ __forceinline__ void mma16816(float* c, const uint32_t* a, const uint32_t* b) {
    asm volatile("mma.sync.aligned.m16n8k16.row.col.f32.f16.f16.f32 "
                 "{%0,%1,%2,%3}, {%4,%5,%6,%7}, {%8,%9}, {%0,%1,%2,%3};"
                 : "+f"(c[0]), "+f"(c[1]), "+f"(c[2]), "+f"(c[3])
                 : "r"(a[0]), "r"(a[1]), "r"(a[2]), "r"(a[3]), "r"(b[0]), "r"(b[1]));
}
__device__ __forceinline__ uint32_t smem_u32(const void* p) {
    return (uint32_t)__cvta_generic_to_shared(p);
}
__device__ __forceinline__ uint32_t packh2(float a, float b) {
    __half2 h = __floats2half2_rn(a, b);
    return *(uint32_t*)&h;
}
__device__ __forceinline__ float ex2(float x) {
    float y;
    asm("ex2.approx.ftz.f32 %0, %1;" : "=f"(y) : "f"(x));
    return y;
}
#define CP16(dst, src) asm volatile("cp.async.cg.shared.global [%0], [%1], 16;" :: "r"(dst), "l"(src) : "memory")
#define CP_COMMIT() asm volatile("cp.async.commit_group;" ::: "memory")
#define CP_WAIT1() asm volatile("cp.async.wait_group 1;" ::: "memory")
#define CP_WAIT0() asm volatile("cp.async.wait_group 0;" ::: "memory")

// ---------------- one-shot convert ----------------
__global__ void convert_all(const float* __restrict__ qw, const float* __restrict__ kw,
                            const float* __restrict__ vw, const float* __restrict__ ow,
                            const float* __restrict__ kvst, const float* __restrict__ hidden,
                            const float* __restrict__ m1w2, const float* __restrict__ m2w2,
                            const int* __restrict__ amask)
{
    unsigned u = blockIdx.x * 256 + threadIdx.x;
    if (u < 705024u) {
        const float* src; __half* dst; unsigned off;
        if      (u <  16384) { src = qw;     dst = d_Wh;          off = u; }
        else if (u <  32768) { src = kw;     dst = d_Wh + 65536;  off = u - 16384; }
        else if (u <  49152) { src = vw;     dst = d_Wh + 131072; off = u - 32768; }
        else if (u <  65536) { src = ow;     dst = d_Wh + 196608; off = u - 49152; }
        else if (u < 589824) { src = kvst;   dst = d_Akv;         off = u - 65536; }
        else                 { src = hidden; dst = d_Aq;          off = u - 589824; }
        float4 f = ((const float4*)src)[off];
        uint2 o; o.x = packh2(f.x, f.y); o.y = packh2(f.z, f.w);
        ((uint2*)dst)[off] = o;
    } else if (u < 707072u) {
        unsigned off = u - 705024u;
        int axis = off >> 10;
        unsigned o2 = off & 1023;
        const float* src = axis ? m2w2 : m1w2;
        float4 f = ((const float4*)src)[o2];
        __half hx = __float2half_rn(f.x), hy = __float2half_rn(f.y);
        __half hz = __float2half_rn(f.z), hw = __float2half_rn(f.w);
        uint2 hiu, lou;
        {
            __half2 a; a.x = hx; a.y = hy; hiu.x = *(uint32_t*)&a;
            __half2 b; b.x = hz; b.y = hw; hiu.y = *(uint32_t*)&b;
        }
        lou.x = packh2(f.x - __half2float(hx), f.y - __half2float(hy));
        lou.y = packh2(f.z - __half2float(hz), f.w - __half2float(hw));
        ((uint2*)(d_w2hi + axis * 4096))[o2] = hiu;
        ((uint2*)(d_w2lo + axis * 4096))[o2] = lou;
    } else {
        unsigned off = u - 707072u;                  // 0..2047, 4 mask vals each
        int4 m = ((const int4*)amask)[off];
        uint2 o;
        o.x = packh2(-100.0f * L2E * m.x, -100.0f * L2E * m.y);
        o.y = packh2(-100.0f * L2E * m.z, -100.0f * L2E * m.w);
        ((uint2*)d_mskh)[off] = o;
    }
}

// ---------------- HMMA GEMM core: 128x32 tile, optional dual weights ----------------
__device__ __forceinline__ void gemm_core(char* smem, int bm, int bn,
    const __half* __restrict__ Ah,
    const __half* __restrict__ W1, const float* __restrict__ b1v, void* C1,
    const __half* __restrict__ W2, const float* __restrict__ b2v, void* C2,
    int M, int rpb, float scale, int mode)
{
    __half* As  = (__half*)smem;
    __half* Ws1 = (__half*)(smem + 10240);
    __half* Ws2 = (__half*)(smem + 12800);

    const int tid = threadIdx.x;
    const int lane = tid & 31;
    const int wid = tid >> 5;
    const bool dual = (W2 != nullptr);

    const int arow = tid >> 1, aseg = (tid & 1) * 16;
    const int wrow = tid >> 3, wseg = (tid & 7) * 4;

    float c1[4][4], c2[4][4];
#pragma unroll
    for (int j = 0; j < 4; j++) {
        c1[j][0] = c1[j][1] = c1[j][2] = c1[j][3] = 0.f;
        c2[j][0] = c2[j][1] = c2[j][2] = c2[j][3] = 0.f;
    }

    const uint32_t AsB = smem_u32(As);
    const uint32_t W1B = smem_u32(Ws1);
    const uint32_t W2B = smem_u32(Ws2);

    uint4 pa0 = make_uint4(0,0,0,0), pa1 = pa0;
    uint2 pw1, pw2 = make_uint2(0,0);
    if (bm + arow < M) {
        const uint4* ap = (const uint4*)&Ah[(size_t)(bm + arow) * 256 + aseg];
        pa0 = ap[0]; pa1 = ap[1];
    }
    pw1 = *(const uint2*)&W1[(size_t)(bn + wrow) * 256 + wseg];
    if (dual) pw2 = *(const uint2*)&W2[(size_t)(bn + wrow) * 256 + wseg];

#pragma unroll 1
    for (int kit = 0; kit < 8; kit++) {
        *(uint4*)&As[arow * 40 + aseg]     = pa0;
        *(uint4*)&As[arow * 40 + aseg + 8] = pa1;
        *(uint2*)&Ws1[wrow * 40 + wseg]    = pw1;
        if (dual) *(uint2*)&Ws2[wrow * 40 + wseg] = pw2;
        __syncthreads();

        if (kit < 7) {
            int k0 = (kit + 1) * 32;
            pa0 = make_uint4(0,0,0,0); pa1 = pa0;
            if (bm + arow < M) {
                const uint4* ap = (const uint4*)&Ah[(size_t)(bm + arow) * 256 + k0 + aseg];
                pa0 = ap[0]; pa1 = ap[1];
            }
            pw1 = *(const uint2*)&W1[(size_t)(bn + wrow) * 256 + k0 + wseg];
            if (dual) pw2 = *(const uint2*)&W2[(size_t)(bn + wrow) * 256 + k0 + wseg];
        }

        uint32_t a0[4], a1[4];
        uint32_t aa = AsB + (uint32_t)((wid * 16 + (lane & 15)) * 40 + ((lane >> 4) * 8)) * 2;
        ldmx4(a0, aa);
        ldmx4(a1, aa + 32);
#pragma unroll
        for (int j = 0; j < 4; j++) {
            uint32_t woff = (uint32_t)((j * 8 + (lane & 7)) * 40 + ((lane >> 3) & 1) * 8) * 2;
            uint32_t b0[2], b1[2];
            ldmx2(b0, W1B + woff);
            ldmx2(b1, W1B + woff + 32);
            mma16816(c1[j], a0, b0);
            mma16816(c1[j], a1, b1);
            if (dual) {
                ldmx2(b0, W2B + woff);
                ldmx2(b1, W2B + woff + 32);
                mma16816(c2[j], a0, b0);
                mma16816(c2[j], a1, b1);
            }
        }
        __syncthreads();
    }

    const int r0 = bm + wid * 16 + (lane >> 2);
    const int cb = 2 * (lane & 3);
    if (mode == 0) {
        float* C = (float*)C1;
#pragma unroll
        for (int j = 0; j < 4; j++) {
            int col = bn + j * 8 + cb;
            float bb0 = b1v[col], bb1 = b1v[col + 1];
            if (r0 < M)     *(float2*)&C[(size_t)r0 * 256 + col]       = make_float2((c1[j][0] + bb0) * scale, (c1[j][1] + bb1) * scale);
            if (r0 + 8 < M) *(float2*)&C[(size_t)(r0 + 8) * 256 + col] = make_float2((c1[j][2] + bb0) * scale, (c1[j][3] + bb1) * scale);
        }
    } else {
        __half* Ca = (__half*)C1;
        __half* Cb = (__half*)C2;
        int ba = r0 / rpb, ra = r0 - ba * rpb;
        int bb = (r0 + 8) / rpb, rb = (r0 + 8) - bb * rpb;
#pragma unroll
        for (int j = 0; j < 4; j++) {
            int col = bn + j * 8 + cb;
            int head = col >> 5, d = col & 31;
            float x0 = b1v[col], x1 = b1v[col + 1];
            if (r0 < M) {
                *(uint32_t*)&Ca[((size_t)((ba * NH + head) * rpb + ra)) * HD + d] =
                    packh2((c1[j][0] + x0) * scale, (c1[j][1] + x1) * scale);
            }
            if (r0 + 8 < M) {
                *(uint32_t*)&Ca[((size_t)((bb * NH + head) * rpb + rb)) * HD + d] =
                    packh2((c1[j][2] + x0) * scale, (c1[j][3] + x1) * scale);
            }
            if (dual) {
                float y0 = b2v[col], y1 = b2v[col + 1];
                if (r0 < M) {
                    *(uint32_t*)&Cb[((size_t)((ba * NH + head) * rpb + ra)) * HD + d] =
                        packh2((c2[j][0] + y0) * scale, (c2[j][1] + y1) * scale);
                }
                if (r0 + 8 < M) {
                    *(uint32_t*)&Cb[((size_t)((bb * NH + head) * rpb + rb)) * HD + d] =
                        packh2((c2[j][2] + y0) * scale, (c2[j][3] + y1) * scale);
                }
            }
        }
    }
}

// ---------------- RPE core (unchanged from R10) ----------------
#define MKFRAG(px, hi0, lo0, hi1, lo1) { \
    float h0 = fmaxf(v0.x - v0.y * (px), 0.f); \
    float h1 = fmaxf(v0.z - v0.w * (px), 0.f); \
    float h2 = fmaxf(v1.x - v1.y * (px), 0.f); \
    float h3 = fmaxf(v1.z - v1.w * (px), 0.f); \
    __half2 t0 = __floats2half2_rn(h0, h1); float2 g0 = __half22float2(t0); \
    __half2 u0 = __floats2half2_rn(h0 - g0.x, h1 - g0.y); \
    __half2 t1 = __floats2half2_rn(h2, h3); float2 g1 = __half22float2(t1); \
    __half2 u1 = __floats2half2_rn(h2 - g1.x, h3 - g1.y); \
    hi0 = *(uint32_t*)&t0; lo0 = *(uint32_t*)&u0; \
    hi1 = *(uint32_t*)&t1; lo1 = *(uint32_t*)&u1; }

__device__ __forceinline__ void rpe_core(char* smem, int q0, int b, int axis,
    const float* __restrict__ refpts,
    const float* __restrict__ w1a, const float* __restrict__ b1a,
    const float* __restrict__ w1b, const float* __restrict__ b1b)
{
    __half* w2hi = (__half*)smem;
    __half* w2lo = (__half*)(smem + 8320);
    float2* as2  = (float2*)(smem + 16640);

    const int tid = threadIdx.x;
    const int lane = tid & 31;
    const int wid = tid >> 5;

    const float* w1  = axis ? w1b : w1a;
    const float* bb1 = axis ? b1b : b1a;
    float* out = axis ? d_rpey : d_rpex;

    const __half* ghi = d_w2hi + axis * 4096;
    const __half* glo = d_w2lo + axis * 4096;
#pragma unroll
    for (int i = tid; i < 2048; i += 256) {
        int h = i >> 8, jj = (i & 255) * 2;
        *(uint32_t*)&w2hi[h * 520 + jj] = *(const uint32_t*)&ghi[h * 512 + jj];
        *(uint32_t*)&w2lo[h * 520 + jj] = *(const uint32_t*)&glo[h * 512 + jj];
    }
#pragma unroll
    for (int i = tid; i < 4 * 512; i += 256) {
        int qi = i >> 9, j = i & 511;
        const float* rp = refpts + ((size_t)b * QLEN + q0 + qi) * 4;
        float cc = rp[axis], ss = rp[2 + axis];
        float lo = (cc - 0.5f * ss) * 1024.f, hi = (cc + 0.5f * ss) * 1024.f;
        float wx = w1[j * 2], wy = w1[j * 2 + 1];
        as2[qi * 512 + j] = make_float2(wx * lo + wy * hi + bb1[j], wx + wy);
    }
    __syncthreads();

    const int qi = wid >> 1;
    const int mt = wid & 1;
    const int q = q0 + qi;
    const int r = lane >> 2;
    const int c0 = 2 * (lane & 3);
    const float pxA = (mt * 16 + r + 0.5f) * 16.f;
    const float pxB = pxA + 128.f;
    const float pxC = pxA + 512.f;
    const float pxD = pxA + 640.f;

    const uint32_t WhiB = smem_u32(w2hi);
    const uint32_t WloB = smem_u32(w2lo);
    const float2* asq = as2 + qi * 512;

    float cA[4] = {0.f, 0.f, 0.f, 0.f};
    float cB[4] = {0.f, 0.f, 0.f, 0.f};

#pragma unroll 4
    for (int kk = 0; kk < 32; kk++) {
        int j0 = kk * 16 + c0;
        float4 v0 = *(const float4*)&asq[j0];
        float4 v1 = *(const float4*)&asq[j0 + 8];

        uint32_t ahiA[4], aloA[4], ahiB[4], aloB[4];
        MKFRAG(pxA, ahiA[0], aloA[0], ahiA[2], aloA[2]);
        MKFRAG(pxB, ahiA[1], aloA[1], ahiA[3], aloA[3]);
        MKFRAG(pxC, ahiB[0], aloB[0], ahiB[2], aloB[2]);
        MKFRAG(pxD, ahiB[1], aloB[1], ahiB[3], aloB[3]);

        uint32_t woff = (uint32_t)((lane & 7) * 520 + kk * 16 + ((lane >> 3) & 1) * 8) * 2;
        uint32_t bhi[2], blo[2];
        ldmx2(bhi, WhiB + woff);
        ldmx2(blo, WloB + woff);
        mma16816(cA, ahiA, bhi);
        mma16816(cA, aloA, bhi);
        mma16816(cA, ahiA, blo);
        mma16816(cB, ahiB, bhi);
        mma16816(cB, aloB, bhi);
        mma16816(cB, ahiB, blo);
    }

    {
        int p0 = mt * 16 + r;
        size_t hstride = (size_t)QLEN * GRD;
        size_t base = ((size_t)(b * NH + c0) * QLEN + q) * GRD;
        out[base + p0]               = cA[0] * L2E;
        out[base + hstride + p0]     = cA[1] * L2E;
        out[base + p0 + 8]           = cA[2] * L2E;
        out[base + hstride + p0 + 8] = cA[3] * L2E;
        out[base + p0 + 32]               = cB[0] * L2E;
        out[base + hstride + p0 + 32]     = cB[1] * L2E;
        out[base + p0 + 40]               = cB[2] * L2E;
        out[base + hstride + p0 + 40]     = cB[3] * L2E;
    }
}

// ---------------- fat mid-kernel ----------------
#define FAT_SMEM 33024
__global__ void __launch_bounds__(256, 4) fat_mid(
    const float* __restrict__ refpts,
    const float* __restrict__ w1a, const float* __restrict__ b1a,
    const float* __restrict__ w1b, const float* __restrict__ b1b,
    const float* __restrict__ qb, const float* __restrict__ kb,
    const float* __restrict__ vb, float qs2)
{
    extern __shared__ char smem[];
    int bx = blockIdx.x;
    if (bx < 900) {
        int axis = bx / 450;
        int rem = bx - axis * 450;
        int b = rem / 225;
        int q0 = (rem % 225) * 4;
        rpe_core(smem, q0, b, axis, refpts, w1a, b1a, w1b, b1b);
    } else if (bx < 1412) {
        int i = bx - 900;
        gemm_core(smem, (i & 63) * 128, (i >> 6) * 32,
                  d_Akv, d_Wh + 65536, kb, d_Kh, d_Wh + 131072, vb, d_Vh,
                  B_ * KVLEN, KVLEN, 1.0f, 1);
    } else {
        int i = bx - 1412;
        gemm_core(smem, (i % 15) * 128, (i / 15) * 32,
                  d_Aq, d_Wh, qb, d_Qh, nullptr, nullptr, nullptr,
                  B_ * QLEN, QLEN, qs2, 1);
    }
}

// ---------------- O projection ----------------
__global__ void __launch_bounds__(256) gemm_o(const float* __restrict__ ob, float* __restrict__ out)
{
    extern __shared__ char smem[];
    gemm_core(smem, blockIdx.x * 128, blockIdx.y * 32,
              d_ctxh, d_Wh + 196608, ob, out, nullptr, nullptr, nullptr,
              B_ * QLEN, QLEN, 1.0f, 0);
}

// ---------------- split-KV HMMA flash attention ----------------
#define PK 40
#define PRY 36
#define QS_OFF  0
#define KS_OFF  5120
#define VS_OFF  15360
#define RY_OFF  25600
#define MK_OFF  34816
#define ATTN_SMEM 38912

__global__ void __launch_bounds__(128) attn_split()
{
    extern __shared__ char smem[];
    __half* Qs  = (__half*)(smem + QS_OFF);
    float*  rys = (float*)(smem + RY_OFF);
    __half* mks = (__half*)(smem + MK_OFF);

    const int tid = threadIdx.x;
    const int lane = tid & 31;
    const int wid = tid >> 5;
    const int qt = blockIdx.x;
    const int bh = blockIdx.y;
    const int kvh = blockIdx.z;
    const int b = bh >> 3;
    const int q0 = qt * 64;
    const int kv0 = kvh * (KVLEN / NSPL);

    const __half* Kb = d_Kh + (size_t)bh * KVLEN * HD + (size_t)kv0 * HD;
    const __half* Vb = d_Vh + (size_t)bh * KVLEN * HD + (size_t)kv0 * HD;

    const int srow = tid >> 1, sseg = (tid & 1) * 16;
    {
        uint32_t kd = smem_u32(smem + KS_OFF) + (uint32_t)(srow * PK + sseg) * 2;
        uint32_t vd = smem_u32(smem + VS_OFF) + (uint32_t)(srow * PK + sseg) * 2;
        const __half* ks = Kb + (size_t)srow * HD + sseg;
        const __half* vs = Vb + (size_t)srow * HD + sseg;
        CP16(kd, ks); CP16(kd + 16, ks + 8);
        CP16(vd, vs); CP16(vd + 16, vs + 8);
        CP_COMMIT();
    }

    // mask (f16) for this half: 2048 vals
    {
        const uint4* mg = (const uint4*)(d_mskh + b * KVLEN + kv0);
#pragma unroll
        for (int i = tid; i < 256; i += 128) ((uint4*)mks)[i] = mg[i];
    }

    {
        int row = tid >> 1, seg = tid & 1;
        int q = q0 + row;
        uint4 v0 = make_uint4(0, 0, 0, 0), v1 = make_uint4(0, 0, 0, 0);
        if (q < QLEN) {
            const uint4* qp = (const uint4*)(d_Qh + ((size_t)bh * QLEN + q) * HD + seg * 16);
            v0 = qp[0]; v1 = qp[1];
        }
        *(uint4*)(Qs + row * PK + seg * 16)     = v0;
        *(uint4*)(Qs + row * PK + seg * 16 + 8) = v1;
    }
    // ry: 32 values (this half's grid rows) per q row
    {
        int row = tid >> 1, sb = (tid & 1) * 16;
        int q = q0 + row;
        if (q < QLEN) {
            const float4* py = (const float4*)(d_rpey + ((size_t)bh * QLEN + q) * GRD + kvh * 32 + sb);
#pragma unroll
            for (int u = 0; u < 4; u++) *(float4*)(rys + row * PRY + sb + u * 4) = py[u];
        } else {
            float4 z = make_float4(0.f, 0.f, 0.f, 0.f);
#pragma unroll
            for (int u = 0; u < 4; u++) *(float4*)(rys + row * PRY + sb + u * 4) = z;
        }
    }
    __syncthreads();

    uint32_t aQ[2][4];
    {
        uint32_t base = smem_u32(Qs);
        int m = wid * 16 + (lane & 15);
        uint32_t a0 = base + (uint32_t)(m * PK + ((lane >> 4) * 8)) * 2;
        ldmx4(aQ[0], a0);
        ldmx4(aQ[1], a0 + 32);
    }

    const int r0 = wid * 16 + (lane >> 2);
    const int cb = 2 * (lane & 3);

    float2 rxa[8], rxb[8];
    {
        int qa = q0 + r0, qb2 = qa + 8;
        const float* rxg = d_rpex + (size_t)bh * QLEN * GRD;
        float2 z = make_float2(0.f, 0.f);
#pragma unroll
        for (int j = 0; j < 8; j++) {
            int n = j * 8 + cb;
            rxa[j] = (qa  < QLEN) ? *(const float2*)&rxg[(size_t)qa  * GRD + n] : z;
            rxb[j] = (qb2 < QLEN) ? *(const float2*)&rxg[(size_t)qb2 * GRD + n] : z;
        }
    }

    float oc[4][4];
#pragma unroll
    for (int i = 0; i < 4; i++)
#pragma unroll
        for (int j = 0; j < 4; j++) oc[i][j] = 0.f;
    float m_run0 = -1e30f, m_run1 = -1e30f, l_run0 = 0.f, l_run1 = 0.f;

    const int NT = KVLEN / NSPL / 64;  // 32 tiles
    for (int t = 0; t < NT; t++) {
        if (t + 1 < NT) {
            int buf = (t + 1) & 1;
            uint32_t kd = smem_u32(smem + KS_OFF + buf * 5120) + (uint32_t)(srow * PK + sseg) * 2;
            uint32_t vd = smem_u32(smem + VS_OFF + buf * 5120) + (uint32_t)(srow * PK + sseg) * 2;
            const __half* ks = Kb + (size_t)((t + 1) * 64 + srow) * HD + sseg;
            const __half* vs = Vb + (size_t)((t + 1) * 64 + srow) * HD + sseg;
            CP16(kd, ks); CP16(kd + 16, ks + 8);
            CP16(vd, vs); CP16(vd + 16, vs + 8);
            CP_COMMIT();
            CP_WAIT1();
        } else {
            CP_WAIT0();
        }
        __syncthreads();

        const uint32_t KsB = smem_u32(smem + KS_OFF + (t & 1) * 5120);
        const uint32_t VsB = smem_u32(smem + VS_OFF + (t & 1) * 5120);

        float sc[8][4];
#pragma unroll
        for (int j = 0; j < 8; j++) {
            sc[j][0] = sc[j][1] = sc[j][2] = sc[j][3] = 0.f;
            uint32_t addr = KsB + (uint32_t)((j * 8 + (lane & 7)) * PK + ((lane >> 3) & 1) * 8) * 2;
            uint32_t bk0[2], bk1[2];
            ldmx2(bk0, addr);
            ldmx2(bk1, addr + 32);
            mma16816(sc[j], aQ[0], bk0);
            mma16816(sc[j], aQ[1], bk1);
        }

        float mx0 = -1e30f, mx1 = -1e30f;
#pragma unroll
        for (int j = 0; j < 8; j++) {
            int n = j * 8 + cb;
            float2 mk = __half22float2(*(__half2*)(mks + t * 64 + n));
            sc[j][0] += rxa[j].x + mk.x;
            sc[j][1] += rxa[j].y + mk.y;
            sc[j][2] += rxb[j].x + mk.x;
            sc[j][3] += rxb[j].y + mk.y;
            mx0 = fmaxf(mx0, fmaxf(sc[j][0], sc[j][1]));
            mx1 = fmaxf(mx1, fmaxf(sc[j][2], sc[j][3]));
        }
        mx0 = fmaxf(mx0, __shfl_xor_sync(0xffffffffu, mx0, 1));
        mx0 = fmaxf(mx0, __shfl_xor_sync(0xffffffffu, mx0, 2));
        mx1 = fmaxf(mx1, __shfl_xor_sync(0xffffffffu, mx1, 1));
        mx1 = fmaxf(mx1, __shfl_xor_sync(0xffffffffu, mx1, 2));

        float ry0 = rys[r0 * PRY + t];
        float ry1 = rys[(r0 + 8) * PRY + t];
        float mn0 = fmaxf(m_run0, mx0 + ry0), mn1 = fmaxf(m_run1, mx1 + ry1);
        float base0 = mn0 - ry0, base1 = mn1 - ry1;
        float f0 = ex2(m_run0 - mn0), f1 = ex2(m_run1 - mn1);
        m_run0 = mn0; m_run1 = mn1;

        float la0 = 0.f, la1 = 0.f;
        uint32_t pa[4][4];
#pragma unroll
        for (int j = 0; j < 8; j++) {
            float p0 = ex2(sc[j][0] - base0);
            float p1 = ex2(sc[j][1] - base0);
            float p2 = ex2(sc[j][2] - base1);
            float p3 = ex2(sc[j][3] - base1);
            la0 += p0 + p1; la1 += p2 + p3;
            int kt = j >> 1, hi = j & 1;
            pa[kt][2 * hi]     = packh2(p0, p1);
            pa[kt][2 * hi + 1] = packh2(p2, p3);
        }
        la0 += __shfl_xor_sync(0xffffffffu, la0, 1);
        la0 += __shfl_xor_sync(0xffffffffu, la0, 2);
        la1 += __shfl_xor_sync(0xffffffffu, la1, 1);
        la1 += __shfl_xor_sync(0xffffffffu, la1, 2);
        l_run0 = l_run0 * f0 + la0;
        l_run1 = l_run1 * f1 + la1;

#pragma unroll
        for (int no = 0; no < 4; no++) {
            oc[no][0] *= f0; oc[no][1] *= f0;
            oc[no][2] *= f1; oc[no][3] *= f1;
        }

#pragma unroll
        for (int kt = 0; kt < 4; kt++) {
            uint32_t addr = VsB + (uint32_t)((kt * 16 + (lane & 15)) * PK) * 2;
#pragma unroll
            for (int no = 0; no < 4; no++) {
                uint32_t bv[2];
                ldmx2t(bv, addr + (uint32_t)(no * 8) * 2);
                mma16816(oc[no], pa[kt], bv);
            }
        }
        __syncthreads();
    }

    // write partials
    {
        int cta = (bh * NQT + qt) * NSPL + kvh;
        float* po = d_po + (size_t)cta * 2048;
#pragma unroll
        for (int no = 0; no < 4; no++) {
            int d = no * 8 + cb;
            *(float2*)&po[r0 * 32 + d]       = make_float2(oc[no][0], oc[no][1]);
            *(float2*)&po[(r0 + 8) * 32 + d] = make_float2(oc[no][2], oc[no][3]);
        }
        if ((lane & 3) == 0) {
            d_pm[cta * 64 + r0]     = m_run0;
            d_pm[cta * 64 + r0 + 8] = m_run1;
            d_pl[cta * 64 + r0]     = l_run0;
            d_pl[cta * 64 + r0 + 8] = l_run1;
        }
    }
}

// ---------------- merge partials -> ctx f16 ----------------
__global__ void __launch_bounds__(64) attn_merge()
{
    const int bx = blockIdx.x;         // bh * NQT + qt
    const int bh = bx / NQT;
    const int qt = bx - bh * NQT;
    const int b = bh >> 3;
    const int head = bh & 7;
    const int ql = threadIdx.x;        // 0..63
    const int q = qt * 64 + ql;
    if (q >= QLEN) return;

    const int c0 = bx * NSPL;
    float m0 = d_pm[(c0 + 0) * 64 + ql], m1 = d_pm[(c0 + 1) * 64 + ql];
    float l0 = d_pl[(c0 + 0) * 64 + ql], l1 = d_pl[(c0 + 1) * 64 + ql];
    float m = fmaxf(m0, m1);
    float f0 = ex2(m0 - m), f1 = ex2(m1 - m);
    float inv = 1.0f / (l0 * f0 + l1 * f1);
    f0 *= inv; f1 *= inv;

    const float4* o0 = (const float4*)(d_po + (size_t)(c0 + 0) * 2048 + ql * 32);
    const float4* o1 = (const float4*)(d_po + (size_t)(c0 + 1) * 2048 + ql * 32);
    uint2* dst = (uint2*)(d_ctxh + ((size_t)b * QLEN + q) * DIMV + head * HD);
#pragma unroll
    for (int u = 0; u < 8; u += 2) {
        float4 a = o0[u],     b4 = o1[u];
        float4 c = o0[u + 1], d4 = o1[u + 1];
        uint2 w0, w1;
        w0.x = packh2(a.x * f0 + b4.x * f1, a.y * f0 + b4.y * f1);
        w0.y = packh2(a.z * f0 + b4.z * f1, a.w * f0 + b4.w * f1);
        w1.x = packh2(c.x * f0 + d4.x * f1, c.y * f0 + d4.y * f1);
        w1.y = packh2(c.z * f0 + d4.z * f1, c.w * f0 + d4.w * f1);
        dst[u]     = w0;
        dst[u + 1] = w1;
    }
}

// ---------------- launch ----------------
extern "C" void kernel_launch(void* const* d_in, const int* in_sizes, int n_in,
                              void* d_out, int out_size)
{
    const float* hidden = (const float*)d_in[0];
    const float* refpts = (const float*)d_in[1];
    const float* kvst   = (const float*)d_in[2];
    const int*   amask  = (const int*)d_in[4];
    const float* m1w1 = (const float*)d_in[5];
    const float* m1b1 = (const float*)d_in[6];
    const float* m1w2 = (const float*)d_in[7];
    const float* m2w1 = (const float*)d_in[8];
    const float* m2b1 = (const float*)d_in[9];
    const float* m2w2 = (const float*)d_in[10];
    const float* qw = (const float*)d_in[11];
    const float* qb = (const float*)d_in[12];
    const float* kw = (const float*)d_in[13];
    const float* kb = (const float*)d_in[14];
    const float* vw = (const float*)d_in[15];
    const float* vb = (const float*)d_in[16];
    const float* ow = (const float*)d_in[17];
    const float* ob = (const float*)d_in[18];
    float* out = (float*)d_out;

    cudaFuncSetAttribute(attn_split, cudaFuncAttributeMaxDynamicSharedMemorySize, ATTN_SMEM);

    const float qs2 = 0.17677669529663687f * L2E;

    convert_all<<<2770, 256>>>(qw, kw, vw, ow, kvst, hidden, m1w2, m2w2, amask);
    fat_mid<<<1532, 256, FAT_SMEM>>>(refpts, m1w1, m1b1, m2w1, m2b1, qb, kb, vb, qs2);
    attn_split<<<dim3(NQT, B_ * NH, NSPL), 128, ATTN_SMEM>>>();
    attn_merge<<<16 * NQT, 64>>>();
    gemm_o<<<dim3(15, 8), 256, 15360>>>(ob, out);
}

// round 12
// speedup vs baseline: 2.8036x; 1.0464x over previous
#include <cuda_runtime.h>
#include <cuda_fp16.h>
#include <cstdint>

#define B_    2
#define QLEN  900
#define DIMV  256
#define NH    8
#define HD    32
#define KVLEN 4096
#define GRD   64
#define RPEH  512
#define L2E   1.4426950408889634f
#define NQT   15          // q tiles of 64
#define NSPL  4           // kv splits

// ---------------- scratch ----------------
__device__ __half d_Qh[B_*NH*QLEN*HD];
__device__ __half d_Kh[B_*NH*KVLEN*HD];
__device__ __half d_Vh[B_*NH*KVLEN*HD];
__device__ __half d_ctxh[B_*QLEN*DIMV];
__device__ float  d_rpex[B_*NH*QLEN*GRD];
__device__ float  d_rpey[B_*NH*QLEN*GRD];
__device__ __half d_Wh[4*65536];
__device__ __half d_Akv[B_*KVLEN*DIMV];
__device__ __half d_Aq[B_*QLEN*DIMV];
__device__ __half d_w2hi[2*8*512];
__device__ __half d_w2lo[2*8*512];
__device__ __half d_mskh[B_*KVLEN];            // -100*log2e*mask (f16)
__device__ float  d_po[16*NQT*NSPL*64*32];     // partial O
__device__ float  d_pm[16*NQT*NSPL*64];        // partial m
__device__ float  d_pl[16*NQT*NSPL*64];        // partial l

// ---------------- helpers ----------------
__device__ __forceinline__ void ldmx4(uint32_t* r, uint32_t a) {
    asm volatile("ldmatrix.sync.aligned.m8n8.x4.shared.b16 {%0,%1,%2,%3}, [%4];"
                 : "=r"(r[0]), "=r"(r[1]), "=r"(r[2]), "=r"(r[3]) : "r"(a));
}
__device__ __forceinline__ void ldmx2(uint32_t* r, uint32_t a) {
    asm volatile("ldmatrix.sync.aligned.m8n8.x2.shared.b16 {%0,%1}, [%2];"
                 : "=r"(r[0]), "=r"(r[1]) : "r"(a));
}
__device__ __forceinline__ void ldmx2t(uint32_t* r, uint32_t a) {
    asm volatile("ldmatrix.sync.aligned.m8n8.x2.trans.shared.b16 {%0,%1}, [%2];"
                 : "=r"(r[0]), "=r"(r[1]) : "r"(a));
}
__device__ __forceinline__ void mma16816(float* c, const uint32_t* a, const uint32_t* b) {
    asm volatile("mma.sync.aligned.m16n8k16.row.col.f32.f16.f16.f32 "
                 "{%0,%1,%2,%3}, {%4,%5,%6,%7}, {%8,%9}, {%0,%1,%2,%3};"
                 : "+f"(c[0]), "+f"(c[1]), "+f"(c[2]), "+f"(c[3])
                 : "r"(a[0]), "r"(a[1]), "r"(a[2]), "r"(a[3]), "r"(b[0]), "r"(b[1]));
}
__device__ __forceinline__ uint32_t smem_u32(const void* p) {
    return (uint32_t)__cvta_generic_to_shared(p);
}
__device__ __forceinline__ uint32_t packh2(float a, float b) {
    __half2 h = __floats2half2_rn(a, b);
    return *(uint32_t*)&h;
}
__device__ __forceinline__ float ex2(float x) {
    float y;
    asm("ex2.approx.ftz.f32 %0, %1;" : "=f"(y) : "f"(x));
    return y;
}
#define CP16(dst, src) asm volatile("cp.async.cg.shared.global [%0], [%1], 16;" :: "r"(dst), "l"(src) : "memory")
#define CP_COMMIT() asm volatile("cp.async.commit_group;" ::: "memory")
#define CP_WAIT1() asm volatile("cp.async.wait_group 1;" ::: "memory")
#define CP_WAIT0() asm volatile("cp.async.wait_group 0;" ::: "memory")

// ---------------- one-shot convert ----------------
__global__ void convert_all(const float* __restrict__ qw, const float* __restrict__ kw,
                            const float* __restrict__ vw, const float* __restrict__ ow,
                            const float* __restrict__ kvst, const float* __restrict__ hidden,
                            const float* __restrict__ m1w2, const float* __restrict__ m2w2,
                            const int* __restrict__ amask)
{
    unsigned u = blockIdx.x * 256 + threadIdx.x;
    if (u < 705024u) {
        const float* src; __half* dst; unsigned off;
        if      (u <  16384) { src = qw;     dst = d_Wh;          off = u; }
        else if (u <  32768) { src = kw;     dst = d_Wh + 65536;  off = u - 16384; }
        else if (u <  49152) { src = vw;     dst = d_Wh + 131072; off = u - 32768; }
        else if (u <  65536) { src = ow;     dst = d_Wh + 196608; off = u - 49152; }
        else if (u < 589824) { src = kvst;   dst = d_Akv;         off = u - 65536; }
        else                 { src = hidden; dst = d_Aq;          off = u - 589824; }
        float4 f = ((const float4*)src)[off];
        uint2 o; o.x = packh2(f.x, f.y); o.y = packh2(f.z, f.w);
        ((uint2*)dst)[off] = o;
    } else if (u < 707072u) {
        unsigned off = u - 705024u;
        int axis = off >> 10;
        unsigned o2 = off & 1023;
        const float* src = axis ? m2w2 : m1w2;
        float4 f = ((const float4*)src)[o2];
        __half hx = __float2half_rn(f.x), hy = __float2half_rn(f.y);
        __half hz = __float2half_rn(f.z), hw = __float2half_rn(f.w);
        uint2 hiu, lou;
        {
            __half2 a; a.x = hx; a.y = hy; hiu.x = *(uint32_t*)&a;
            __half2 b; b.x = hz; b.y = hw; hiu.y = *(uint32_t*)&b;
        }
        lou.x = packh2(f.x - __half2float(hx), f.y - __half2float(hy));
        lou.y = packh2(f.z - __half2float(hz), f.w - __half2float(hw));
        ((uint2*)(d_w2hi + axis * 4096))[o2] = hiu;
        ((uint2*)(d_w2lo + axis * 4096))[o2] = lou;
    } else {
        unsigned off = u - 707072u;
        int4 m = ((const int4*)amask)[off];
        uint2 o;
        o.x = packh2(-100.0f * L2E * m.x, -100.0f * L2E * m.y);
        o.y = packh2(-100.0f * L2E * m.z, -100.0f * L2E * m.w);
        ((uint2*)d_mskh)[off] = o;
    }
}

// ---------------- HMMA GEMM core: 128x32 tile, optional dual weights ----------------
__device__ __forceinline__ void gemm_core(char* smem, int bm, int bn,
    const __half* __restrict__ Ah,
    const __half* __restrict__ W1, const float* __restrict__ b1v, void* C1,
    const __half* __restrict__ W2, const float* __restrict__ b2v, void* C2,
    int M, int rpb, float scale, int mode)
{
    __half* As  = (__half*)smem;
    __half* Ws1 = (__half*)(smem + 10240);
    __half* Ws2 = (__half*)(smem + 12800);

    const int tid = threadIdx.x;
    const int lane = tid & 31;
    const int wid = tid >> 5;
    const bool dual = (W2 != nullptr);

    const int arow = tid >> 1, aseg = (tid & 1) * 16;
    const int wrow = tid >> 3, wseg = (tid & 7) * 4;

    float c1[4][4], c2[4][4];
#pragma unroll
    for (int j = 0; j < 4; j++) {
        c1[j][0] = c1[j][1] = c1[j][2] = c1[j][3] = 0.f;
        c2[j][0] = c2[j][1] = c2[j][2] = c2[j][3] = 0.f;
    }

    const uint32_t AsB = smem_u32(As);
    const uint32_t W1B = smem_u32(Ws1);
    const uint32_t W2B = smem_u32(Ws2);

    uint4 pa0 = make_uint4(0,0,0,0), pa1 = pa0;
    uint2 pw1, pw2 = make_uint2(0,0);
    if (bm + arow < M) {
        const uint4* ap = (const uint4*)&Ah[(size_t)(bm + arow) * 256 + aseg];
        pa0 = ap[0]; pa1 = ap[1];
    }
    pw1 = *(const uint2*)&W1[(size_t)(bn + wrow) * 256 + wseg];
    if (dual) pw2 = *(const uint2*)&W2[(size_t)(bn + wrow) * 256 + wseg];

#pragma unroll 1
    for (int kit = 0; kit < 8; kit++) {
        *(uint4*)&As[arow * 40 + aseg]     = pa0;
        *(uint4*)&As[arow * 40 + aseg + 8] = pa1;
        *(uint2*)&Ws1[wrow * 40 + wseg]    = pw1;
        if (dual) *(uint2*)&Ws2[wrow * 40 + wseg] = pw2;
        __syncthreads();

        if (kit < 7) {
            int k0 = (kit + 1) * 32;
            pa0 = make_uint4(0,0,0,0); pa1 = pa0;
            if (bm + arow < M) {
                const uint4* ap = (const uint4*)&Ah[(size_t)(bm + arow) * 256 + k0 + aseg];
                pa0 = ap[0]; pa1 = ap[1];
            }
            pw1 = *(const uint2*)&W1[(size_t)(bn + wrow) * 256 + k0 + wseg];
            if (dual) pw2 = *(const uint2*)&W2[(size_t)(bn + wrow) * 256 + k0 + wseg];
        }

        uint32_t a0[4], a1[4];
        uint32_t aa = AsB + (uint32_t)((wid * 16 + (lane & 15)) * 40 + ((lane >> 4) * 8)) * 2;
        ldmx4(a0, aa);
        ldmx4(a1, aa + 32);
#pragma unroll
        for (int j = 0; j < 4; j++) {
            uint32_t woff = (uint32_t)((j * 8 + (lane & 7)) * 40 + ((lane >> 3) & 1) * 8) * 2;
            uint32_t b0[2], b1[2];
            ldmx2(b0, W1B + woff);
            ldmx2(b1, W1B + woff + 32);
            mma16816(c1[j], a0, b0);
            mma16816(c1[j], a1, b1);
            if (dual) {
                ldmx2(b0, W2B + woff);
                ldmx2(b1, W2B + woff + 32);
                mma16816(c2[j], a0, b0);
                mma16816(c2[j], a1, b1);
            }
        }
        __syncthreads();
    }

    const int r0 = bm + wid * 16 + (lane >> 2);
    const int cb = 2 * (lane & 3);
    if (mode == 0) {
        float* C = (float*)C1;
#pragma unroll
        for (int j = 0; j < 4; j++) {
            int col = bn + j * 8 + cb;
            float bb0 = b1v[col], bb1 = b1v[col + 1];
            if (r0 < M)     *(float2*)&C[(size_t)r0 * 256 + col]       = make_float2((c1[j][0] + bb0) * scale, (c1[j][1] + bb1) * scale);
            if (r0 + 8 < M) *(float2*)&C[(size_t)(r0 + 8) * 256 + col] = make_float2((c1[j][2] + bb0) * scale, (c1[j][3] + bb1) * scale);
        }
    } else {
        __half* Ca = (__half*)C1;
        __half* Cb = (__half*)C2;
        int ba = r0 / rpb, ra = r0 - ba * rpb;
        int bb = (r0 + 8) / rpb, rb = (r0 + 8) - bb * rpb;
#pragma unroll
        for (int j = 0; j < 4; j++) {
            int col = bn + j * 8 + cb;
            int head = col >> 5, d = col & 31;
            float x0 = b1v[col], x1 = b1v[col + 1];
            if (r0 < M) {
                *(uint32_t*)&Ca[((size_t)((ba * NH + head) * rpb + ra)) * HD + d] =
                    packh2((c1[j][0] + x0) * scale, (c1[j][1] + x1) * scale);
            }
            if (r0 + 8 < M) {
                *(uint32_t*)&Ca[((size_t)((bb * NH + head) * rpb + rb)) * HD + d] =
                    packh2((c1[j][2] + x0) * scale, (c1[j][3] + x1) * scale);
            }
            if (dual) {
                float y0 = b2v[col], y1 = b2v[col + 1];
                if (r0 < M) {
                    *(uint32_t*)&Cb[((size_t)((ba * NH + head) * rpb + ra)) * HD + d] =
                        packh2((c2[j][0] + y0) * scale, (c2[j][1] + y1) * scale);
                }
                if (r0 + 8 < M) {
                    *(uint32_t*)&Cb[((size_t)((bb * NH + head) * rpb + rb)) * HD + d] =
                        packh2((c2[j][2] + y0) * scale, (c2[j][3] + y1) * scale);
                }
            }
        }
    }
}

// ---------------- RPE core ----------------
#define MKFRAG(px, hi0, lo0, hi1, lo1) { \
    float h0 = fmaxf(v0.x - v0.y * (px), 0.f); \
    float h1 = fmaxf(v0.z - v0.w * (px), 0.f); \
    float h2 = fmaxf(v1.x - v1.y * (px), 0.f); \
    float h3 = fmaxf(v1.z - v1.w * (px), 0.f); \
    __half2 t0 = __floats2half2_rn(h0, h1); float2 g0 = __half22float2(t0); \
    __half2 u0 = __floats2half2_rn(h0 - g0.x, h1 - g0.y); \
    __half2 t1 = __floats2half2_rn(h2, h3); float2 g1 = __half22float2(t1); \
    __half2 u1 = __floats2half2_rn(h2 - g1.x, h3 - g1.y); \
    hi0 = *(uint32_t*)&t0; lo0 = *(uint32_t*)&u0; \
    hi1 = *(uint32_t*)&t1; lo1 = *(uint32_t*)&u1; }

__device__ __forceinline__ void rpe_core(char* smem, int q0, int b, int axis,
    const float* __restrict__ refpts,
    const float* __restrict__ w1a, const float* __restrict__ b1a,
    const float* __restrict__ w1b, const float* __restrict__ b1b)
{
    __half* w2hi = (__half*)smem;
    __half* w2lo = (__half*)(smem + 8320);
    float2* as2  = (float2*)(smem + 16640);

    const int tid = threadIdx.x;
    const int lane = tid & 31;
    const int wid = tid >> 5;

    const float* w1  = axis ? w1b : w1a;
    const float* bb1 = axis ? b1b : b1a;
    float* out = axis ? d_rpey : d_rpex;

    const __half* ghi = d_w2hi + axis * 4096;
    const __half* glo = d_w2lo + axis * 4096;
#pragma unroll
    for (int i = tid; i < 2048; i += 256) {
        int h = i >> 8, jj = (i & 255) * 2;
        *(uint32_t*)&w2hi[h * 520 + jj] = *(const uint32_t*)&ghi[h * 512 + jj];
        *(uint32_t*)&w2lo[h * 520 + jj] = *(const uint32_t*)&glo[h * 512 + jj];
    }
#pragma unroll
    for (int i = tid; i < 4 * 512; i += 256) {
        int qi = i >> 9, j = i & 511;
        const float* rp = refpts + ((size_t)b * QLEN + q0 + qi) * 4;
        float cc = rp[axis], ss = rp[2 + axis];
        float lo = (cc - 0.5f * ss) * 1024.f, hi = (cc + 0.5f * ss) * 1024.f;
        float wx = w1[j * 2], wy = w1[j * 2 + 1];
        as2[qi * 512 + j] = make_float2(wx * lo + wy * hi + bb1[j], wx + wy);
    }
    __syncthreads();

    const int qi = wid >> 1;
    const int mt = wid & 1;
    const int q = q0 + qi;
    const int r = lane >> 2;
    const int c0 = 2 * (lane & 3);
    const float pxA = (mt * 16 + r + 0.5f) * 16.f;
    const float pxB = pxA + 128.f;
    const float pxC = pxA + 512.f;
    const float pxD = pxA + 640.f;

    const uint32_t WhiB = smem_u32(w2hi);
    const uint32_t WloB = smem_u32(w2lo);
    const float2* asq = as2 + qi * 512;

    float cA[4] = {0.f, 0.f, 0.f, 0.f};
    float cB[4] = {0.f, 0.f, 0.f, 0.f};

#pragma unroll 4
    for (int kk = 0; kk < 32; kk++) {
        int j0 = kk * 16 + c0;
        float4 v0 = *(const float4*)&asq[j0];
        float4 v1 = *(const float4*)&asq[j0 + 8];

        uint32_t ahiA[4], aloA[4], ahiB[4], aloB[4];
        MKFRAG(pxA, ahiA[0], aloA[0], ahiA[2], aloA[2]);
        MKFRAG(pxB, ahiA[1], aloA[1], ahiA[3], aloA[3]);
        MKFRAG(pxC, ahiB[0], aloB[0], ahiB[2], aloB[2]);
        MKFRAG(pxD, ahiB[1], aloB[1], ahiB[3], aloB[3]);

        uint32_t woff = (uint32_t)((lane & 7) * 520 + kk * 16 + ((lane >> 3) & 1) * 8) * 2;
        uint32_t bhi[2], blo[2];
        ldmx2(bhi, WhiB + woff);
        ldmx2(blo, WloB + woff);
        mma16816(cA, ahiA, bhi);
        mma16816(cA, aloA, bhi);
        mma16816(cA, ahiA, blo);
        mma16816(cB, ahiB, bhi);
        mma16816(cB, aloB, bhi);
        mma16816(cB, ahiB, blo);
    }

    {
        int p0 = mt * 16 + r;
        size_t hstride = (size_t)QLEN * GRD;
        size_t base = ((size_t)(b * NH + c0) * QLEN + q) * GRD;
        out[base + p0]               = cA[0] * L2E;
        out[base + hstride + p0]     = cA[1] * L2E;
        out[base + p0 + 8]           = cA[2] * L2E;
        out[base + hstride + p0 + 8] = cA[3] * L2E;
        out[base + p0 + 32]               = cB[0] * L2E;
        out[base + hstride + p0 + 32]     = cB[1] * L2E;
        out[base + p0 + 40]               = cB[2] * L2E;
        out[base + hstride + p0 + 40]     = cB[3] * L2E;
    }
}

// ---------------- fat mid-kernel ----------------
#define FAT_SMEM 33024
__global__ void __launch_bounds__(256, 4) fat_mid(
    const float* __restrict__ refpts,
    const float* __restrict__ w1a, const float* __restrict__ b1a,
    const float* __restrict__ w1b, const float* __restrict__ b1b,
    const float* __restrict__ qb, const float* __restrict__ kb,
    const float* __restrict__ vb, float qs2)
{
    extern __shared__ char smem[];
    int bx = blockIdx.x;
    if (bx < 900) {
        int axis = bx / 450;
        int rem = bx - axis * 450;
        int b = rem / 225;
        int q0 = (rem % 225) * 4;
        rpe_core(smem, q0, b, axis, refpts, w1a, b1a, w1b, b1b);
    } else if (bx < 1412) {
        int i = bx - 900;
        gemm_core(smem, (i & 63) * 128, (i >> 6) * 32,
                  d_Akv, d_Wh + 65536, kb, d_Kh, d_Wh + 131072, vb, d_Vh,
                  B_ * KVLEN, KVLEN, 1.0f, 1);
    } else {
        int i = bx - 1412;
        gemm_core(smem, (i % 15) * 128, (i / 15) * 32,
                  d_Aq, d_Wh, qb, d_Qh, nullptr, nullptr, nullptr,
                  B_ * QLEN, QLEN, qs2, 1);
    }
}

// ---------------- O projection ----------------
__global__ void __launch_bounds__(256) gemm_o(const float* __restrict__ ob, float* __restrict__ out)
{
    extern __shared__ char smem[];
    gemm_core(smem, blockIdx.x * 128, blockIdx.y * 32,
              d_ctxh, d_Wh + 196608, ob, out, nullptr, nullptr, nullptr,
              B_ * QLEN, QLEN, 1.0f, 0);
}

// ---------------- split-KV HMMA flash attention (NSPL=4) ----------------
#define PK 40
#define PRY 20
#define QS_OFF  0
#define KS_OFF  5120
#define VS_OFF  15360
#define RY_OFF  25600
#define MK_OFF  30720
#define ATTN_SMEM 32768

__global__ void __launch_bounds__(128) attn_split()
{
    extern __shared__ char smem[];
    __half* Qs  = (__half*)(smem + QS_OFF);
    float*  rys = (float*)(smem + RY_OFF);
    __half* mks = (__half*)(smem + MK_OFF);

    const int tid = threadIdx.x;
    const int lane = tid & 31;
    const int wid = tid >> 5;
    const int qt = blockIdx.x;
    const int bh = blockIdx.y;
    const int kvh = blockIdx.z;
    const int b = bh >> 3;
    const int q0 = qt * 64;
    const int kv0 = kvh * (KVLEN / NSPL);

    const __half* Kb = d_Kh + (size_t)bh * KVLEN * HD + (size_t)kv0 * HD;
    const __half* Vb = d_Vh + (size_t)bh * KVLEN * HD + (size_t)kv0 * HD;

    const int srow = tid >> 1, sseg = (tid & 1) * 16;
    {
        uint32_t kd = smem_u32(smem + KS_OFF) + (uint32_t)(srow * PK + sseg) * 2;
        uint32_t vd = smem_u32(smem + VS_OFF) + (uint32_t)(srow * PK + sseg) * 2;
        const __half* ks = Kb + (size_t)srow * HD + sseg;
        const __half* vs = Vb + (size_t)srow * HD + sseg;
        CP16(kd, ks); CP16(kd + 16, ks + 8);
        CP16(vd, vs); CP16(vd + 16, vs + 8);
        CP_COMMIT();
    }

    // mask (f16) for this quarter: 1024 vals = 128 uint4
    if (tid < 128) {
        const uint4* mg = (const uint4*)(d_mskh + b * KVLEN + kv0);
        ((uint4*)mks)[tid] = mg[tid];
    }

    {
        int row = tid >> 1, seg = tid & 1;
        int q = q0 + row;
        uint4 v0 = make_uint4(0, 0, 0, 0), v1 = make_uint4(0, 0, 0, 0);
        if (q < QLEN) {
            const uint4* qp = (const uint4*)(d_Qh + ((size_t)bh * QLEN + q) * HD + seg * 16);
            v0 = qp[0]; v1 = qp[1];
        }
        *(uint4*)(Qs + row * PK + seg * 16)     = v0;
        *(uint4*)(Qs + row * PK + seg * 16 + 8) = v1;
    }
    // ry: 16 values (this quarter's grid rows) per q row
    {
        int row = tid >> 1, sb = (tid & 1) * 8;
        int q = q0 + row;
        if (q < QLEN) {
            const float4* py = (const float4*)(d_rpey + ((size_t)bh * QLEN + q) * GRD + kvh * 16 + sb);
            *(float4*)(rys + row * PRY + sb)     = py[0];
            *(float4*)(rys + row * PRY + sb + 4) = py[1];
        } else {
            float4 z = make_float4(0.f, 0.f, 0.f, 0.f);
            *(float4*)(rys + row * PRY + sb)     = z;
            *(float4*)(rys + row * PRY + sb + 4) = z;
        }
    }
    __syncthreads();

    uint32_t aQ[2][4];
    {
        uint32_t base = smem_u32(Qs);
        int m = wid * 16 + (lane & 15);
        uint32_t a0 = base + (uint32_t)(m * PK + ((lane >> 4) * 8)) * 2;
        ldmx4(aQ[0], a0);
        ldmx4(aQ[1], a0 + 32);
    }

    const int r0 = wid * 16 + (lane >> 2);
    const int cb = 2 * (lane & 3);

    float2 rxa[8], rxb[8];
    {
        int qa = q0 + r0, qb2 = qa + 8;
        const float* rxg = d_rpex + (size_t)bh * QLEN * GRD;
        float2 z = make_float2(0.f, 0.f);
#pragma unroll
        for (int j = 0; j < 8; j++) {
            int n = j * 8 + cb;
            rxa[j] = (qa  < QLEN) ? *(const float2*)&rxg[(size_t)qa  * GRD + n] : z;
            rxb[j] = (qb2 < QLEN) ? *(const float2*)&rxg[(size_t)qb2 * GRD + n] : z;
        }
    }

    float oc[4][4];
#pragma unroll
    for (int i = 0; i < 4; i++)
#pragma unroll
        for (int j = 0; j < 4; j++) oc[i][j] = 0.f;
    float m_run0 = -1e30f, m_run1 = -1e30f, l_run0 = 0.f, l_run1 = 0.f;

    const int NT = KVLEN / NSPL / 64;  // 16 tiles
    for (int t = 0; t < NT; t++) {
        if (t + 1 < NT) {
            int buf = (t + 1) & 1;
            uint32_t kd = smem_u32(smem + KS_OFF + buf * 5120) + (uint32_t)(srow * PK + sseg) * 2;
            uint32_t vd = smem_u32(smem + VS_OFF + buf * 5120) + (uint32_t)(srow * PK + sseg) * 2;
            const __half* ks = Kb + (size_t)((t + 1) * 64 + srow) * HD + sseg;
            const __half* vs = Vb + (size_t)((t + 1) * 64 + srow) * HD + sseg;
            CP16(kd, ks); CP16(kd + 16, ks + 8);
            CP16(vd, vs); CP16(vd + 16, vs + 8);
            CP_COMMIT();
            CP_WAIT1();
        } else {
            CP_WAIT0();
        }
        __syncthreads();

        const uint32_t KsB = smem_u32(smem + KS_OFF + (t & 1) * 5120);
        const uint32_t VsB = smem_u32(smem + VS_OFF + (t & 1) * 5120);

        float sc[8][4];
#pragma unroll
        for (int j = 0; j < 8; j++) {
            sc[j][0] = sc[j][1] = sc[j][2] = sc[j][3] = 0.f;
            uint32_t addr = KsB + (uint32_t)((j * 8 + (lane & 7)) * PK + ((lane >> 3) & 1) * 8) * 2;
            uint32_t bk0[2], bk1[2];
            ldmx2(bk0, addr);
            ldmx2(bk1, addr + 32);
            mma16816(sc[j], aQ[0], bk0);
            mma16816(sc[j], aQ[1], bk1);
        }

        float mx0 = -1e30f, mx1 = -1e30f;
#pragma unroll
        for (int j = 0; j < 8; j++) {
            int n = j * 8 + cb;
            float2 mk = __half22float2(*(__half2*)(mks + t * 64 + n));
            sc[j][0] += rxa[j].x + mk.x;
            sc[j][1] += rxa[j].y + mk.y;
            sc[j][2] += rxb[j].x + mk.x;
            sc[j][3] += rxb[j].y + mk.y;
            mx0 = fmaxf(mx0, fmaxf(sc[j][0], sc[j][1]));
            mx1 = fmaxf(mx1, fmaxf(sc[j][2], sc[j][3]));
        }
        mx0 = fmaxf(mx0, __shfl_xor_sync(0xffffffffu, mx0, 1));
        mx0 = fmaxf(mx0, __shfl_xor_sync(0xffffffffu, mx0, 2));
        mx1 = fmaxf(mx1, __shfl_xor_sync(0xffffffffu, mx1, 1));
        mx1 = fmaxf(mx1, __shfl_xor_sync(0xffffffffu, mx1, 2));

        float ry0 = rys[r0 * PRY + t];
        float ry1 = rys[(r0 + 8) * PRY + t];
        float mn0 = fmaxf(m_run0, mx0 + ry0), mn1 = fmaxf(m_run1, mx1 + ry1);
        float base0 = mn0 - ry0, base1 = mn1 - ry1;
        float f0 = ex2(m_run0 - mn0), f1 = ex2(m_run1 - mn1);
        m_run0 = mn0; m_run1 = mn1;

        float la0 = 0.f, la1 = 0.f;
        uint32_t pa[4][4];
#pragma unroll
        for (int j = 0; j < 8; j++) {
            float p0 = ex2(sc[j][0] - base0);
            float p1 = ex2(sc[j][1] - base0);
            float p2 = ex2(sc[j][2] - base1);
            float p3 = ex2(sc[j][3] - base1);
            la0 += p0 + p1; la1 += p2 + p3;
            int kt = j >> 1, hi = j & 1;
            pa[kt][2 * hi]     = packh2(p0, p1);
            pa[kt][2 * hi + 1] = packh2(p2, p3);
        }
        la0 += __shfl_xor_sync(0xffffffffu, la0, 1);
        la0 += __shfl_xor_sync(0xffffffffu, la0, 2);
        la1 += __shfl_xor_sync(0xffffffffu, la1, 1);
        la1 += __shfl_xor_sync(0xffffffffu, la1, 2);
        l_run0 = l_run0 * f0 + la0;
        l_run1 = l_run1 * f1 + la1;

#pragma unroll
        for (int no = 0; no < 4; no++) {
            oc[no][0] *= f0; oc[no][1] *= f0;
            oc[no][2] *= f1; oc[no][3] *= f1;
        }

#pragma unroll
        for (int kt = 0; kt < 4; kt++) {
            uint32_t addr = VsB + (uint32_t)((kt * 16 + (lane & 15)) * PK) * 2;
#pragma unroll
            for (int no = 0; no < 4; no++) {
                uint32_t bv[2];
                ldmx2t(bv, addr + (uint32_t)(no * 8) * 2);
                mma16816(oc[no], pa[kt], bv);
            }
        }
        __syncthreads();
    }

    // write partials
    {
        int cta = (bh * NQT + qt) * NSPL + kvh;
        float* po = d_po + (size_t)cta * 2048;
#pragma unroll
        for (int no = 0; no < 4; no++) {
            int d = no * 8 + cb;
            *(float2*)&po[r0 * 32 + d]       = make_float2(oc[no][0], oc[no][1]);
            *(float2*)&po[(r0 + 8) * 32 + d] = make_float2(oc[no][2], oc[no][3]);
        }
        if ((lane & 3) == 0) {
            d_pm[cta * 64 + r0]     = m_run0;
            d_pm[cta * 64 + r0 + 8] = m_run1;
            d_pl[cta * 64 + r0]     = l_run0;
            d_pl[cta * 64 + r0 + 8] = l_run1;
        }
    }
}

// ---------------- merge partials -> ctx f16 (256 threads: q-row x dim-chunk) --------
__global__ void __launch_bounds__(256) attn_merge()
{
    const int bx = blockIdx.x;         // bh * NQT + qt
    const int bh = bx / NQT;
    const int qt = bx - bh * NQT;
    const int b = bh >> 3;
    const int head = bh & 7;
    const int ql = threadIdx.x >> 2;   // 0..63
    const int du = threadIdx.x & 3;    // 8-dim chunk
    const int q = qt * 64 + ql;
    if (q >= QLEN) return;

    const int c0 = bx * NSPL;
    float ms[NSPL], ls[NSPL];
    float m = -1e30f;
#pragma unroll
    for (int s = 0; s < NSPL; s++) {
        ms[s] = d_pm[(c0 + s) * 64 + ql];
        ls[s] = d_pl[(c0 + s) * 64 + ql];
        m = fmaxf(m, ms[s]);
    }
    float fs[NSPL], lsum = 0.f;
#pragma unroll
    for (int s = 0; s < NSPL; s++) { fs[s] = ex2(ms[s] - m); lsum += ls[s] * fs[s]; }
    float inv = 1.0f / lsum;

    float acc[8];
#pragma unroll
    for (int i = 0; i < 8; i++) acc[i] = 0.f;
#pragma unroll
    for (int s = 0; s < NSPL; s++) {
        const float4* o = (const float4*)(d_po + (size_t)(c0 + s) * 2048 + ql * 32 + du * 8);
        float f = fs[s] * inv;
        float4 a = o[0], c = o[1];
        acc[0] += a.x * f; acc[1] += a.y * f; acc[2] += a.z * f; acc[3] += a.w * f;
        acc[4] += c.x * f; acc[5] += c.y * f; acc[6] += c.z * f; acc[7] += c.w * f;
    }
    uint4 w;
    w.x = packh2(acc[0], acc[1]); w.y = packh2(acc[2], acc[3]);
    w.z = packh2(acc[4], acc[5]); w.w = packh2(acc[6], acc[7]);
    *(uint4*)(d_ctxh + ((size_t)b * QLEN + q) * DIMV + head * HD + du * 8) = w;
}

// ---------------- launch ----------------
extern "C" void kernel_launch(void* const* d_in, const int* in_sizes, int n_in,
                              void* d_out, int out_size)
{
    const float* hidden = (const float*)d_in[0];
    const float* refpts = (const float*)d_in[1];
    const float* kvst   = (const float*)d_in[2];
    const int*   amask  = (const int*)d_in[4];
    const float* m1w1 = (const float*)d_in[5];
    const float* m1b1 = (const float*)d_in[6];
    const float* m1w2 = (const float*)d_in[7];
    const float* m2w1 = (const float*)d_in[8];
    const float* m2b1 = (const float*)d_in[9];
    const float* m2w2 = (const float*)d_in[10];
    const float* qw = (const float*)d_in[11];
    const float* qb = (const float*)d_in[12];
    const float* kw = (const float*)d_in[13];
    const float* kb = (const float*)d_in[14];
    const float* vw = (const float*)d_in[15];
    const float* vb = (const float*)d_in[16];
    const float* ow = (const float*)d_in[17];
    const float* ob = (const float*)d_in[18];
    float* out = (float*)d_out;

    cudaFuncSetAttribute(attn_split, cudaFuncAttributeMaxDynamicSharedMemorySize, ATTN_SMEM);

    const float qs2 = 0.17677669529663687f * L2E;

    convert_all<<<2770, 256>>>(qw, kw, vw, ow, kvst, hidden, m1w2, m2w2, amask);
    fat_mid<<<1532, 256, FAT_SMEM>>>(refpts, m1w1, m1b1, m2w1, m2b1, qb, kb, vb, qs2);
    attn_split<<<dim3(NQT, B_ * NH, NSPL), 128, ATTN_SMEM>>>();
    attn_merge<<<16 * NQT, 256>>>();
    gemm_o<<<dim3(15, 8), 256, 15360>>>(ob, out);
}

// round 13
// speedup vs baseline: 2.8600x; 1.0201x over previous
#include <cuda_runtime.h>
#include <cuda_fp16.h>
#include <cstdint>

#define B_    2
#define QLEN  900
#define DIMV  256
#define NH    8
#define HD    32
#define KVLEN 4096
#define GRD   64
#define RPEH  512
#define L2E   1.4426950408889634f
#define NQT   15          // q tiles of 64
#define NSPL  4           // kv splits

// ---------------- scratch ----------------
__device__ __half d_Qh[B_*NH*QLEN*HD];
__device__ __half d_Kh[B_*NH*KVLEN*HD];
__device__ __half d_Vh[B_*NH*KVLEN*HD];
__device__ __half d_ctxh[B_*QLEN*DIMV];
__device__ float  d_rpex[B_*NH*QLEN*GRD];
__device__ float  d_rpey[B_*NH*QLEN*GRD];
__device__ __half d_Wh[4*65536];
__device__ __half d_Akv[B_*KVLEN*DIMV];
__device__ __half d_Aq[B_*QLEN*DIMV];
__device__ __half d_w2hi[2*8*512];
__device__ __half d_w2lo[2*8*512];
__device__ __half d_mskh[B_*KVLEN];            // -100*log2e*mask (f16)
__device__ __half d_poh[16*NQT*NSPL*64*32];    // partial O (normalized, f16)
__device__ float  d_pm[16*NQT*NSPL*64];        // partial m
__device__ float  d_pl[16*NQT*NSPL*64];        // partial l

// ---------------- helpers ----------------
__device__ __forceinline__ void ldmx4(uint32_t* r, uint32_t a) {
    asm volatile("ldmatrix.sync.aligned.m8n8.x4.shared.b16 {%0,%1,%2,%3}, [%4];"
                 : "=r"(r[0]), "=r"(r[1]), "=r"(r[2]), "=r"(r[3]) : "r"(a));
}
__device__ __forceinline__ void ldmx2(uint32_t* r, uint32_t a) {
    asm volatile("ldmatrix.sync.aligned.m8n8.x2.shared.b16 {%0,%1}, [%2];"
                 : "=r"(r[0]), "=r"(r[1]) : "r"(a));
}
__device__ __forceinline__ void ldmx2t(uint32_t* r, uint32_t a) {
    asm volatile("ldmatrix.sync.aligned.m8n8.x2.trans.shared.b16 {%0,%1}, [%2];"
                 : "=r"(r[0]), "=r"(r[1]) : "r"(a));
}
__device__ __forceinline__ void mma16816(float* c, const uint32_t* a, const uint32_t* b) {
    asm volatile("mma.sync.aligned.m16n8k16.row.col.f32.f16.f16.f32 "
                 "{%0,%1,%2,%3}, {%4,%5,%6,%7}, {%8,%9}, {%0,%1,%2,%3};"
                 : "+f"(c[0]), "+f"(c[1]), "+f"(c[2]), "+f"(c[3])
                 : "r"(a[0]), "r"(a[1]), "r"(a[2]), "r"(a[3]), "r"(b[0]), "r"(b[1]));
}
__device__ __forceinline__ uint32_t smem_u32(const void* p) {
    return (uint32_t)__cvta_generic_to_shared(p);
}
__device__ __forceinline__ uint32_t packh2(float a, float b) {
    __half2 h = __floats2half2_rn(a, b);
    return *(uint32_t*)&h;
}
__device__ __forceinline__ float ex2(float x) {
    float y;
    asm("ex2.approx.ftz.f32 %0, %1;" : "=f"(y) : "f"(x));
    return y;
}
#define CP16(dst, src) asm volatile("cp.async.cg.shared.global [%0], [%1], 16;" :: "r"(dst), "l"(src) : "memory")
#define CP_COMMIT() asm volatile("cp.async.commit_group;" ::: "memory")
#define CP_WAIT0() asm volatile("cp.async.wait_group 0;" ::: "memory")

// ---------------- one-shot convert ----------------
__global__ void convert_all(const float* __restrict__ qw, const float* __restrict__ kw,
                            const float* __restrict__ vw, const float* __restrict__ ow,
                            const float* __restrict__ kvst, const float* __restrict__ hidden,
                            const float* __restrict__ m1w2, const float* __restrict__ m2w2,
                            const int* __restrict__ amask)
{
    unsigned u = blockIdx.x * 256 + threadIdx.x;
    if (u < 705024u) {
        const float* src; __half* dst; unsigned off;
        if      (u <  16384) { src = qw;     dst = d_Wh;          off = u; }
        else if (u <  32768) { src = kw;     dst = d_Wh + 65536;  off = u - 16384; }
        else if (u <  49152) { src = vw;     dst = d_Wh + 131072; off = u - 32768; }
        else if (u <  65536) { src = ow;     dst = d_Wh + 196608; off = u - 49152; }
        else if (u < 589824) { src = kvst;   dst = d_Akv;         off = u - 65536; }
        else                 { src = hidden; dst = d_Aq;          off = u - 589824; }
        float4 f = ((const float4*)src)[off];
        uint2 o; o.x = packh2(f.x, f.y); o.y = packh2(f.z, f.w);
        ((uint2*)dst)[off] = o;
    } else if (u < 707072u) {
        unsigned off = u - 705024u;
        int axis = off >> 10;
        unsigned o2 = off & 1023;
        const float* src = axis ? m2w2 : m1w2;
        float4 f = ((const float4*)src)[o2];
        __half hx = __float2half_rn(f.x), hy = __float2half_rn(f.y);
        __half hz = __float2half_rn(f.z), hw = __float2half_rn(f.w);
        uint2 hiu, lou;
        {
            __half2 a; a.x = hx; a.y = hy; hiu.x = *(uint32_t*)&a;
            __half2 b; b.x = hz; b.y = hw; hiu.y = *(uint32_t*)&b;
        }
        lou.x = packh2(f.x - __half2float(hx), f.y - __half2float(hy));
        lou.y = packh2(f.z - __half2float(hz), f.w - __half2float(hw));
        ((uint2*)(d_w2hi + axis * 4096))[o2] = hiu;
        ((uint2*)(d_w2lo + axis * 4096))[o2] = lou;
    } else {
        unsigned off = u - 707072u;
        int4 m = ((const int4*)amask)[off];
        uint2 o;
        o.x = packh2(-100.0f * L2E * m.x, -100.0f * L2E * m.y);
        o.y = packh2(-100.0f * L2E * m.z, -100.0f * L2E * m.w);
        ((uint2*)d_mskh)[off] = o;
    }
}

// ---------------- HMMA GEMM core: 128x32 tile, optional dual weights ----------------
__device__ __forceinline__ void gemm_core(char* smem, int bm, int bn,
    const __half* __restrict__ Ah,
    const __half* __restrict__ W1, const float* __restrict__ b1v, void* C1,
    const __half* __restrict__ W2, const float* __restrict__ b2v, void* C2,
    int M, int rpb, float scale, int mode)
{
    __half* As  = (__half*)smem;
    __half* Ws1 = (__half*)(smem + 10240);
    __half* Ws2 = (__half*)(smem + 12800);

    const int tid = threadIdx.x;
    const int lane = tid & 31;
    const int wid = tid >> 5;
    const bool dual = (W2 != nullptr);

    const int arow = tid >> 1, aseg = (tid & 1) * 16;
    const int wrow = tid >> 3, wseg = (tid & 7) * 4;

    float c1[4][4], c2[4][4];
#pragma unroll
    for (int j = 0; j < 4; j++) {
        c1[j][0] = c1[j][1] = c1[j][2] = c1[j][3] = 0.f;
        c2[j][0] = c2[j][1] = c2[j][2] = c2[j][3] = 0.f;
    }

    const uint32_t AsB = smem_u32(As);
    const uint32_t W1B = smem_u32(Ws1);
    const uint32_t W2B = smem_u32(Ws2);

    uint4 pa0 = make_uint4(0,0,0,0), pa1 = pa0;
    uint2 pw1, pw2 = make_uint2(0,0);
    if (bm + arow < M) {
        const uint4* ap = (const uint4*)&Ah[(size_t)(bm + arow) * 256 + aseg];
        pa0 = ap[0]; pa1 = ap[1];
    }
    pw1 = *(const uint2*)&W1[(size_t)(bn + wrow) * 256 + wseg];
    if (dual) pw2 = *(const uint2*)&W2[(size_t)(bn + wrow) * 256 + wseg];

#pragma unroll 1
    for (int kit = 0; kit < 8; kit++) {
        *(uint4*)&As[arow * 40 + aseg]     = pa0;
        *(uint4*)&As[arow * 40 + aseg + 8] = pa1;
        *(uint2*)&Ws1[wrow * 40 + wseg]    = pw1;
        if (dual) *(uint2*)&Ws2[wrow * 40 + wseg] = pw2;
        __syncthreads();

        if (kit < 7) {
            int k0 = (kit + 1) * 32;
            pa0 = make_uint4(0,0,0,0); pa1 = pa0;
            if (bm + arow < M) {
                const uint4* ap = (const uint4*)&Ah[(size_t)(bm + arow) * 256 + k0 + aseg];
                pa0 = ap[0]; pa1 = ap[1];
            }
            pw1 = *(const uint2*)&W1[(size_t)(bn + wrow) * 256 + k0 + wseg];
            if (dual) pw2 = *(const uint2*)&W2[(size_t)(bn + wrow) * 256 + k0 + wseg];
        }

        uint32_t a0[4], a1[4];
        uint32_t aa = AsB + (uint32_t)((wid * 16 + (lane & 15)) * 40 + ((lane >> 4) * 8)) * 2;
        ldmx4(a0, aa);
        ldmx4(a1, aa + 32);
#pragma unroll
        for (int j = 0; j < 4; j++) {
            uint32_t woff = (uint32_t)((j * 8 + (lane & 7)) * 40 + ((lane >> 3) & 1) * 8) * 2;
            uint32_t b0[2], b1[2];
            ldmx2(b0, W1B + woff);
            ldmx2(b1, W1B + woff + 32);
            mma16816(c1[j], a0, b0);
            mma16816(c1[j], a1, b1);
            if (dual) {
                ldmx2(b0, W2B + woff);
                ldmx2(b1, W2B + woff + 32);
                mma16816(c2[j], a0, b0);
                mma16816(c2[j], a1, b1);
            }
        }
        __syncthreads();
    }

    const int r0 = bm + wid * 16 + (lane >> 2);
    const int cb = 2 * (lane & 3);
    if (mode == 0) {
        float* C = (float*)C1;
#pragma unroll
        for (int j = 0; j < 4; j++) {
            int col = bn + j * 8 + cb;
            float bb0 = b1v[col], bb1 = b1v[col + 1];
            if (r0 < M)     *(float2*)&C[(size_t)r0 * 256 + col]       = make_float2((c1[j][0] + bb0) * scale, (c1[j][1] + bb1) * scale);
            if (r0 + 8 < M) *(float2*)&C[(size_t)(r0 + 8) * 256 + col] = make_float2((c1[j][2] + bb0) * scale, (c1[j][3] + bb1) * scale);
        }
    } else {
        __half* Ca = (__half*)C1;
        __half* Cb = (__half*)C2;
        int ba = r0 / rpb, ra = r0 - ba * rpb;
        int bb = (r0 + 8) / rpb, rb = (r0 + 8) - bb * rpb;
#pragma unroll
        for (int j = 0; j < 4; j++) {
            int col = bn + j * 8 + cb;
            int head = col >> 5, d = col & 31;
            float x0 = b1v[col], x1 = b1v[col + 1];
            if (r0 < M) {
                *(uint32_t*)&Ca[((size_t)((ba * NH + head) * rpb + ra)) * HD + d] =
                    packh2((c1[j][0] + x0) * scale, (c1[j][1] + x1) * scale);
            }
            if (r0 + 8 < M) {
                *(uint32_t*)&Ca[((size_t)((bb * NH + head) * rpb + rb)) * HD + d] =
                    packh2((c1[j][2] + x0) * scale, (c1[j][3] + x1) * scale);
            }
            if (dual) {
                float y0 = b2v[col], y1 = b2v[col + 1];
                if (r0 < M) {
                    *(uint32_t*)&Cb[((size_t)((ba * NH + head) * rpb + ra)) * HD + d] =
                        packh2((c2[j][0] + y0) * scale, (c2[j][1] + y1) * scale);
                }
                if (r0 + 8 < M) {
                    *(uint32_t*)&Cb[((size_t)((bb * NH + head) * rpb + rb)) * HD + d] =
                        packh2((c2[j][2] + y0) * scale, (c2[j][3] + y1) * scale);
                }
            }
        }
    }
}

// ---------------- RPE core ----------------
#define MKFRAG(px, hi0, lo0, hi1, lo1) { \
    float h0 = fmaxf(v0.x - v0.y * (px), 0.f); \
    float h1 = fmaxf(v0.z - v0.w * (px), 0.f); \
    float h2 = fmaxf(v1.x - v1.y * (px), 0.f); \
    float h3 = fmaxf(v1.z - v1.w * (px), 0.f); \
    __half2 t0 = __floats2half2_rn(h0, h1); float2 g0 = __half22float2(t0); \
    __half2 u0 = __floats2half2_rn(h0 - g0.x, h1 - g0.y); \
    __half2 t1 = __floats2half2_rn(h2, h3); float2 g1 = __half22float2(t1); \
    __half2 u1 = __floats2half2_rn(h2 - g1.x, h3 - g1.y); \
    hi0 = *(uint32_t*)&t0; lo0 = *(uint32_t*)&u0; \
    hi1 = *(uint32_t*)&t1; lo1 = *(uint32_t*)&u1; }

__device__ __forceinline__ void rpe_core(char* smem, int q0, int b, int axis,
    const float* __restrict__ refpts,
    const float* __restrict__ w1a, const float* __restrict__ b1a,
    const float* __restrict__ w1b, const float* __restrict__ b1b)
{
    __half* w2hi = (__half*)smem;
    __half* w2lo = (__half*)(smem + 8320);
    float2* as2  = (float2*)(smem + 16640);

    const int tid = threadIdx.x;
    const int lane = tid & 31;
    const int wid = tid >> 5;

    const float* w1  = axis ? w1b : w1a;
    const float* bb1 = axis ? b1b : b1a;
    float* out = axis ? d_rpey : d_rpex;

    const __half* ghi = d_w2hi + axis * 4096;
    const __half* glo = d_w2lo + axis * 4096;
#pragma unroll
    for (int i = tid; i < 2048; i += 256) {
        int h = i >> 8, jj = (i & 255) * 2;
        *(uint32_t*)&w2hi[h * 520 + jj] = *(const uint32_t*)&ghi[h * 512 + jj];
        *(uint32_t*)&w2lo[h * 520 + jj] = *(const uint32_t*)&glo[h * 512 + jj];
    }
#pragma unroll
    for (int i = tid; i < 4 * 512; i += 256) {
        int qi = i >> 9, j = i & 511;
        const float* rp = refpts + ((size_t)b * QLEN + q0 + qi) * 4;
        float cc = rp[axis], ss = rp[2 + axis];
        float lo = (cc - 0.5f * ss) * 1024.f, hi = (cc + 0.5f * ss) * 1024.f;
        float wx = w1[j * 2], wy = w1[j * 2 + 1];
        as2[qi * 512 + j] = make_float2(wx * lo + wy * hi + bb1[j], wx + wy);
    }
    __syncthreads();

    const int qi = wid >> 1;
    const int mt = wid & 1;
    const int q = q0 + qi;
    const int r = lane >> 2;
    const int c0 = 2 * (lane & 3);
    const float pxA = (mt * 16 + r + 0.5f) * 16.f;
    const float pxB = pxA + 128.f;
    const float pxC = pxA + 512.f;
    const float pxD = pxA + 640.f;

    const uint32_t WhiB = smem_u32(w2hi);
    const uint32_t WloB = smem_u32(w2lo);
    const float2* asq = as2 + qi * 512;

    float cA[4] = {0.f, 0.f, 0.f, 0.f};
    float cB[4] = {0.f, 0.f, 0.f, 0.f};

#pragma unroll 4
    for (int kk = 0; kk < 32; kk++) {
        int j0 = kk * 16 + c0;
        float4 v0 = *(const float4*)&asq[j0];
        float4 v1 = *(const float4*)&asq[j0 + 8];

        uint32_t ahiA[4], aloA[4], ahiB[4], aloB[4];
        MKFRAG(pxA, ahiA[0], aloA[0], ahiA[2], aloA[2]);
        MKFRAG(pxB, ahiA[1], aloA[1], ahiA[3], aloA[3]);
        MKFRAG(pxC, ahiB[0], aloB[0], ahiB[2], aloB[2]);
        MKFRAG(pxD, ahiB[1], aloB[1], ahiB[3], aloB[3]);

        uint32_t woff = (uint32_t)((lane & 7) * 520 + kk * 16 + ((lane >> 3) & 1) * 8) * 2;
        uint32_t bhi[2], blo[2];
        ldmx2(bhi, WhiB + woff);
        ldmx2(blo, WloB + woff);
        mma16816(cA, ahiA, bhi);
        mma16816(cA, aloA, bhi);
        mma16816(cA, ahiA, blo);
        mma16816(cB, ahiB, bhi);
        mma16816(cB, aloB, bhi);
        mma16816(cB, ahiB, blo);
    }

    {
        int p0 = mt * 16 + r;
        size_t hstride = (size_t)QLEN * GRD;
        size_t base = ((size_t)(b * NH + c0) * QLEN + q) * GRD;
        out[base + p0]               = cA[0] * L2E;
        out[base + hstride + p0]     = cA[1] * L2E;
        out[base + p0 + 8]           = cA[2] * L2E;
        out[base + hstride + p0 + 8] = cA[3] * L2E;
        out[base + p0 + 32]               = cB[0] * L2E;
        out[base + hstride + p0 + 32]     = cB[1] * L2E;
        out[base + p0 + 40]               = cB[2] * L2E;
        out[base + hstride + p0 + 40]     = cB[3] * L2E;
    }
}

// ---------------- fat mid-kernel ----------------
#define FAT_SMEM 33024
__global__ void __launch_bounds__(256, 4) fat_mid(
    const float* __restrict__ refpts,
    const float* __restrict__ w1a, const float* __restrict__ b1a,
    const float* __restrict__ w1b, const float* __restrict__ b1b,
    const float* __restrict__ qb, const float* __restrict__ kb,
    const float* __restrict__ vb, float qs2)
{
    extern __shared__ char smem[];
    int bx = blockIdx.x;
    if (bx < 900) {
        int axis = bx / 450;
        int rem = bx - axis * 450;
        int b = rem / 225;
        int q0 = (rem % 225) * 4;
        rpe_core(smem, q0, b, axis, refpts, w1a, b1a, w1b, b1b);
    } else if (bx < 1412) {
        int i = bx - 900;
        gemm_core(smem, (i & 63) * 128, (i >> 6) * 32,
                  d_Akv, d_Wh + 65536, kb, d_Kh, d_Wh + 131072, vb, d_Vh,
                  B_ * KVLEN, KVLEN, 1.0f, 1);
    } else {
        int i = bx - 1412;
        gemm_core(smem, (i % 15) * 128, (i / 15) * 32,
                  d_Aq, d_Wh, qb, d_Qh, nullptr, nullptr, nullptr,
                  B_ * QLEN, QLEN, qs2, 1);
    }
}

// ---------------- O projection ----------------
__global__ void __launch_bounds__(256) gemm_o(const float* __restrict__ ob, float* __restrict__ out)
{
    extern __shared__ char smem[];
    gemm_core(smem, blockIdx.x * 128, blockIdx.y * 32,
              d_ctxh, d_Wh + 196608, ob, out, nullptr, nullptr, nullptr,
              B_ * QLEN, QLEN, 1.0f, 0);
}

// ---------------- split-KV HMMA flash attention (NSPL=4, single-sync pipeline) ------
#define PK 40
#define PRY 20
#define QS_OFF  0
#define KS_OFF  5120
#define VS_OFF  15360
#define RY_OFF  25600
#define MK_OFF  30720
#define ATTN_SMEM 32768

__global__ void __launch_bounds__(128) attn_split()
{
    extern __shared__ char smem[];
    __half* Qs  = (__half*)(smem + QS_OFF);
    float*  rys = (float*)(smem + RY_OFF);
    __half* mks = (__half*)(smem + MK_OFF);

    const int tid = threadIdx.x;
    const int lane = tid & 31;
    const int wid = tid >> 5;
    const int qt = blockIdx.x;
    const int bh = blockIdx.y;
    const int kvh = blockIdx.z;
    const int b = bh >> 3;
    const int q0 = qt * 64;
    const int kv0 = kvh * (KVLEN / NSPL);

    const __half* Kb = d_Kh + (size_t)bh * KVLEN * HD + (size_t)kv0 * HD;
    const __half* Vb = d_Vh + (size_t)bh * KVLEN * HD + (size_t)kv0 * HD;

    const int srow = tid >> 1, sseg = (tid & 1) * 16;
    {
        uint32_t kd = smem_u32(smem + KS_OFF) + (uint32_t)(srow * PK + sseg) * 2;
        uint32_t vd = smem_u32(smem + VS_OFF) + (uint32_t)(srow * PK + sseg) * 2;
        const __half* ks = Kb + (size_t)srow * HD + sseg;
        const __half* vs = Vb + (size_t)srow * HD + sseg;
        CP16(kd, ks); CP16(kd + 16, ks + 8);
        CP16(vd, vs); CP16(vd + 16, vs + 8);
        CP_COMMIT();
    }

    if (tid < 128) {
        const uint4* mg = (const uint4*)(d_mskh + b * KVLEN + kv0);
        ((uint4*)mks)[tid] = mg[tid];
    }

    {
        int row = tid >> 1, seg = tid & 1;
        int q = q0 + row;
        uint4 v0 = make_uint4(0, 0, 0, 0), v1 = make_uint4(0, 0, 0, 0);
        if (q < QLEN) {
            const uint4* qp = (const uint4*)(d_Qh + ((size_t)bh * QLEN + q) * HD + seg * 16);
            v0 = qp[0]; v1 = qp[1];
        }
        *(uint4*)(Qs + row * PK + seg * 16)     = v0;
        *(uint4*)(Qs + row * PK + seg * 16 + 8) = v1;
    }
    {
        int row = tid >> 1, sb = (tid & 1) * 8;
        int q = q0 + row;
        if (q < QLEN) {
            const float4* py = (const float4*)(d_rpey + ((size_t)bh * QLEN + q) * GRD + kvh * 16 + sb);
            *(float4*)(rys + row * PRY + sb)     = py[0];
            *(float4*)(rys + row * PRY + sb + 4) = py[1];
        } else {
            float4 z = make_float4(0.f, 0.f, 0.f, 0.f);
            *(float4*)(rys + row * PRY + sb)     = z;
            *(float4*)(rys + row * PRY + sb + 4) = z;
        }
    }
    __syncthreads();

    uint32_t aQ[2][4];
    {
        uint32_t base = smem_u32(Qs);
        int m = wid * 16 + (lane & 15);
        uint32_t a0 = base + (uint32_t)(m * PK + ((lane >> 4) * 8)) * 2;
        ldmx4(aQ[0], a0);
        ldmx4(aQ[1], a0 + 32);
    }

    const int r0 = wid * 16 + (lane >> 2);
    const int cb = 2 * (lane & 3);

    float2 rxa[8], rxb[8];
    {
        int qa = q0 + r0, qb2 = qa + 8;
        const float* rxg = d_rpex + (size_t)bh * QLEN * GRD;
        float2 z = make_float2(0.f, 0.f);
#pragma unroll
        for (int j = 0; j < 8; j++) {
            int n = j * 8 + cb;
            rxa[j] = (qa  < QLEN) ? *(const float2*)&rxg[(size_t)qa  * GRD + n] : z;
            rxb[j] = (qb2 < QLEN) ? *(const float2*)&rxg[(size_t)qb2 * GRD + n] : z;
        }
    }

    float oc[4][4];
#pragma unroll
    for (int i = 0; i < 4; i++)
#pragma unroll
        for (int j = 0; j < 4; j++) oc[i][j] = 0.f;
    float m_run0 = -1e30f, m_run1 = -1e30f, l_run0 = 0.f, l_run1 = 0.f;

    const int NT = KVLEN / NSPL / 64;  // 16 tiles
    for (int t = 0; t < NT; t++) {
        CP_WAIT0();
        __syncthreads();
        if (t + 1 < NT) {
            int buf = (t + 1) & 1;
            uint32_t kd = smem_u32(smem + KS_OFF + buf * 5120) + (uint32_t)(srow * PK + sseg) * 2;
            uint32_t vd = smem_u32(smem + VS_OFF + buf * 5120) + (uint32_t)(srow * PK + sseg) * 2;
            const __half* ks = Kb + (size_t)((t + 1) * 64 + srow) * HD + sseg;
            const __half* vs = Vb + (size_t)((t + 1) * 64 + srow) * HD + sseg;
            CP16(kd, ks); CP16(kd + 16, ks + 8);
            CP16(vd, vs); CP16(vd + 16, vs + 8);
            CP_COMMIT();
        }

        const uint32_t KsB = smem_u32(smem + KS_OFF + (t & 1) * 5120);
        const uint32_t VsB = smem_u32(smem + VS_OFF + (t & 1) * 5120);

        float sc[8][4];
#pragma unroll
        for (int j = 0; j < 8; j++) {
            sc[j][0] = sc[j][1] = sc[j][2] = sc[j][3] = 0.f;
            uint32_t addr = KsB + (uint32_t)((j * 8 + (lane & 7)) * PK + ((lane >> 3) & 1) * 8) * 2;
            uint32_t bk0[2], bk1[2];
            ldmx2(bk0, addr);
            ldmx2(bk1, addr + 32);
            mma16816(sc[j], aQ[0], bk0);
            mma16816(sc[j], aQ[1], bk1);
        }

        float mx0 = -1e30f, mx1 = -1e30f;
#pragma unroll
        for (int j = 0; j < 8; j++) {
            int n = j * 8 + cb;
            float2 mk = __half22float2(*(__half2*)(mks + t * 64 + n));
            sc[j][0] += rxa[j].x + mk.x;
            sc[j][1] += rxa[j].y + mk.y;
            sc[j][2] += rxb[j].x + mk.x;
            sc[j][3] += rxb[j].y + mk.y;
            mx0 = fmaxf(mx0, fmaxf(sc[j][0], sc[j][1]));
            mx1 = fmaxf(mx1, fmaxf(sc[j][2], sc[j][3]));
        }
        mx0 = fmaxf(mx0, __shfl_xor_sync(0xffffffffu, mx0, 1));
        mx0 = fmaxf(mx0, __shfl_xor_sync(0xffffffffu, mx0, 2));
        mx1 = fmaxf(mx1, __shfl_xor_sync(0xffffffffu, mx1, 1));
        mx1 = fmaxf(mx1, __shfl_xor_sync(0xffffffffu, mx1, 2));

        float ry0 = rys[r0 * PRY + t];
        float ry1 = rys[(r0 + 8) * PRY + t];
        float mn0 = fmaxf(m_run0, mx0 + ry0), mn1 = fmaxf(m_run1, mx1 + ry1);
        float base0 = mn0 - ry0, base1 = mn1 - ry1;
        float f0 = ex2(m_run0 - mn0), f1 = ex2(m_run1 - mn1);
        m_run0 = mn0; m_run1 = mn1;

        float la0 = 0.f, la1 = 0.f;
        uint32_t pa[4][4];
#pragma unroll
        for (int j = 0; j < 8; j++) {
            float p0 = ex2(sc[j][0] - base0);
            float p1 = ex2(sc[j][1] - base0);
            float p2 = ex2(sc[j][2] - base1);
            float p3 = ex2(sc[j][3] - base1);
            la0 += p0 + p1; la1 += p2 + p3;
            int kt = j >> 1, hi = j & 1;
            pa[kt][2 * hi]     = packh2(p0, p1);
            pa[kt][2 * hi + 1] = packh2(p2, p3);
        }
        la0 += __shfl_xor_sync(0xffffffffu, la0, 1);
        la0 += __shfl_xor_sync(0xffffffffu, la0, 2);
        la1 += __shfl_xor_sync(0xffffffffu, la1, 1);
        la1 += __shfl_xor_sync(0xffffffffu, la1, 2);
        l_run0 = l_run0 * f0 + la0;
        l_run1 = l_run1 * f1 + la1;

#pragma unroll
        for (int no = 0; no < 4; no++) {
            oc[no][0] *= f0; oc[no][1] *= f0;
            oc[no][2] *= f1; oc[no][3] *= f1;
        }

#pragma unroll
        for (int kt = 0; kt < 4; kt++) {
            uint32_t addr = VsB + (uint32_t)((kt * 16 + (lane & 15)) * PK) * 2;
#pragma unroll
            for (int no = 0; no < 4; no++) {
                uint32_t bv[2];
                ldmx2t(bv, addr + (uint32_t)(no * 8) * 2);
                mma16816(oc[no], pa[kt], bv);
            }
        }
    }

    // write partials (normalized, f16)
    {
        int cta = (bh * NQT + qt) * NSPL + kvh;
        __half* po = d_poh + (size_t)cta * 2048;
        float inv0 = 1.0f / l_run0;
        float inv1 = 1.0f / l_run1;
#pragma unroll
        for (int no = 0; no < 4; no++) {
            int d = no * 8 + cb;
            *(uint32_t*)&po[r0 * 32 + d]       = packh2(oc[no][0] * inv0, oc[no][1] * inv0);
            *(uint32_t*)&po[(r0 + 8) * 32 + d] = packh2(oc[no][2] * inv1, oc[no][3] * inv1);
        }
        if ((lane & 3) == 0) {
            d_pm[cta * 64 + r0]     = m_run0;
            d_pm[cta * 64 + r0 + 8] = m_run1;
            d_pl[cta * 64 + r0]     = l_run0;
            d_pl[cta * 64 + r0 + 8] = l_run1;
        }
    }
}

// ---------------- merge partials -> ctx f16 (480 blocks x 256 threads) ----------------
__global__ void __launch_bounds__(256) attn_merge()
{
    const int bx = blockIdx.x;         // bh * NQT + qt
    const int bh = bx / NQT;
    const int qt = bx - bh * NQT;
    const int b = bh >> 3;
    const int head = bh & 7;
    const int ql = (threadIdx.x >> 3) + blockIdx.y * 32;   // 0..63
    const int du = threadIdx.x & 7;    // 4-dim chunk
    const int q = qt * 64 + ql;
    if (q >= QLEN) return;

    const int c0 = bx * NSPL;
    float ms[NSPL], ls[NSPL];
    float m = -1e30f;
#pragma unroll
    for (int s = 0; s < NSPL; s++) {
        ms[s] = d_pm[(c0 + s) * 64 + ql];
        ls[s] = d_pl[(c0 + s) * 64 + ql];
        m = fmaxf(m, ms[s]);
    }
    float ws[NSPL], lsum = 0.f;
#pragma unroll
    for (int s = 0; s < NSPL; s++) { ws[s] = ls[s] * ex2(ms[s] - m); lsum += ws[s]; }
    float inv = 1.0f / lsum;

    float acc[4] = {0.f, 0.f, 0.f, 0.f};
#pragma unroll
    for (int s = 0; s < NSPL; s++) {
        const uint2* o = (const uint2*)(d_poh + (size_t)(c0 + s) * 2048 + ql * 32 + du * 4);
        uint2 v = o[0];
        float2 a = __half22float2(*(__half2*)&v.x);
        float2 c = __half22float2(*(__half2*)&v.y);
        float f = ws[s] * inv;
        acc[0] += a.x * f; acc[1] += a.y * f;
        acc[2] += c.x * f; acc[3] += c.y * f;
    }
    uint2 w;
    w.x = packh2(acc[0], acc[1]); w.y = packh2(acc[2], acc[3]);
    *(uint2*)(d_ctxh + ((size_t)b * QLEN + q) * DIMV + head * HD + du * 4) = w;
}

// ---------------- launch ----------------
extern "C" void kernel_launch(void* const* d_in, const int* in_sizes, int n_in,
                              void* d_out, int out_size)
{
    const float* hidden = (const float*)d_in[0];
    const float* refpts = (const float*)d_in[1];
    const float* kvst   = (const float*)d_in[2];
    const int*   amask  = (const int*)d_in[4];
    const float* m1w1 = (const float*)d_in[5];
    const float* m1b1 = (const float*)d_in[6];
    const float* m1w2 = (const float*)d_in[7];
    const float* m2w1 = (const float*)d_in[8];
    const float* m2b1 = (const float*)d_in[9];
    const float* m2w2 = (const float*)d_in[10];
    const float* qw = (const float*)d_in[11];
    const float* qb = (const float*)d_in[12];
    const float* kw = (const float*)d_in[13];
    const float* kb = (const float*)d_in[14];
    const float* vw = (const float*)d_in[15];
    const float* vb = (const float*)d_in[16];
    const float* ow = (const float*)d_in[17];
    const float* ob = (const float*)d_in[18];
    float* out = (float*)d_out;

    cudaFuncSetAttribute(attn_split, cudaFuncAttributeMaxDynamicSharedMemorySize, ATTN_SMEM);

    const float qs2 = 0.17677669529663687f * L2E;

    convert_all<<<2770, 256>>>(qw, kw, vw, ow, kvst, hidden, m1w2, m2w2, amask);
    fat_mid<<<1532, 256, FAT_SMEM>>>(refpts, m1w1, m1b1, m2w1, m2b1, qb, kb, vb, qs2);
    attn_split<<<dim3(NQT, B_ * NH, NSPL), 128, ATTN_SMEM>>>();
    attn_merge<<<dim3(16 * NQT, 2), 256>>>();
    gemm_o<<<dim3(15, 8), 256, 15360>>>(ob, out);
}